// round 1
// baseline (speedup 1.0000x reference)
#include <cuda_runtime.h>
#include <cuda_bf16.h>

// Problem constants
// B=16, C=512, T=1024 (32x32), L=77, S=1101, HEADS=8, D=64, GROUPS=32, CROSS_DIM=768

__device__ float g_xn[16 * 512 * 1024];      // normalized x   [B,C,T]
__device__ float g_qkv[16 * 1536 * 1024];    // qkv            [B,3C,T]
__device__ float g_ckv[16 * 1024 * 77];      // cond kv        [B,2C,L]
__device__ float g_attn[16 * 512 * 1024];    // attention out  [B,C,T]

// ---------------------------------------------------------------------------
// GroupNorm(32): one block per (b, group); 16 channels x 1024 spatial each.
// ---------------------------------------------------------------------------
__global__ __launch_bounds__(256)
void groupnorm_kernel(const float* __restrict__ x,
                      const float* __restrict__ gamma,
                      const float* __restrict__ beta,
                      float* __restrict__ xn)
{
    int b = blockIdx.x >> 5;
    int g = blockIdx.x & 31;
    const float* xp = x + ((size_t)b * 512 + (size_t)g * 16) * 1024;

    float s = 0.f, s2 = 0.f;
    for (int i = threadIdx.x; i < 16384; i += 256) {
        float v = xp[i];
        s += v; s2 += v * v;
    }
#pragma unroll
    for (int o = 16; o > 0; o >>= 1) {
        s  += __shfl_xor_sync(0xffffffffu, s, o);
        s2 += __shfl_xor_sync(0xffffffffu, s2, o);
    }
    __shared__ float ss[8], ss2[8];
    __shared__ float smean, sinv;
    int w = threadIdx.x >> 5;
    if ((threadIdx.x & 31) == 0) { ss[w] = s; ss2[w] = s2; }
    __syncthreads();
    if (threadIdx.x == 0) {
        float S = 0.f, S2 = 0.f;
#pragma unroll
        for (int i = 0; i < 8; i++) { S += ss[i]; S2 += ss2[i]; }
        float mean = S * (1.f / 16384.f);
        float var  = S2 * (1.f / 16384.f) - mean * mean;
        smean = mean;
        sinv  = rsqrtf(var + 1e-5f);
    }
    __syncthreads();
    float mean = smean, inv = sinv;
    float* op = xn + ((size_t)b * 512 + (size_t)g * 16) * 1024;
    for (int i = threadIdx.x; i < 16384; i += 256) {
        int ch = g * 16 + (i >> 10);
        op[i] = (xp[i] - mean) * inv * gamma[ch] + beta[ch];
    }
}

// ---------------------------------------------------------------------------
// Batched SGEMM: out[b][m][n] = sum_k W[m][k] * X[b][k][n] + bias[m] (+ res)
// 64x64 tile, BK=16, 256 threads, 4x4 register micro-tile.
// M multiple of 64, K multiple of 16; N arbitrary (guarded).
// ---------------------------------------------------------------------------
__global__ __launch_bounds__(256)
void sgemm_kernel(const float* __restrict__ W, const float* __restrict__ X,
                  const float* __restrict__ bias, const float* __restrict__ res,
                  float* __restrict__ out,
                  int M, int N, int K, long xStride, long outStride)
{
    int b = blockIdx.z;
    X   += (size_t)b * xStride;
    out += (size_t)b * outStride;
    const float* resp = res ? (res + (size_t)b * outStride) : nullptr;

    __shared__ __align__(16) float Wsm[16 * 65];   // [kk][m], padded stride 65
    __shared__ __align__(16) float Xsm[16 * 64];   // [kk][n]

    int tid = threadIdx.x;
    int tx = tid & 15, ty = tid >> 4;
    int m0 = blockIdx.y * 64, n0 = blockIdx.x * 64;

    float acc[4][4];
#pragma unroll
    for (int i = 0; i < 4; i++)
#pragma unroll
        for (int j = 0; j < 4; j++) acc[i][j] = 0.f;

    for (int k0 = 0; k0 < K; k0 += 16) {
#pragma unroll
        for (int i = 0; i < 4; i++) {
            int e = tid + 256 * i;
            int kk = e & 15, m = e >> 4;           // W tile: kk fastest -> coalesced
            Wsm[kk * 65 + m] = W[(size_t)(m0 + m) * K + k0 + kk];
            int n = e & 63, kk2 = e >> 6;          // X tile: n fastest -> coalesced
            float xv = 0.f;
            if (n0 + n < N) xv = X[(size_t)(k0 + kk2) * N + n0 + n];
            Xsm[kk2 * 64 + n] = xv;
        }
        __syncthreads();
#pragma unroll
        for (int kk = 0; kk < 16; kk++) {
            float a0 = Wsm[kk * 65 + ty * 4 + 0];
            float a1 = Wsm[kk * 65 + ty * 4 + 1];
            float a2 = Wsm[kk * 65 + ty * 4 + 2];
            float a3 = Wsm[kk * 65 + ty * 4 + 3];
            float4 bv = *(const float4*)&Xsm[kk * 64 + tx * 4];
            acc[0][0] += a0 * bv.x; acc[0][1] += a0 * bv.y; acc[0][2] += a0 * bv.z; acc[0][3] += a0 * bv.w;
            acc[1][0] += a1 * bv.x; acc[1][1] += a1 * bv.y; acc[1][2] += a1 * bv.z; acc[1][3] += a1 * bv.w;
            acc[2][0] += a2 * bv.x; acc[2][1] += a2 * bv.y; acc[2][2] += a2 * bv.z; acc[2][3] += a2 * bv.w;
            acc[3][0] += a3 * bv.x; acc[3][1] += a3 * bv.y; acc[3][2] += a3 * bv.z; acc[3][3] += a3 * bv.w;
        }
        __syncthreads();
    }

#pragma unroll
    for (int i = 0; i < 4; i++) {
        int m = m0 + ty * 4 + i;
        float bi = bias[m];
#pragma unroll
        for (int j = 0; j < 4; j++) {
            int n = n0 + tx * 4 + j;
            if (n < N) {
                float v = acc[i][j] + bi;
                if (resp) v += resp[(size_t)m * N + n];
                out[(size_t)m * N + n] = v;
            }
        }
    }
}

// ---------------------------------------------------------------------------
// Flash attention, fp32. One block = (b, h, 64-query tile); 64 threads,
// one query per thread (q + accumulator in registers, 128 floats).
// K/V staged per 64-key tile in smem, rows padded to 68 floats so the
// row-per-thread float4 STS and the broadcast float4 LDS are conflict-free.
// Keys 0..1023 from self qkv; 1024..1100 from cond ckv.
// ---------------------------------------------------------------------------
__global__ __launch_bounds__(64)
void attn_kernel(const float* __restrict__ qkv, const float* __restrict__ ckv,
                 float* __restrict__ out)
{
    int t0 = blockIdx.x * 64;
    int h  = blockIdx.y;
    int b  = blockIdx.z;
    int tid = threadIdx.x;

    const float* qbase = qkv + ((size_t)b * 1536 + (size_t)h * 64) * 1024;
    const float* kbase = qkv + ((size_t)b * 1536 + 512  + (size_t)h * 64) * 1024;
    const float* vbase = qkv + ((size_t)b * 1536 + 1024 + (size_t)h * 64) * 1024;
    const float* kcb   = ckv + ((size_t)b * 1024 + (size_t)h * 64) * 77;
    const float* vcb   = ckv + ((size_t)b * 1024 + 512 + (size_t)h * 64) * 77;

    __shared__ __align__(16) float ksm[64 * 68];
    __shared__ __align__(16) float vsm[64 * 68];

    float qv[64];
#pragma unroll
    for (int d = 0; d < 64; d++) qv[d] = qbase[(size_t)d * 1024 + t0 + tid];

    float acc[64];
#pragma unroll
    for (int d = 0; d < 64; d++) acc[d] = 0.f;
    float mval = -1e30f, l = 0.f;

    for (int s0 = 0; s0 < 1101; s0 += 64) {
        int len = min(64, 1101 - s0);
        if (s0 < 1024) {
            int s = s0 + tid;
#pragma unroll
            for (int c = 0; c < 16; c++) {
                float4 kq, vq;
                kq.x = kbase[(size_t)(4 * c + 0) * 1024 + s];
                kq.y = kbase[(size_t)(4 * c + 1) * 1024 + s];
                kq.z = kbase[(size_t)(4 * c + 2) * 1024 + s];
                kq.w = kbase[(size_t)(4 * c + 3) * 1024 + s];
                vq.x = vbase[(size_t)(4 * c + 0) * 1024 + s];
                vq.y = vbase[(size_t)(4 * c + 1) * 1024 + s];
                vq.z = vbase[(size_t)(4 * c + 2) * 1024 + s];
                vq.w = vbase[(size_t)(4 * c + 3) * 1024 + s];
                *(float4*)&ksm[tid * 68 + 4 * c] = kq;
                *(float4*)&vsm[tid * 68 + 4 * c] = vq;
            }
        } else {
            int li = s0 - 1024 + tid;
            if (li < 77) {
#pragma unroll
                for (int c = 0; c < 16; c++) {
                    float4 kq, vq;
                    kq.x = kcb[(size_t)(4 * c + 0) * 77 + li];
                    kq.y = kcb[(size_t)(4 * c + 1) * 77 + li];
                    kq.z = kcb[(size_t)(4 * c + 2) * 77 + li];
                    kq.w = kcb[(size_t)(4 * c + 3) * 77 + li];
                    vq.x = vcb[(size_t)(4 * c + 0) * 77 + li];
                    vq.y = vcb[(size_t)(4 * c + 1) * 77 + li];
                    vq.z = vcb[(size_t)(4 * c + 2) * 77 + li];
                    vq.w = vcb[(size_t)(4 * c + 3) * 77 + li];
                    *(float4*)&ksm[tid * 68 + 4 * c] = kq;
                    *(float4*)&vsm[tid * 68 + 4 * c] = vq;
                }
            }
        }
        __syncthreads();

        for (int j = 0; j < len; j++) {
            const float4* kr = (const float4*)(ksm + j * 68);
            float sc = 0.f;
#pragma unroll
            for (int c = 0; c < 16; c++) {
                float4 k4 = kr[c];
                sc += qv[4 * c + 0] * k4.x + qv[4 * c + 1] * k4.y
                    + qv[4 * c + 2] * k4.z + qv[4 * c + 3] * k4.w;
            }
            sc *= 0.125f;   // 1/sqrt(64)
            if (sc > mval) {
                float corr = __expf(mval - sc);
                l *= corr;
#pragma unroll
                for (int d = 0; d < 64; d++) acc[d] *= corr;
                mval = sc;
            }
            float p = __expf(sc - mval);
            l += p;
            const float4* vr = (const float4*)(vsm + j * 68);
#pragma unroll
            for (int c = 0; c < 16; c++) {
                float4 v4 = vr[c];
                acc[4 * c + 0] += p * v4.x;
                acc[4 * c + 1] += p * v4.y;
                acc[4 * c + 2] += p * v4.z;
                acc[4 * c + 3] += p * v4.w;
            }
        }
        __syncthreads();
    }

    float inv = 1.f / l;
    float* ob = out + ((size_t)b * 512 + (size_t)h * 64) * 1024 + t0 + tid;
#pragma unroll
    for (int d = 0; d < 64; d++) ob[(size_t)d * 1024] = acc[d] * inv;
}

// ---------------------------------------------------------------------------
extern "C" void kernel_launch(void* const* d_in, const int* in_sizes, int n_in,
                              void* d_out, int out_size)
{
    const float* x     = (const float*)d_in[0];
    const float* c     = (const float*)d_in[1];
    const float* gamma = (const float*)d_in[2];
    const float* beta  = (const float*)d_in[3];
    const float* w_qkv = (const float*)d_in[4];
    const float* b_qkv = (const float*)d_in[5];
    const float* w_c   = (const float*)d_in[6];
    const float* b_c   = (const float*)d_in[7];
    const float* w_p   = (const float*)d_in[8];
    const float* b_p   = (const float*)d_in[9];
    float* out = (float*)d_out;

    float *xn, *qkv, *ckv, *attn;
    cudaGetSymbolAddress((void**)&xn,   g_xn);
    cudaGetSymbolAddress((void**)&qkv,  g_qkv);
    cudaGetSymbolAddress((void**)&ckv,  g_ckv);
    cudaGetSymbolAddress((void**)&attn, g_attn);

    // 1. GroupNorm
    groupnorm_kernel<<<512, 256>>>(x, gamma, beta, xn);

    // 2. qkv 1x1 conv: [1536,1024] = W[1536,512] @ xn_b[512,1024]
    dim3 gq(16, 24, 16);
    sgemm_kernel<<<gq, 256>>>(w_qkv, xn, b_qkv, nullptr, qkv,
                              1536, 1024, 512, 512L * 1024, 1536L * 1024);

    // 3. cond kv: [1024,77] = Wc[1024,768] @ c_b[768,77]
    dim3 gc(2, 16, 16);
    sgemm_kernel<<<gc, 256>>>(w_c, c, b_c, nullptr, ckv,
                              1024, 77, 768, 768L * 77, 1024L * 77);

    // 4. attention (flash, S = 1024 self + 77 cross)
    dim3 ga(16, 8, 16);
    attn_kernel<<<ga, 64>>>(qkv, ckv, attn);

    // 5. proj + bias + residual -> d_out
    dim3 gp(16, 8, 16);
    sgemm_kernel<<<gp, 256>>>(w_p, attn, b_p, x, out,
                              512, 1024, 512, 512L * 1024, 512L * 1024);
}

// round 2
// speedup vs baseline: 1.5511x; 1.5511x over previous
#include <cuda_runtime.h>
#include <cuda_bf16.h>
#include <cstdint>

// B=16, C=512, T=1024, L=77, S=1101, HEADS=8, D=64, GROUPS=32, CROSS=768

__device__ float g_xn[16 * 512 * 1024];
__device__ float g_qkv[16 * 1536 * 1024];
__device__ float g_ckv[16 * 1024 * 77];
__device__ float g_attn[16 * 512 * 1024];

// ---------------------------------------------------------------------------
// helpers: tf32 convert / split, mma.m16n8k8 tf32
// ---------------------------------------------------------------------------
__device__ __forceinline__ unsigned f2tf(float x) {
    unsigned r; asm("cvt.rna.tf32.f32 %0, %1;" : "=r"(r) : "f"(x)); return r;
}
__device__ __forceinline__ void split_tf(float x, unsigned& hi, unsigned& lo) {
    hi = f2tf(x);
    lo = f2tf(x - __uint_as_float(hi));
}
__device__ __forceinline__ void mma_tf32(float* c, unsigned a0, unsigned a1,
                                         unsigned a2, unsigned a3,
                                         unsigned b0, unsigned b1) {
    asm volatile(
        "mma.sync.aligned.m16n8k8.row.col.f32.tf32.tf32.f32 "
        "{%0,%1,%2,%3},{%4,%5,%6,%7},{%8,%9},{%0,%1,%2,%3};"
        : "+f"(c[0]), "+f"(c[1]), "+f"(c[2]), "+f"(c[3])
        : "r"(a0), "r"(a1), "r"(a2), "r"(a3), "r"(b0), "r"(b1));
}

// ---------------------------------------------------------------------------
// GroupNorm(32)
// ---------------------------------------------------------------------------
__global__ __launch_bounds__(256)
void groupnorm_kernel(const float* __restrict__ x,
                      const float* __restrict__ gamma,
                      const float* __restrict__ beta,
                      float* __restrict__ xn)
{
    int b = blockIdx.x >> 5;
    int g = blockIdx.x & 31;
    const float* xp = x + ((size_t)b * 512 + (size_t)g * 16) * 1024;

    float s = 0.f, s2 = 0.f;
    for (int i = threadIdx.x; i < 16384; i += 256) {
        float v = xp[i];
        s += v; s2 += v * v;
    }
#pragma unroll
    for (int o = 16; o > 0; o >>= 1) {
        s  += __shfl_xor_sync(0xffffffffu, s, o);
        s2 += __shfl_xor_sync(0xffffffffu, s2, o);
    }
    __shared__ float ss[8], ss2[8];
    __shared__ float smean, sinv;
    int w = threadIdx.x >> 5;
    if ((threadIdx.x & 31) == 0) { ss[w] = s; ss2[w] = s2; }
    __syncthreads();
    if (threadIdx.x == 0) {
        float S = 0.f, S2 = 0.f;
#pragma unroll
        for (int i = 0; i < 8; i++) { S += ss[i]; S2 += ss2[i]; }
        float mean = S * (1.f / 16384.f);
        float var  = S2 * (1.f / 16384.f) - mean * mean;
        smean = mean;
        sinv  = rsqrtf(var + 1e-5f);
    }
    __syncthreads();
    float mean = smean, inv = sinv;
    float* op = xn + ((size_t)b * 512 + (size_t)g * 16) * 1024;
    for (int i = threadIdx.x; i < 16384; i += 256) {
        int ch = g * 16 + (i >> 10);
        op[i] = (xp[i] - mean) * inv * gamma[ch] + beta[ch];
    }
}

// ---------------------------------------------------------------------------
// 3xTF32 GEMM: out[b] = W[M,K] @ X[b][K,N] + bias (+res), fp32-grade accuracy.
// Block tile 128x128, BK=16, 256 thr = 8 warps (2m x 4n), warp tile 64x32.
// M % 128 == 0, K % 16 == 0; N guarded.
// ---------------------------------------------------------------------------
__global__ __launch_bounds__(256)
void gemm3x_kernel(const float* __restrict__ W, const float* __restrict__ X,
                   const float* __restrict__ bias, const float* __restrict__ res,
                   float* __restrict__ out,
                   int M, int N, int K, long xStride, long outStride)
{
    int b = blockIdx.z;
    X   += (size_t)b * xStride;
    out += (size_t)b * outStride;
    const float* resp = res ? (res + (size_t)b * outStride) : nullptr;

    __shared__ float Wh[128 * 20], Wl[128 * 20];   // [m][k] stride 20
    __shared__ float Xh[16 * 136], Xl[16 * 136];   // [k][n] stride 136

    int tid = threadIdx.x;
    int w = tid >> 5, lane = tid & 31;
    int g = lane >> 2, tg = lane & 3;
    int warp_m = w >> 2, warp_n = w & 3;
    int m0 = blockIdx.y * 128, n0 = blockIdx.x * 128;

    float acc[4][4][4];
#pragma unroll
    for (int i = 0; i < 4; i++)
#pragma unroll
        for (int j = 0; j < 4; j++)
#pragma unroll
            for (int c = 0; c < 4; c++) acc[i][j][c] = 0.f;

    bool fullN = (n0 + 128 <= N);

    for (int k0 = 0; k0 < K; k0 += 16) {
        // load W tile 128x16
#pragma unroll
        for (int i = 0; i < 2; i++) {
            int m = (tid >> 2) + i * 64;
            int kk = (tid & 3) * 4;
            float4 wv = *(const float4*)&W[(size_t)(m0 + m) * K + k0 + kk];
            unsigned h, l;
            split_tf(wv.x, h, l); Wh[m*20+kk+0] = __uint_as_float(h); Wl[m*20+kk+0] = __uint_as_float(l);
            split_tf(wv.y, h, l); Wh[m*20+kk+1] = __uint_as_float(h); Wl[m*20+kk+1] = __uint_as_float(l);
            split_tf(wv.z, h, l); Wh[m*20+kk+2] = __uint_as_float(h); Wl[m*20+kk+2] = __uint_as_float(l);
            split_tf(wv.w, h, l); Wh[m*20+kk+3] = __uint_as_float(h); Wl[m*20+kk+3] = __uint_as_float(l);
        }
        // load X tile 16x128
#pragma unroll
        for (int i = 0; i < 2; i++) {
            int kk = (tid >> 5) + i * 8;
            int n4 = (tid & 31) * 4;
            float xv[4];
            if (fullN) {
                float4 t = *(const float4*)&X[(size_t)(k0 + kk) * N + n0 + n4];
                xv[0]=t.x; xv[1]=t.y; xv[2]=t.z; xv[3]=t.w;
            } else {
#pragma unroll
                for (int j = 0; j < 4; j++)
                    xv[j] = (n0 + n4 + j < N) ? X[(size_t)(k0 + kk) * N + n0 + n4 + j] : 0.f;
            }
#pragma unroll
            for (int j = 0; j < 4; j++) {
                unsigned h, l; split_tf(xv[j], h, l);
                Xh[kk*136 + n4 + j] = __uint_as_float(h);
                Xl[kk*136 + n4 + j] = __uint_as_float(l);
            }
        }
        __syncthreads();

#pragma unroll
        for (int ks = 0; ks < 16; ks += 8) {
            unsigned ah[4][4], al[4][4], bh[4][2], bl[4][2];
#pragma unroll
            for (int mt = 0; mt < 4; mt++) {
                int rb = warp_m * 64 + mt * 16;
                ah[mt][0] = __float_as_uint(Wh[(rb+g  )*20 + ks+tg  ]);
                ah[mt][1] = __float_as_uint(Wh[(rb+g+8)*20 + ks+tg  ]);
                ah[mt][2] = __float_as_uint(Wh[(rb+g  )*20 + ks+tg+4]);
                ah[mt][3] = __float_as_uint(Wh[(rb+g+8)*20 + ks+tg+4]);
                al[mt][0] = __float_as_uint(Wl[(rb+g  )*20 + ks+tg  ]);
                al[mt][1] = __float_as_uint(Wl[(rb+g+8)*20 + ks+tg  ]);
                al[mt][2] = __float_as_uint(Wl[(rb+g  )*20 + ks+tg+4]);
                al[mt][3] = __float_as_uint(Wl[(rb+g+8)*20 + ks+tg+4]);
            }
#pragma unroll
            for (int nt = 0; nt < 4; nt++) {
                int cb = warp_n * 32 + nt * 8 + g;
                bh[nt][0] = __float_as_uint(Xh[(ks+tg  )*136 + cb]);
                bh[nt][1] = __float_as_uint(Xh[(ks+tg+4)*136 + cb]);
                bl[nt][0] = __float_as_uint(Xl[(ks+tg  )*136 + cb]);
                bl[nt][1] = __float_as_uint(Xl[(ks+tg+4)*136 + cb]);
            }
#pragma unroll
            for (int mt = 0; mt < 4; mt++)
#pragma unroll
                for (int nt = 0; nt < 4; nt++) {
                    mma_tf32(acc[mt][nt], ah[mt][0],ah[mt][1],ah[mt][2],ah[mt][3], bl[nt][0], bl[nt][1]);
                    mma_tf32(acc[mt][nt], al[mt][0],al[mt][1],al[mt][2],al[mt][3], bh[nt][0], bh[nt][1]);
                    mma_tf32(acc[mt][nt], ah[mt][0],ah[mt][1],ah[mt][2],ah[mt][3], bh[nt][0], bh[nt][1]);
                }
        }
        __syncthreads();
    }

    // epilogue
#pragma unroll
    for (int mt = 0; mt < 4; mt++) {
#pragma unroll
        for (int rr = 0; rr < 2; rr++) {
            int m = m0 + warp_m * 64 + mt * 16 + rr * 8 + g;
            float bi = bias[m];
#pragma unroll
            for (int nt = 0; nt < 4; nt++) {
#pragma unroll
                for (int ci = 0; ci < 2; ci++) {
                    int n = n0 + warp_n * 32 + nt * 8 + 2 * tg + ci;
                    if (n < N) {
                        float v = acc[mt][nt][rr * 2 + ci] + bi;
                        if (resp) v += resp[(size_t)m * N + n];
                        out[(size_t)m * N + n] = v;
                    }
                }
            }
        }
    }
}

// ---------------------------------------------------------------------------
// Flash attention with tf32 mma. Block = 128 queries for one (b,h).
// 256 thr = 8 warps, warp grid 4(m) x 2(n).
// S tile 128q x 128k: QK^T via 3xTF32 (accurate logits).
// P·V via 1x tf32. Online softmax per key tile.
// ---------------------------------------------------------------------------
__global__ __launch_bounds__(256)
void attn_mma_kernel(const float* __restrict__ qkv, const float* __restrict__ ckv,
                     float* __restrict__ out)
{
    extern __shared__ float sm[];
    float* Qh  = sm;             // [128][68]  tf32-hi of Q^T
    float* Ql  = sm + 8704;      // [128][68]  tf32-lo
    float* Ks  = sm + 17408;     // [64][136]  fp32 K tile (d-major)
    float* Vs  = sm + 26112;     // [64][132]  fp32 V tile (d-major)
    float* Ps  = sm + 34560;     // [128][132] tf32 P
    float* red = sm + 51456;     // [2][128]

    int t0 = blockIdx.x * 128;
    int h  = blockIdx.y;
    int b  = blockIdx.z;
    int tid = threadIdx.x;
    int w = tid >> 5, lane = tid & 31;
    int g = lane >> 2, tg = lane & 3;
    int warp_m = w >> 1, warp_n = w & 1;

    const float* qbase = qkv + ((size_t)b * 1536 + (size_t)h * 64) * 1024;
    const float* kbase = qkv + ((size_t)b * 1536 + 512  + (size_t)h * 64) * 1024;
    const float* vbase = qkv + ((size_t)b * 1536 + 1024 + (size_t)h * 64) * 1024;
    const float* kcb   = ckv + ((size_t)b * 1024 + (size_t)h * 64) * 77;
    const float* vcb   = ckv + ((size_t)b * 1024 + 512 + (size_t)h * 64) * 77;

    // load Q (transpose [d][t] -> [t][d]) and split into tf32 hi/lo
    {
        int tl = tid & 127;
        int d0 = tid >> 7;
#pragma unroll
        for (int i = 0; i < 32; i++) {
            int d = d0 + 2 * i;
            float v = qbase[(size_t)d * 1024 + t0 + tl];
            unsigned hi, lo; split_tf(v, hi, lo);
            Qh[tl * 68 + d] = __uint_as_float(hi);
            Ql[tl * 68 + d] = __uint_as_float(lo);
        }
    }

    float oacc[2][4][4];
#pragma unroll
    for (int mt = 0; mt < 2; mt++)
#pragma unroll
        for (int nt = 0; nt < 4; nt++)
#pragma unroll
            for (int c = 0; c < 4; c++) oacc[mt][nt][c] = 0.f;
    float m_run[2][2] = {{-1e30f,-1e30f},{-1e30f,-1e30f}};
    float l_run[2][2] = {{0.f,0.f},{0.f,0.f}};

    __syncthreads();

    for (int kt = 0; kt < 9; kt++) {
        int s0 = kt * 128;
        // ---- load K/V tile ----
        if (kt < 8) {
#pragma unroll
            for (int i = 0; i < 8; i++) {
                int d = (tid >> 5) + 8 * i;
                int s4 = (tid & 31) * 4;
                float4 kf = *(const float4*)&kbase[(size_t)d * 1024 + s0 + s4];
                float4 vf = *(const float4*)&vbase[(size_t)d * 1024 + s0 + s4];
                *(float4*)&Ks[d * 136 + s4] = kf;
                *(float4*)&Vs[d * 132 + s4] = vf;
            }
        } else {
#pragma unroll
            for (int i = 0; i < 32; i++) {
                int p = tid + 256 * i;
                int d = p >> 7, s = p & 127;
                float kv = 0.f, vv = 0.f;
                if (s < 77) {
                    kv = kcb[d * 77 + s];
                    vv = vcb[d * 77 + s];
                }
                Ks[d * 136 + s] = kv;
                Vs[d * 132 + s] = vv;
            }
        }
        __syncthreads();

        // ---- S = Q K^T (3xTF32), warp tile 32q x 64k ----
        float sacc[2][8][4];
#pragma unroll
        for (int mt = 0; mt < 2; mt++)
#pragma unroll
            for (int nt = 0; nt < 8; nt++)
#pragma unroll
                for (int c = 0; c < 4; c++) sacc[mt][nt][c] = 0.f;

#pragma unroll
        for (int ks = 0; ks < 8; ks++) {
            int kd = ks * 8;
            unsigned ah[2][4], al[2][4];
#pragma unroll
            for (int mt = 0; mt < 2; mt++) {
                int rb = warp_m * 32 + mt * 16;
                ah[mt][0] = __float_as_uint(Qh[(rb+g  )*68 + kd+tg  ]);
                ah[mt][1] = __float_as_uint(Qh[(rb+g+8)*68 + kd+tg  ]);
                ah[mt][2] = __float_as_uint(Qh[(rb+g  )*68 + kd+tg+4]);
                ah[mt][3] = __float_as_uint(Qh[(rb+g+8)*68 + kd+tg+4]);
                al[mt][0] = __float_as_uint(Ql[(rb+g  )*68 + kd+tg  ]);
                al[mt][1] = __float_as_uint(Ql[(rb+g+8)*68 + kd+tg  ]);
                al[mt][2] = __float_as_uint(Ql[(rb+g  )*68 + kd+tg+4]);
                al[mt][3] = __float_as_uint(Ql[(rb+g+8)*68 + kd+tg+4]);
            }
#pragma unroll
            for (int half = 0; half < 2; half++) {
                unsigned bh[4][2], bl[4][2];
#pragma unroll
                for (int j = 0; j < 4; j++) {
                    int nt = half * 4 + j;
                    int cb = warp_n * 64 + nt * 8 + g;
                    float k0v = Ks[(kd+tg  )*136 + cb];
                    float k1v = Ks[(kd+tg+4)*136 + cb];
                    split_tf(k0v, bh[j][0], bl[j][0]);
                    split_tf(k1v, bh[j][1], bl[j][1]);
                }
#pragma unroll
                for (int mt = 0; mt < 2; mt++)
#pragma unroll
                    for (int j = 0; j < 4; j++) {
                        int nt = half * 4 + j;
                        mma_tf32(sacc[mt][nt], ah[mt][0],ah[mt][1],ah[mt][2],ah[mt][3], bl[j][0], bl[j][1]);
                        mma_tf32(sacc[mt][nt], al[mt][0],al[mt][1],al[mt][2],al[mt][3], bh[j][0], bh[j][1]);
                        mma_tf32(sacc[mt][nt], ah[mt][0],ah[mt][1],ah[mt][2],ah[mt][3], bh[j][0], bh[j][1]);
                    }
            }
        }

        // ---- scale + mask ----
#pragma unroll
        for (int mt = 0; mt < 2; mt++)
#pragma unroll
            for (int nt = 0; nt < 8; nt++)
#pragma unroll
                for (int c = 0; c < 4; c++) {
                    float v = sacc[mt][nt][c] * 0.125f;
                    if (kt == 8) {
                        int col = warp_n * 64 + nt * 8 + 2 * tg + (c & 1);
                        if (col >= 77) v = -1e30f;
                    }
                    sacc[mt][nt][c] = v;
                }

        // ---- row max (thread -> tg group -> cross warp_n) ----
        float mx[2][2];
#pragma unroll
        for (int mt = 0; mt < 2; mt++)
#pragma unroll
            for (int rr = 0; rr < 2; rr++) {
                float m = -1e30f;
#pragma unroll
                for (int nt = 0; nt < 8; nt++) {
                    m = fmaxf(m, sacc[mt][nt][rr*2]);
                    m = fmaxf(m, sacc[mt][nt][rr*2+1]);
                }
                m = fmaxf(m, __shfl_xor_sync(0xffffffffu, m, 1));
                m = fmaxf(m, __shfl_xor_sync(0xffffffffu, m, 2));
                mx[mt][rr] = m;
            }
        if (tg == 0) {
#pragma unroll
            for (int mt = 0; mt < 2; mt++)
#pragma unroll
                for (int rr = 0; rr < 2; rr++) {
                    int row = warp_m * 32 + mt * 16 + rr * 8 + g;
                    red[warp_n * 128 + row] = mx[mt][rr];
                }
        }
        __syncthreads();
        float corr[2][2], nm[2][2];
#pragma unroll
        for (int mt = 0; mt < 2; mt++)
#pragma unroll
            for (int rr = 0; rr < 2; rr++) {
                int row = warp_m * 32 + mt * 16 + rr * 8 + g;
                float tot = fmaxf(mx[mt][rr], red[(1 - warp_n) * 128 + row]);
                float newm = fmaxf(m_run[mt][rr], tot);
                corr[mt][rr] = __expf(m_run[mt][rr] - newm);
                nm[mt][rr] = newm;
                m_run[mt][rr] = newm;
            }
        __syncthreads();   // done reading red (max)

        // ---- exp, write P (tf32), row sums ----
        float rs[2][2] = {{0.f,0.f},{0.f,0.f}};
#pragma unroll
        for (int mt = 0; mt < 2; mt++)
#pragma unroll
            for (int rr = 0; rr < 2; rr++) {
                int row = warp_m * 32 + mt * 16 + rr * 8 + g;
#pragma unroll
                for (int nt = 0; nt < 8; nt++) {
#pragma unroll
                    for (int ci = 0; ci < 2; ci++) {
                        float p = __expf(sacc[mt][nt][rr*2+ci] - nm[mt][rr]);
                        rs[mt][rr] += p;
                        int col = warp_n * 64 + nt * 8 + 2 * tg + ci;
                        Ps[row * 132 + col] = __uint_as_float(f2tf(p));
                    }
                }
            }
#pragma unroll
        for (int mt = 0; mt < 2; mt++)
#pragma unroll
            for (int rr = 0; rr < 2; rr++) {
                float s = rs[mt][rr];
                s += __shfl_xor_sync(0xffffffffu, s, 1);
                s += __shfl_xor_sync(0xffffffffu, s, 2);
                rs[mt][rr] = s;
            }
        if (tg == 0) {
#pragma unroll
            for (int mt = 0; mt < 2; mt++)
#pragma unroll
                for (int rr = 0; rr < 2; rr++) {
                    int row = warp_m * 32 + mt * 16 + rr * 8 + g;
                    red[warp_n * 128 + row] = rs[mt][rr];
                }
        }
        // rescale O while waiting
#pragma unroll
        for (int mt = 0; mt < 2; mt++)
#pragma unroll
            for (int nt = 0; nt < 4; nt++) {
                oacc[mt][nt][0] *= corr[mt][0];
                oacc[mt][nt][1] *= corr[mt][0];
                oacc[mt][nt][2] *= corr[mt][1];
                oacc[mt][nt][3] *= corr[mt][1];
            }
        __syncthreads();   // P complete + red(sum) ready
#pragma unroll
        for (int mt = 0; mt < 2; mt++)
#pragma unroll
            for (int rr = 0; rr < 2; rr++) {
                int row = warp_m * 32 + mt * 16 + rr * 8 + g;
                float tot = rs[mt][rr] + red[(1 - warp_n) * 128 + row];
                l_run[mt][rr] = l_run[mt][rr] * corr[mt][rr] + tot;
            }

        // ---- O += P V^T (1x tf32), warp tile 32q x 32d ----
#pragma unroll
        for (int ks = 0; ks < 16; ks++) {
            int kd = ks * 8;
            unsigned pa[2][4];
#pragma unroll
            for (int mt = 0; mt < 2; mt++) {
                int rb = warp_m * 32 + mt * 16;
                pa[mt][0] = __float_as_uint(Ps[(rb+g  )*132 + kd+tg  ]);
                pa[mt][1] = __float_as_uint(Ps[(rb+g+8)*132 + kd+tg  ]);
                pa[mt][2] = __float_as_uint(Ps[(rb+g  )*132 + kd+tg+4]);
                pa[mt][3] = __float_as_uint(Ps[(rb+g+8)*132 + kd+tg+4]);
            }
#pragma unroll
            for (int nt = 0; nt < 4; nt++) {
                int db = warp_n * 32 + nt * 8 + g;
                unsigned b0 = f2tf(Vs[db * 132 + kd + tg]);
                unsigned b1 = f2tf(Vs[db * 132 + kd + tg + 4]);
#pragma unroll
                for (int mt = 0; mt < 2; mt++)
                    mma_tf32(oacc[mt][nt], pa[mt][0],pa[mt][1],pa[mt][2],pa[mt][3], b0, b1);
            }
        }
        __syncthreads();   // before next tile overwrites Ks/Vs/Ps
    }

    // ---- normalize + write out [b][h*64+d][t] ----
    float inv[2][2];
#pragma unroll
    for (int mt = 0; mt < 2; mt++)
#pragma unroll
        for (int rr = 0; rr < 2; rr++) inv[mt][rr] = 1.f / l_run[mt][rr];

    float* ob = out + ((size_t)b * 512 + (size_t)h * 64) * 1024;
#pragma unroll
    for (int mt = 0; mt < 2; mt++)
#pragma unroll
        for (int nt = 0; nt < 4; nt++)
#pragma unroll
            for (int c = 0; c < 4; c++) {
                int rr = c >> 1;
                int t = t0 + warp_m * 32 + mt * 16 + rr * 8 + g;
                int d = warp_n * 32 + nt * 8 + 2 * tg + (c & 1);
                ob[(size_t)d * 1024 + t] = oacc[mt][nt][c] * inv[mt][rr];
            }
}

// ---------------------------------------------------------------------------
extern "C" void kernel_launch(void* const* d_in, const int* in_sizes, int n_in,
                              void* d_out, int out_size)
{
    const float* x     = (const float*)d_in[0];
    const float* c     = (const float*)d_in[1];
    const float* gamma = (const float*)d_in[2];
    const float* beta  = (const float*)d_in[3];
    const float* w_qkv = (const float*)d_in[4];
    const float* b_qkv = (const float*)d_in[5];
    const float* w_c   = (const float*)d_in[6];
    const float* b_c   = (const float*)d_in[7];
    const float* w_p   = (const float*)d_in[8];
    const float* b_p   = (const float*)d_in[9];
    float* out = (float*)d_out;

    float *xn, *qkv, *ckv, *attn;
    cudaGetSymbolAddress((void**)&xn,   g_xn);
    cudaGetSymbolAddress((void**)&qkv,  g_qkv);
    cudaGetSymbolAddress((void**)&ckv,  g_ckv);
    cudaGetSymbolAddress((void**)&attn, g_attn);

    static bool attr_done = false;
    if (!attr_done) {
        cudaFuncSetAttribute(attn_mma_kernel,
                             cudaFuncAttributeMaxDynamicSharedMemorySize, 206848);
        attr_done = true;
    }

    groupnorm_kernel<<<512, 256>>>(x, gamma, beta, xn);

    // qkv: [1536,1024] = W[1536,512] @ xn
    dim3 gq(8, 12, 16);
    gemm3x_kernel<<<gq, 256>>>(w_qkv, xn, b_qkv, nullptr, qkv,
                               1536, 1024, 512, 512L * 1024, 1536L * 1024);

    // cond kv: [1024,77] = Wc[1024,768] @ c
    dim3 gc(1, 8, 16);
    gemm3x_kernel<<<gc, 256>>>(w_c, c, b_c, nullptr, ckv,
                               1024, 77, 768, 768L * 77, 1024L * 77);

    // attention
    dim3 ga(8, 8, 16);
    attn_mma_kernel<<<ga, 256, 206848>>>(qkv, ckv, attn);

    // proj + residual
    dim3 gp(8, 4, 16);
    gemm3x_kernel<<<gp, 256>>>(w_p, attn, b_p, x, out,
                               512, 1024, 512, 512L * 1024, 512L * 1024);
}

// round 5
// speedup vs baseline: 2.9100x; 1.8761x over previous
#include <cuda_runtime.h>
#include <cuda_bf16.h>
#include <cuda_fp16.h>
#include <cstdint>

// B=16, C=512, T=1024, L=77, S=1101(pad->1152), HEADS=8, D=64, GROUPS=32, CROSS=768

__device__ float g_xn[16 * 512 * 1024];
__device__ float g_qkv[16 * 1536 * 1024];
__device__ float g_ckv[16 * 1024 * 77];

__device__ __nv_bfloat16 g_xnT_h[16 * 1024 * 512], g_xnT_l[16 * 1024 * 512];
__device__ __nv_bfloat16 g_cT_h [16 * 77 * 768],   g_cT_l [16 * 77 * 768];
__device__ __nv_bfloat16 g_aT_h [16 * 1024 * 512], g_aT_l [16 * 1024 * 512];
__device__ __nv_bfloat16 g_wq_h[1536 * 512], g_wq_l[1536 * 512];
__device__ __nv_bfloat16 g_wc_h[1024 * 768], g_wc_l[1024 * 768];
__device__ __nv_bfloat16 g_wp_h[512 * 512],  g_wp_l[512 * 512];
__device__ __nv_bfloat16 g_kT_h[128 * 1152 * 64], g_kT_l[128 * 1152 * 64];
__device__ __half        g_vT[128 * 64 * 1152];

#define DINL __device__ __forceinline__

DINL void mma_bf(float* c, const uint32_t* a, uint32_t b0, uint32_t b1) {
    asm volatile(
        "mma.sync.aligned.m16n8k16.row.col.f32.bf16.bf16.f32 "
        "{%0,%1,%2,%3},{%4,%5,%6,%7},{%8,%9},{%0,%1,%2,%3};"
        : "+f"(c[0]), "+f"(c[1]), "+f"(c[2]), "+f"(c[3])
        : "r"(a[0]), "r"(a[1]), "r"(a[2]), "r"(a[3]), "r"(b0), "r"(b1));
}
DINL void mma_f16(float* c, const uint32_t* a, uint32_t b0, uint32_t b1) {
    asm volatile(
        "mma.sync.aligned.m16n8k16.row.col.f32.f16.f16.f32 "
        "{%0,%1,%2,%3},{%4,%5,%6,%7},{%8,%9},{%0,%1,%2,%3};"
        : "+f"(c[0]), "+f"(c[1]), "+f"(c[2]), "+f"(c[3])
        : "r"(a[0]), "r"(a[1]), "r"(a[2]), "r"(a[3]), "r"(b0), "r"(b1));
}
DINL uint32_t pack_h2(float a, float b) {
    __half2 h = __floats2half2_rn(a, b);
    return *(uint32_t*)&h;
}

// ---------------------------------------------------------------------------
// GroupNorm(32)
// ---------------------------------------------------------------------------
__global__ __launch_bounds__(256)
void groupnorm_kernel(const float* __restrict__ x,
                      const float* __restrict__ gamma,
                      const float* __restrict__ beta,
                      float* __restrict__ xn)
{
    int b = blockIdx.x >> 5;
    int g = blockIdx.x & 31;
    const float* xp = x + ((size_t)b * 512 + (size_t)g * 16) * 1024;

    float s = 0.f, s2 = 0.f;
    for (int i = threadIdx.x; i < 16384; i += 256) {
        float v = xp[i];
        s += v; s2 += v * v;
    }
#pragma unroll
    for (int o = 16; o > 0; o >>= 1) {
        s  += __shfl_xor_sync(0xffffffffu, s, o);
        s2 += __shfl_xor_sync(0xffffffffu, s2, o);
    }
    __shared__ float ss[8], ss2[8];
    __shared__ float smean, sinv;
    int w = threadIdx.x >> 5;
    if ((threadIdx.x & 31) == 0) { ss[w] = s; ss2[w] = s2; }
    __syncthreads();
    if (threadIdx.x == 0) {
        float S = 0.f, S2 = 0.f;
#pragma unroll
        for (int i = 0; i < 8; i++) { S += ss[i]; S2 += ss2[i]; }
        float mean = S * (1.f / 16384.f);
        float var  = S2 * (1.f / 16384.f) - mean * mean;
        smean = mean;
        sinv  = rsqrtf(var + 1e-5f);
    }
    __syncthreads();
    float mean = smean, inv = sinv;
    float* op = xn + ((size_t)b * 512 + (size_t)g * 16) * 1024;
    for (int i = threadIdx.x; i < 16384; i += 256) {
        int ch = g * 16 + (i >> 10);
        op[i] = (xp[i] - mean) * inv * gamma[ch] + beta[ch];
    }
}

// ---------------------------------------------------------------------------
// fp32 -> bf16 hi/lo split (weights, elementwise)
// ---------------------------------------------------------------------------
__global__ __launch_bounds__(256)
void splitW_kernel(const float* __restrict__ w, __nv_bfloat16* __restrict__ h,
                   __nv_bfloat16* __restrict__ l, int n)
{
    int i = blockIdx.x * 256 + threadIdx.x;
    if (i < n) {
        float x = w[i];
        __nv_bfloat16 hi = __float2bfloat16(x);
        h[i] = hi;
        l[i] = __float2bfloat16(x - __bfloat162float(hi));
    }
}

// ---------------------------------------------------------------------------
// Transpose + split: in [b][C][T] fp32 -> oh/ol [b][T][C] bf16
// ---------------------------------------------------------------------------
__global__ __launch_bounds__(256)
void splitT_kernel(const float* __restrict__ in, __nv_bfloat16* __restrict__ oh,
                   __nv_bfloat16* __restrict__ ol, int C, int T)
{
    __shared__ float tile[32][33];
    int t0 = blockIdx.x * 32, cb = blockIdx.y * 32, b = blockIdx.z;
    const float* ip = in + (size_t)b * C * T;
    int tx = threadIdx.x & 31, ty = threadIdx.x >> 5;
#pragma unroll
    for (int i = 0; i < 4; i++) {
        int cr = ty + i * 8;
        tile[cr][tx] = (t0 + tx < T) ? ip[(size_t)(cb + cr) * T + t0 + tx] : 0.f;
    }
    __syncthreads();
    size_t ob = (size_t)b * C * T;
#pragma unroll
    for (int i = 0; i < 4; i++) {
        int tr = ty + i * 8;
        if (t0 + tr < T) {
            float x = tile[tx][tr];
            __nv_bfloat16 h = __float2bfloat16(x);
            __nv_bfloat16 l = __float2bfloat16(x - __bfloat162float(h));
            oh[ob + (size_t)(t0 + tr) * C + cb + tx] = h;
            ol[ob + (size_t)(t0 + tr) * C + cb + tx] = l;
        }
    }
}

// ---------------------------------------------------------------------------
// Attention operand prep (self region s<1024):
//  kT h/l bf16 [bh][s][64], vT fp16 [bh][64][1152]
// ---------------------------------------------------------------------------
__global__ __launch_bounds__(256)
void prep_self(const float* __restrict__ qkv, __nv_bfloat16* __restrict__ kTh,
               __nv_bfloat16* __restrict__ kTl, __half* __restrict__ vT)
{
    __shared__ float tile[64 * 129];
    int s0 = blockIdx.x * 128;
    int bh = blockIdx.y, b = bh >> 3, h = bh & 7;
    const float* kc = qkv + ((size_t)b * 1536 + 512  + h * 64) * 1024;
    const float* vc = qkv + ((size_t)b * 1536 + 1024 + h * 64) * 1024;
    int tid = threadIdx.x;
#pragma unroll
    for (int it = 0; it < 32; it++) {
        int i = tid + it * 256;
        int d = i >> 7, s = i & 127;
        tile[d * 129 + s] = kc[(size_t)d * 1024 + s0 + s];
        vT[((size_t)bh * 64 + d) * 1152 + s0 + s] = __float2half(vc[(size_t)d * 1024 + s0 + s]);
    }
    __syncthreads();
#pragma unroll
    for (int it = 0; it < 32; it++) {
        int i = tid + it * 256;
        int s = i >> 6, d = i & 63;
        float x = tile[d * 129 + s];
        __nv_bfloat16 hi = __float2bfloat16(x);
        size_t o = ((size_t)bh * 1152 + s0 + s) * 64 + d;
        kTh[o] = hi;
        kTl[o] = __float2bfloat16(x - __bfloat162float(hi));
    }
}

// cond region s in [1024,1152): data from ckv for local s<77, else 0
__global__ __launch_bounds__(256)
void prep_cond(const float* __restrict__ ckv, __nv_bfloat16* __restrict__ kTh,
               __nv_bfloat16* __restrict__ kTl, __half* __restrict__ vT)
{
    int bh = blockIdx.x, b = bh >> 3, h = bh & 7;
    int tid = threadIdx.x;
#pragma unroll
    for (int it = 0; it < 32; it++) {
        int i = tid + it * 256;
        int d = i & 63, sl = i >> 6;
        float kv = 0.f;
        if (sl < 77) kv = ckv[((size_t)b * 1024 + h * 64 + d) * 77 + sl];
        __nv_bfloat16 hi = __float2bfloat16(kv);
        size_t o = ((size_t)bh * 1152 + 1024 + sl) * 64 + d;
        kTh[o] = hi;
        kTl[o] = __float2bfloat16(kv - __bfloat162float(hi));
    }
#pragma unroll
    for (int it = 0; it < 32; it++) {
        int i = tid + it * 256;
        int sl = i & 127, d = i >> 7;
        float vv = 0.f;
        if (sl < 77) vv = ckv[((size_t)b * 1024 + 512 + h * 64 + d) * 77 + sl];
        vT[((size_t)bh * 64 + d) * 1152 + 1024 + sl] = __float2half(vv);
    }
}

// ---------------------------------------------------------------------------
// bf16x3 GEMM via mma.m16n8k16:
// out[b][m][n] = sum_k W[m][k] * XT[b][n][k] + bias[m] (+res)
// Block 128x128, BK=64, 256 thr = 8 warps (2m x 4n), warp tile 64x32.
// Smem row stride 36 words (72 bf16) -> conflict-free fragment loads.
// ---------------------------------------------------------------------------
__global__ __launch_bounds__(256)
void gemm_bf(const __nv_bfloat16* __restrict__ Wh, const __nv_bfloat16* __restrict__ Wl,
             const __nv_bfloat16* __restrict__ Xh, const __nv_bfloat16* __restrict__ Xl,
             const float* __restrict__ bias, const float* __restrict__ res,
             float* __restrict__ out, int M, int N, int K, long xStride, long outStride)
{
    extern __shared__ uint32_t gsm[];
    const int OWH = 0, OWL = 4608, OXH = 9216, OXL = 13824;   // word offsets

    int b = blockIdx.z;
    Xh += (size_t)b * xStride;
    Xl += (size_t)b * xStride;
    out += (size_t)b * outStride;
    const float* resp = res ? (res + (size_t)b * outStride) : nullptr;

    int tid = threadIdx.x, w = tid >> 5, lane = tid & 31;
    int g = lane >> 2, tg = lane & 3;
    int warp_m = w >> 2, warp_n = w & 3;
    int m0 = blockIdx.y * 128, n0 = blockIdx.x * 128;

    float acc[4][4][4];
#pragma unroll
    for (int i = 0; i < 4; i++)
#pragma unroll
        for (int j = 0; j < 4; j++)
#pragma unroll
            for (int c = 0; c < 4; c++) acc[i][j][c] = 0.f;

    for (int k0 = 0; k0 < K; k0 += 64) {
#pragma unroll
        for (int it = 0; it < 4; it++) {
            int i = tid + it * 256;
            int row = i >> 3, seg = i & 7;
            *(uint4*)(gsm + OWH + row * 36 + seg * 4) =
                *(const uint4*)(Wh + (size_t)(m0 + row) * K + k0 + seg * 8);
            *(uint4*)(gsm + OWL + row * 36 + seg * 4) =
                *(const uint4*)(Wl + (size_t)(m0 + row) * K + k0 + seg * 8);
            uint4 xh = make_uint4(0, 0, 0, 0), xl = xh;
            if (n0 + row < N) {
                xh = *(const uint4*)(Xh + (size_t)(n0 + row) * K + k0 + seg * 8);
                xl = *(const uint4*)(Xl + (size_t)(n0 + row) * K + k0 + seg * 8);
            }
            *(uint4*)(gsm + OXH + row * 36 + seg * 4) = xh;
            *(uint4*)(gsm + OXL + row * 36 + seg * 4) = xl;
        }
        __syncthreads();
#pragma unroll
        for (int ks = 0; ks < 4; ks++) {
            int kb = ks * 8;
            uint32_t ah[4][4], al[4][4];
#pragma unroll
            for (int mt = 0; mt < 4; mt++) {
                int rb = warp_m * 64 + mt * 16;
                ah[mt][0] = gsm[OWH + (rb+g  )*36 + kb + tg];
                ah[mt][1] = gsm[OWH + (rb+g+8)*36 + kb + tg];
                ah[mt][2] = gsm[OWH + (rb+g  )*36 + kb + tg + 4];
                ah[mt][3] = gsm[OWH + (rb+g+8)*36 + kb + tg + 4];
                al[mt][0] = gsm[OWL + (rb+g  )*36 + kb + tg];
                al[mt][1] = gsm[OWL + (rb+g+8)*36 + kb + tg];
                al[mt][2] = gsm[OWL + (rb+g  )*36 + kb + tg + 4];
                al[mt][3] = gsm[OWL + (rb+g+8)*36 + kb + tg + 4];
            }
#pragma unroll
            for (int nt = 0; nt < 4; nt++) {
                int cb = warp_n * 32 + nt * 8 + g;
                uint32_t bh0 = gsm[OXH + cb*36 + kb + tg];
                uint32_t bh1 = gsm[OXH + cb*36 + kb + tg + 4];
                uint32_t bl0 = gsm[OXL + cb*36 + kb + tg];
                uint32_t bl1 = gsm[OXL + cb*36 + kb + tg + 4];
#pragma unroll
                for (int mt = 0; mt < 4; mt++) {
                    mma_bf(acc[mt][nt], ah[mt], bl0, bl1);
                    mma_bf(acc[mt][nt], al[mt], bh0, bh1);
                    mma_bf(acc[mt][nt], ah[mt], bh0, bh1);
                }
            }
        }
        __syncthreads();
    }

#pragma unroll
    for (int mt = 0; mt < 4; mt++) {
#pragma unroll
        for (int rr = 0; rr < 2; rr++) {
            int m = m0 + warp_m * 64 + mt * 16 + rr * 8 + g;
            float bi = bias[m];
#pragma unroll
            for (int nt = 0; nt < 4; nt++) {
#pragma unroll
                for (int ci = 0; ci < 2; ci++) {
                    int n = n0 + warp_n * 32 + nt * 8 + 2 * tg + ci;
                    if (n < N) {
                        float v = acc[mt][nt][rr * 2 + ci] + bi;
                        if (resp) v += resp[(size_t)m * N + n];
                        out[(size_t)m * N + n] = v;
                    }
                }
            }
        }
    }
}

// ---------------------------------------------------------------------------
// Flash attention: QK^T bf16x3 k16, softmax fp32, P·V fp16 k16 (1 pass).
// Block = 128 queries for (b,h); 256 thr = 8 warps (4m x 2n).
// Output written directly as proj B operand: aT h/l bf16 [b][t][512].
// ---------------------------------------------------------------------------
__global__ __launch_bounds__(256)
void attn_kernel(const float* __restrict__ qkv,
                 const __nv_bfloat16* __restrict__ kTh,
                 const __nv_bfloat16* __restrict__ kTl,
                 const __half* __restrict__ vT,
                 __nv_bfloat16* __restrict__ aTh, __nv_bfloat16* __restrict__ aTl)
{
    extern __shared__ uint32_t smw[];
    const int OQH = 0, OQL = 4608, OKH = 9216, OKL = 13824, OV = 18432, OP = 22784;
    float* red = (float*)(smw + 31488);   // [2][128]

    int t0 = blockIdx.x * 128;
    int h  = blockIdx.y;
    int b  = blockIdx.z;
    int bh = b * 8 + h;
    int tid = threadIdx.x;
    int w = tid >> 5, lane = tid & 31;
    int g = lane >> 2, tg = lane & 3;
    int warp_m = w >> 1, warp_n = w & 1;

    // ---- stage Q (transpose + bf16 split) ----
    {
        const float* qbase = qkv + ((size_t)b * 1536 + h * 64) * 1024 + t0;
        __nv_bfloat16* Qhb = (__nv_bfloat16*)(smw + OQH);
        __nv_bfloat16* Qlb = (__nv_bfloat16*)(smw + OQL);
        int tl = tid & 127, dh = tid >> 7;
#pragma unroll
        for (int i = 0; i < 32; i++) {
            int d = dh * 32 + i;
            float x = qbase[(size_t)d * 1024 + tl];
            __nv_bfloat16 hi = __float2bfloat16(x);
            Qhb[tl * 72 + d] = hi;
            Qlb[tl * 72 + d] = __float2bfloat16(x - __bfloat162float(hi));
        }
    }

    float oacc[2][4][4];
#pragma unroll
    for (int mt = 0; mt < 2; mt++)
#pragma unroll
        for (int nt = 0; nt < 4; nt++)
#pragma unroll
            for (int c = 0; c < 4; c++) oacc[mt][nt][c] = 0.f;
    float m_run[2][2] = {{-1e30f,-1e30f},{-1e30f,-1e30f}};
    float l_run[2][2] = {{0.f,0.f},{0.f,0.f}};

    __syncthreads();

    for (int kt = 0; kt < 9; kt++) {
        // ---- stage K tile [s][64] bf16 h/l, V tile [d][128] fp16 ----
        {
            const __nv_bfloat16* kh = kTh + ((size_t)bh * 1152 + kt * 128) * 64;
            const __nv_bfloat16* kl = kTl + ((size_t)bh * 1152 + kt * 128) * 64;
#pragma unroll
            for (int it = 0; it < 4; it++) {
                int i = tid + it * 256;
                int s = i >> 3, seg = i & 7;
                *(uint4*)(smw + OKH + s * 36 + seg * 4) = *(const uint4*)(kh + s * 64 + seg * 8);
                *(uint4*)(smw + OKL + s * 36 + seg * 4) = *(const uint4*)(kl + s * 64 + seg * 8);
            }
            const __half* vs = vT + (size_t)bh * 64 * 1152 + kt * 128;
#pragma unroll
            for (int it = 0; it < 4; it++) {
                int i = tid + it * 256;
                int d = i >> 4, seg = i & 15;
                *(uint4*)(smw + OV + d * 68 + seg * 4) = *(const uint4*)(vs + (size_t)d * 1152 + seg * 8);
            }
        }
        __syncthreads();

        // ---- S = Q K^T (bf16x3), warp tile 32q x 64s ----
        float sacc[2][8][4];
#pragma unroll
        for (int mt = 0; mt < 2; mt++)
#pragma unroll
            for (int nt = 0; nt < 8; nt++)
#pragma unroll
                for (int c = 0; c < 4; c++) sacc[mt][nt][c] = 0.f;

#pragma unroll
        for (int ks = 0; ks < 4; ks++) {
            int kb = ks * 8;
            uint32_t ah[2][4], al[2][4];
#pragma unroll
            for (int mt = 0; mt < 2; mt++) {
                int rb = warp_m * 32 + mt * 16;
                ah[mt][0] = smw[OQH + (rb+g  )*36 + kb + tg];
                ah[mt][1] = smw[OQH + (rb+g+8)*36 + kb + tg];
                ah[mt][2] = smw[OQH + (rb+g  )*36 + kb + tg + 4];
                ah[mt][3] = smw[OQH + (rb+g+8)*36 + kb + tg + 4];
                al[mt][0] = smw[OQL + (rb+g  )*36 + kb + tg];
                al[mt][1] = smw[OQL + (rb+g+8)*36 + kb + tg];
                al[mt][2] = smw[OQL + (rb+g  )*36 + kb + tg + 4];
                al[mt][3] = smw[OQL + (rb+g+8)*36 + kb + tg + 4];
            }
#pragma unroll
            for (int nt = 0; nt < 8; nt++) {
                int cb = warp_n * 64 + nt * 8 + g;
                uint32_t bh0 = smw[OKH + cb*36 + kb + tg];
                uint32_t bh1 = smw[OKH + cb*36 + kb + tg + 4];
                uint32_t bl0 = smw[OKL + cb*36 + kb + tg];
                uint32_t bl1 = smw[OKL + cb*36 + kb + tg + 4];
#pragma unroll
                for (int mt = 0; mt < 2; mt++) {
                    mma_bf(sacc[mt][nt], ah[mt], bl0, bl1);
                    mma_bf(sacc[mt][nt], al[mt], bh0, bh1);
                    mma_bf(sacc[mt][nt], ah[mt], bh0, bh1);
                }
            }
        }

        // ---- scale + mask ----
#pragma unroll
        for (int mt = 0; mt < 2; mt++)
#pragma unroll
            for (int nt = 0; nt < 8; nt++)
#pragma unroll
                for (int c = 0; c < 4; c++) {
                    float v = sacc[mt][nt][c] * 0.125f;
                    if (kt == 8) {
                        int col = warp_n * 64 + nt * 8 + 2 * tg + (c & 1);
                        if (col >= 77) v = -1e30f;
                    }
                    sacc[mt][nt][c] = v;
                }

        // ---- row max ----
        float mx[2][2];
#pragma unroll
        for (int mt = 0; mt < 2; mt++)
#pragma unroll
            for (int rr = 0; rr < 2; rr++) {
                float m = -1e30f;
#pragma unroll
                for (int nt = 0; nt < 8; nt++) {
                    m = fmaxf(m, sacc[mt][nt][rr*2]);
                    m = fmaxf(m, sacc[mt][nt][rr*2+1]);
                }
                m = fmaxf(m, __shfl_xor_sync(0xffffffffu, m, 1));
                m = fmaxf(m, __shfl_xor_sync(0xffffffffu, m, 2));
                mx[mt][rr] = m;
            }
        if (tg == 0) {
#pragma unroll
            for (int mt = 0; mt < 2; mt++)
#pragma unroll
                for (int rr = 0; rr < 2; rr++) {
                    int row = warp_m * 32 + mt * 16 + rr * 8 + g;
                    red[warp_n * 128 + row] = mx[mt][rr];
                }
        }
        __syncthreads();
        float corr[2][2], nm[2][2];
#pragma unroll
        for (int mt = 0; mt < 2; mt++)
#pragma unroll
            for (int rr = 0; rr < 2; rr++) {
                int row = warp_m * 32 + mt * 16 + rr * 8 + g;
                float tot = fmaxf(mx[mt][rr], red[(1 - warp_n) * 128 + row]);
                float newm = fmaxf(m_run[mt][rr], tot);
                corr[mt][rr] = __expf(m_run[mt][rr] - newm);
                nm[mt][rr] = newm;
                m_run[mt][rr] = newm;
            }
        __syncthreads();   // done reading red(max)

        // ---- exp, write P (fp16), row sums ----
        float rs[2][2] = {{0.f,0.f},{0.f,0.f}};
#pragma unroll
        for (int mt = 0; mt < 2; mt++)
#pragma unroll
            for (int rr = 0; rr < 2; rr++) {
                int row = warp_m * 32 + mt * 16 + rr * 8 + g;
#pragma unroll
                for (int nt = 0; nt < 8; nt++) {
                    float p0 = __expf(sacc[mt][nt][rr*2]   - nm[mt][rr]);
                    float p1 = __expf(sacc[mt][nt][rr*2+1] - nm[mt][rr]);
                    rs[mt][rr] += p0 + p1;
                    smw[OP + row * 68 + warp_n * 32 + nt * 4 + tg] = pack_h2(p0, p1);
                }
            }
#pragma unroll
        for (int mt = 0; mt < 2; mt++)
#pragma unroll
            for (int rr = 0; rr < 2; rr++) {
                float s = rs[mt][rr];
                s += __shfl_xor_sync(0xffffffffu, s, 1);
                s += __shfl_xor_sync(0xffffffffu, s, 2);
                rs[mt][rr] = s;
            }
        if (tg == 0) {
#pragma unroll
            for (int mt = 0; mt < 2; mt++)
#pragma unroll
                for (int rr = 0; rr < 2; rr++) {
                    int row = warp_m * 32 + mt * 16 + rr * 8 + g;
                    red[warp_n * 128 + row] = rs[mt][rr];
                }
        }
        // rescale O while waiting
#pragma unroll
        for (int mt = 0; mt < 2; mt++)
#pragma unroll
            for (int nt = 0; nt < 4; nt++) {
                oacc[mt][nt][0] *= corr[mt][0];
                oacc[mt][nt][1] *= corr[mt][0];
                oacc[mt][nt][2] *= corr[mt][1];
                oacc[mt][nt][3] *= corr[mt][1];
            }
        __syncthreads();   // P complete + red(sum) ready
#pragma unroll
        for (int mt = 0; mt < 2; mt++)
#pragma unroll
            for (int rr = 0; rr < 2; rr++) {
                int row = warp_m * 32 + mt * 16 + rr * 8 + g;
                float tot = rs[mt][rr] + red[(1 - warp_n) * 128 + row];
                l_run[mt][rr] = l_run[mt][rr] * corr[mt][rr] + tot;
            }

        // ---- O += P·V (fp16, 1 pass), warp tile 32q x 32d ----
#pragma unroll
        for (int ks = 0; ks < 8; ks++) {
            int kb = ks * 8;
            uint32_t pa[2][4];
#pragma unroll
            for (int mt = 0; mt < 2; mt++) {
                int rb = warp_m * 32 + mt * 16;
                pa[mt][0] = smw[OP + (rb+g  )*68 + kb + tg];
                pa[mt][1] = smw[OP + (rb+g+8)*68 + kb + tg];
                pa[mt][2] = smw[OP + (rb+g  )*68 + kb + tg + 4];
                pa[mt][3] = smw[OP + (rb+g+8)*68 + kb + tg + 4];
            }
#pragma unroll
            for (int nt = 0; nt < 4; nt++) {
                int db = warp_n * 32 + nt * 8 + g;
                uint32_t b0 = smw[OV + db*68 + kb + tg];
                uint32_t b1 = smw[OV + db*68 + kb + tg + 4];
#pragma unroll
                for (int mt = 0; mt < 2; mt++)
                    mma_f16(oacc[mt][nt], pa[mt], b0, b1);
            }
        }
        __syncthreads();   // before next tile overwrites K/V/P
    }

    // ---- normalize + write aT (proj B operand) ----
    float inv[2][2];
#pragma unroll
    for (int mt = 0; mt < 2; mt++)
#pragma unroll
        for (int rr = 0; rr < 2; rr++) inv[mt][rr] = 1.f / l_run[mt][rr];

#pragma unroll
    for (int mt = 0; mt < 2; mt++)
#pragma unroll
        for (int nt = 0; nt < 4; nt++)
#pragma unroll
            for (int c = 0; c < 4; c++) {
                int rr = c >> 1;
                int t = t0 + warp_m * 32 + mt * 16 + rr * 8 + g;
                int d = warp_n * 32 + nt * 8 + 2 * tg + (c & 1);
                float v = oacc[mt][nt][c] * inv[mt][rr];
                __nv_bfloat16 hi = __float2bfloat16(v);
                size_t o = ((size_t)b * 1024 + t) * 512 + h * 64 + d;
                aTh[o] = hi;
                aTl[o] = __float2bfloat16(v - __bfloat162float(hi));
            }
}

// ---------------------------------------------------------------------------
extern "C" void kernel_launch(void* const* d_in, const int* in_sizes, int n_in,
                              void* d_out, int out_size)
{
    const float* x     = (const float*)d_in[0];
    const float* c     = (const float*)d_in[1];
    const float* gamma = (const float*)d_in[2];
    const float* beta  = (const float*)d_in[3];
    const float* w_qkv = (const float*)d_in[4];
    const float* b_qkv = (const float*)d_in[5];
    const float* w_c   = (const float*)d_in[6];
    const float* b_c   = (const float*)d_in[7];
    const float* w_p   = (const float*)d_in[8];
    const float* b_p   = (const float*)d_in[9];
    float* out = (float*)d_out;

    float *xn, *qkv, *ckv;
    __nv_bfloat16 *xnT_h, *xnT_l, *cT_h, *cT_l, *aT_h, *aT_l;
    __nv_bfloat16 *wq_h, *wq_l, *wc_h, *wc_l, *wp_h, *wp_l, *kT_h, *kT_l;
    __half* vT;
    cudaGetSymbolAddress((void**)&xn,    g_xn);
    cudaGetSymbolAddress((void**)&qkv,   g_qkv);
    cudaGetSymbolAddress((void**)&ckv,   g_ckv);
    cudaGetSymbolAddress((void**)&xnT_h, g_xnT_h);
    cudaGetSymbolAddress((void**)&xnT_l, g_xnT_l);
    cudaGetSymbolAddress((void**)&cT_h,  g_cT_h);
    cudaGetSymbolAddress((void**)&cT_l,  g_cT_l);
    cudaGetSymbolAddress((void**)&aT_h,  g_aT_h);
    cudaGetSymbolAddress((void**)&aT_l,  g_aT_l);
    cudaGetSymbolAddress((void**)&wq_h,  g_wq_h);
    cudaGetSymbolAddress((void**)&wq_l,  g_wq_l);
    cudaGetSymbolAddress((void**)&wc_h,  g_wc_h);
    cudaGetSymbolAddress((void**)&wc_l,  g_wc_l);
    cudaGetSymbolAddress((void**)&wp_h,  g_wp_h);
    cudaGetSymbolAddress((void**)&wp_l,  g_wp_l);
    cudaGetSymbolAddress((void**)&kT_h,  g_kT_h);
    cudaGetSymbolAddress((void**)&kT_l,  g_kT_l);
    cudaGetSymbolAddress((void**)&vT,    g_vT);

    static bool attr_done = false;
    if (!attr_done) {
        cudaFuncSetAttribute(gemm_bf,
                             cudaFuncAttributeMaxDynamicSharedMemorySize, 73728);
        cudaFuncSetAttribute(attn_kernel,
                             cudaFuncAttributeMaxDynamicSharedMemorySize, 126976);
        attr_done = true;
    }

    groupnorm_kernel<<<512, 256>>>(x, gamma, beta, xn);
    splitW_kernel<<<3072, 256>>>(w_qkv, wq_h, wq_l, 1536 * 512);
    splitW_kernel<<<3072, 256>>>(w_c, wc_h, wc_l, 1024 * 768);
    splitW_kernel<<<1024, 256>>>(w_p, wp_h, wp_l, 512 * 512);
    splitT_kernel<<<dim3(3, 24, 16), 256>>>(c, cT_h, cT_l, 768, 77);
    splitT_kernel<<<dim3(32, 16, 16), 256>>>(xn, xnT_h, xnT_l, 512, 1024);

    // ckv: [1024,77] = Wc[1024,768] @ cT
    gemm_bf<<<dim3(1, 8, 16), 256, 73728>>>(wc_h, wc_l, cT_h, cT_l, b_c, nullptr,
                                            ckv, 1024, 77, 768, 77L * 768, 1024L * 77);
    // qkv: [1536,1024] = Wq[1536,512] @ xnT
    gemm_bf<<<dim3(8, 12, 16), 256, 73728>>>(wq_h, wq_l, xnT_h, xnT_l, b_qkv, nullptr,
                                             qkv, 1536, 1024, 512, 1024L * 512, 1536L * 1024);

    // attention operand prep
    prep_self<<<dim3(8, 128), 256>>>(qkv, kT_h, kT_l, vT);
    prep_cond<<<128, 256>>>(ckv, kT_h, kT_l, vT);

    // attention (writes proj B operand aT h/l directly)
    attn_kernel<<<dim3(8, 8, 16), 256, 126976>>>(qkv, kT_h, kT_l, vT, aT_h, aT_l);

    // proj + residual -> d_out
    gemm_bf<<<dim3(8, 4, 16), 256, 73728>>>(wp_h, wp_l, aT_h, aT_l, b_p, x,
                                            out, 512, 1024, 512, 1024L * 512, 512L * 1024);
}

// round 6
// speedup vs baseline: 3.8858x; 1.3353x over previous
#include <cuda_runtime.h>
#include <cuda_fp16.h>
#include <cstdint>

// B=16, C=512, T=1024, L=77, S=1101(pad->1152), HEADS=8, D=64, GROUPS=32, CROSS=768

__device__ __half g_xnT [16 * 1024 * 512];     // [b][t][512]
__device__ __half g_qkvT[16 * 1024 * 1536];    // [b][t][1536] hi
__device__ __half g_qTl [16 * 1024 * 512];     // [b][t][512]  q lo
__device__ __half g_cT  [16 * 77 * 768];       // [b][l][768]
__device__ __half g_ckvT[16 * 77 * 1024];      // [b][l][1024]
__device__ __half g_kT  [128 * 1152 * 64];     // [bh][s][64]
__device__ __half g_vT  [128 * 64 * 1152];     // [bh][d][1152]
__device__ __half g_aT  [16 * 1024 * 512];     // [b][t][512]
__device__ __half g_wq_h[1536 * 512], g_wq_l[1536 * 512];
__device__ __half g_wc_h[1024 * 768], g_wc_l[1024 * 768];
__device__ __half g_wp_h[512 * 512],  g_wp_l[512 * 512];

#define DINL __device__ __forceinline__

DINL void mma_f16(float* c, const uint32_t* a, uint32_t b0, uint32_t b1) {
    asm volatile(
        "mma.sync.aligned.m16n8k16.row.col.f32.f16.f16.f32 "
        "{%0,%1,%2,%3},{%4,%5,%6,%7},{%8,%9},{%0,%1,%2,%3};"
        : "+f"(c[0]), "+f"(c[1]), "+f"(c[2]), "+f"(c[3])
        : "r"(a[0]), "r"(a[1]), "r"(a[2]), "r"(a[3]), "r"(b0), "r"(b1));
}
DINL uint32_t pack_h2(float a, float b) {
    __half2 h = __floats2half2_rn(a, b);
    return *(uint32_t*)&h;
}

// ---------------------------------------------------------------------------
// GroupNorm(32) fused with transpose + fp16: x[b][C][T] -> xnT[b][t][C]
// block = (b, group of 16 ch)
// ---------------------------------------------------------------------------
__global__ __launch_bounds__(256)
void groupnorm_kernel(const float* __restrict__ x,
                      const float* __restrict__ gamma,
                      const float* __restrict__ beta,
                      __half* __restrict__ xnT)
{
    int b = blockIdx.x >> 5;
    int g = blockIdx.x & 31;
    const float* xp = x + ((size_t)b * 512 + (size_t)g * 16) * 1024;

    float s = 0.f, s2 = 0.f;
    for (int i = threadIdx.x; i < 16384; i += 256) {
        float v = xp[i];
        s += v; s2 += v * v;
    }
#pragma unroll
    for (int o = 16; o > 0; o >>= 1) {
        s  += __shfl_xor_sync(0xffffffffu, s, o);
        s2 += __shfl_xor_sync(0xffffffffu, s2, o);
    }
    __shared__ float ss[8], ss2[8];
    __shared__ float smean, sinv;
    __shared__ float tile[256 * 17];
    int w = threadIdx.x >> 5;
    if ((threadIdx.x & 31) == 0) { ss[w] = s; ss2[w] = s2; }
    __syncthreads();
    if (threadIdx.x == 0) {
        float S = 0.f, S2 = 0.f;
#pragma unroll
        for (int i = 0; i < 8; i++) { S += ss[i]; S2 += ss2[i]; }
        float mean = S * (1.f / 16384.f);
        float var  = S2 * (1.f / 16384.f) - mean * mean;
        smean = mean;
        sinv  = rsqrtf(var + 1e-5f);
    }
    __syncthreads();
    float mean = smean, inv = sinv;

    for (int seg = 0; seg < 4; seg++) {
#pragma unroll
        for (int j = 0; j < 16; j++) {
            int idx = threadIdx.x + j * 256;
            int ch = idx >> 8, tt = idx & 255;
            float v = xp[ch * 1024 + seg * 256 + tt];
            tile[tt * 17 + ch] = (v - mean) * inv * gamma[g * 16 + ch] + beta[g * 16 + ch];
        }
        __syncthreads();
        {
            int t = seg * 256 + threadIdx.x;
            uint32_t wv[8];
#pragma unroll
            for (int c = 0; c < 8; c++)
                wv[c] = pack_h2(tile[threadIdx.x * 17 + 2 * c], tile[threadIdx.x * 17 + 2 * c + 1]);
            __half* dst = xnT + ((size_t)b * 1024 + t) * 512 + g * 16;
            *(uint4*)dst = *(uint4*)&wv[0];
            *(uint4*)(dst + 8) = *(uint4*)&wv[4];
        }
        __syncthreads();
    }
}

// ---------------------------------------------------------------------------
// weights: fp32 -> fp16 hi/lo of (32*w)
// ---------------------------------------------------------------------------
__global__ __launch_bounds__(256)
void splitW_kernel(const float* __restrict__ w, __half* __restrict__ h,
                   __half* __restrict__ l, int n)
{
    int i = blockIdx.x * 256 + threadIdx.x;
    if (i < n) {
        float x = w[i] * 32.f;
        __half hi = __float2half_rn(x);
        h[i] = hi;
        l[i] = __float2half_rn(x - __half2float(hi));
    }
}

// ---------------------------------------------------------------------------
// c [b][768][77] fp32 -> cT [b][77][768] fp16
// ---------------------------------------------------------------------------
__global__ __launch_bounds__(256)
void prep_c_kernel(const float* __restrict__ c, __half* __restrict__ cT)
{
    __shared__ float tile[32][33];
    int t0 = blockIdx.x * 32, cb = blockIdx.y * 32, b = blockIdx.z;
    const float* ip = c + (size_t)b * 768 * 77;
    int tx = threadIdx.x & 31, ty = threadIdx.x >> 5;
#pragma unroll
    for (int i = 0; i < 4; i++) {
        int cr = ty + i * 8;
        tile[cr][tx] = (t0 + tx < 77) ? ip[(size_t)(cb + cr) * 77 + t0 + tx] : 0.f;
    }
    __syncthreads();
#pragma unroll
    for (int i = 0; i < 4; i++) {
        int tr = ty + i * 8;
        if (t0 + tr < 77)
            cT[(size_t)b * 77 * 768 + (size_t)(t0 + tr) * 768 + cb + tx] =
                __float2half_rn(tile[tx][tr]);
    }
}

// ---------------------------------------------------------------------------
// gemm_AT: out[b][m=t][n=ch] = (1/32)*sum_k A[b][t][k]*(Wh+Wl)[ch][k] + bias
// A single fp16 k-major; W fp16 hi/lo (pre-scaled x32). 2-pass mma.
// Block 128(t) x 128(ch), BK=64, 8 warps (2m x 4n).
// oh fp16 [t][ldo]; ol (optional, n<loN) gets fp16-lo of the value (for Q).
// ---------------------------------------------------------------------------
__global__ __launch_bounds__(256)
void gemm_AT(const __half* __restrict__ A,
             const __half* __restrict__ Wh, const __half* __restrict__ Wl,
             const float* __restrict__ bias,
             __half* __restrict__ oh, __half* __restrict__ ol,
             int Mrows, int K, long aStride, int ldo, long oStride,
             int loN, long olStride)
{
    extern __shared__ uint32_t sm[];
    const int OA = 0, OBH = 4608, OBL = 9216;

    int b = blockIdx.z;
    A  += (size_t)b * aStride;
    oh += (size_t)b * oStride;
    __half* olp = ol ? ol + (size_t)b * olStride : nullptr;

    int tid = threadIdx.x, w = tid >> 5, lane = tid & 31;
    int g = lane >> 2, tg = lane & 3;
    int warp_m = w >> 2, warp_n = w & 3;
    int m0 = blockIdx.y * 128, n0 = blockIdx.x * 128;

    float acc[4][4][4];
#pragma unroll
    for (int i = 0; i < 4; i++)
#pragma unroll
        for (int j = 0; j < 4; j++)
#pragma unroll
            for (int c = 0; c < 4; c++) acc[i][j][c] = 0.f;

    for (int k0 = 0; k0 < K; k0 += 64) {
#pragma unroll
        for (int it = 0; it < 4; it++) {
            int i = tid + it * 256;
            int row = i >> 3, seg = i & 7;
            uint4 av = make_uint4(0, 0, 0, 0);
            if (m0 + row < Mrows)
                av = *(const uint4*)(A + (size_t)(m0 + row) * K + k0 + seg * 8);
            *(uint4*)(sm + OA + row * 36 + seg * 4) = av;
            *(uint4*)(sm + OBH + row * 36 + seg * 4) =
                *(const uint4*)(Wh + (size_t)(n0 + row) * K + k0 + seg * 8);
            *(uint4*)(sm + OBL + row * 36 + seg * 4) =
                *(const uint4*)(Wl + (size_t)(n0 + row) * K + k0 + seg * 8);
        }
        __syncthreads();
#pragma unroll
        for (int ks = 0; ks < 4; ks++) {
            int kb = ks * 8;
            uint32_t af[4][4];
#pragma unroll
            for (int mt = 0; mt < 4; mt++) {
                int rb = warp_m * 64 + mt * 16;
                af[mt][0] = sm[OA + (rb+g  )*36 + kb + tg];
                af[mt][1] = sm[OA + (rb+g+8)*36 + kb + tg];
                af[mt][2] = sm[OA + (rb+g  )*36 + kb + tg + 4];
                af[mt][3] = sm[OA + (rb+g+8)*36 + kb + tg + 4];
            }
#pragma unroll
            for (int nt = 0; nt < 4; nt++) {
                int cb = warp_n * 32 + nt * 8 + g;
                uint32_t bh0 = sm[OBH + cb*36 + kb + tg];
                uint32_t bh1 = sm[OBH + cb*36 + kb + tg + 4];
                uint32_t bl0 = sm[OBL + cb*36 + kb + tg];
                uint32_t bl1 = sm[OBL + cb*36 + kb + tg + 4];
#pragma unroll
                for (int mt = 0; mt < 4; mt++) {
                    mma_f16(acc[mt][nt], af[mt], bl0, bl1);
                    mma_f16(acc[mt][nt], af[mt], bh0, bh1);
                }
            }
        }
        __syncthreads();
    }

#pragma unroll
    for (int mt = 0; mt < 4; mt++) {
#pragma unroll
        for (int rr = 0; rr < 2; rr++) {
            int m = m0 + warp_m * 64 + mt * 16 + rr * 8 + g;
            if (m < Mrows) {
#pragma unroll
                for (int nt = 0; nt < 4; nt++) {
                    int n = n0 + warp_n * 32 + nt * 8 + 2 * tg;
                    float v0 = acc[mt][nt][rr * 2]     * (1.f / 32.f) + bias[n];
                    float v1 = acc[mt][nt][rr * 2 + 1] * (1.f / 32.f) + bias[n + 1];
                    __half h0 = __float2half_rn(v0), h1 = __float2half_rn(v1);
                    __half2 hh; hh.x = h0; hh.y = h1;
                    *(uint32_t*)(oh + (size_t)m * ldo + n) = *(uint32_t*)&hh;
                    if (olp && n < loN) {
                        __half2 ll;
                        ll.x = __float2half_rn(v0 - __half2float(h0));
                        ll.y = __float2half_rn(v1 - __half2float(h1));
                        *(uint32_t*)(olp + (size_t)m * loN + n) = *(uint32_t*)&ll;
                    }
                }
            }
        }
    }
}

// ---------------------------------------------------------------------------
// prep: pack K self tiles  kT[bh][s][64] <- qkvT[b][s][512+h*64+..]
// ---------------------------------------------------------------------------
__global__ __launch_bounds__(256)
void prep_kT(const __half* __restrict__ qkvT, __half* __restrict__ kT)
{
    int s0 = blockIdx.x * 128, bh = blockIdx.y;
    int b = bh >> 3, h = bh & 7;
    const __half* src = qkvT + ((size_t)b * 1024 + s0) * 1536 + 512 + h * 64;
    __half* dst = kT + ((size_t)bh * 1152 + s0) * 64;
    int tid = threadIdx.x;
#pragma unroll
    for (int it = 0; it < 4; it++) {
        int i = tid + it * 256;
        int row = i >> 3, seg = i & 7;
        *(uint4*)(dst + row * 64 + seg * 8) =
            *(const uint4*)(src + (size_t)row * 1536 + seg * 8);
    }
}

// transpose V self: vT[bh][d][s] <- qkvT[b][s][1024+h*64+d]
__global__ __launch_bounds__(256)
void prep_vT(const __half* __restrict__ qkvT, __half* __restrict__ vT)
{
    __shared__ __half tl[128 * 72];
    int s0 = blockIdx.x * 128, bh = blockIdx.y;
    int b = bh >> 3, h = bh & 7;
    const __half* src = qkvT + ((size_t)b * 1024 + s0) * 1536 + 1024 + h * 64;
    int tid = threadIdx.x;
#pragma unroll
    for (int it = 0; it < 4; it++) {
        int i = tid + it * 256;
        int row = i >> 3, seg = i & 7;
        *(uint4*)(tl + row * 72 + seg * 8) =
            *(const uint4*)(src + (size_t)row * 1536 + seg * 8);
    }
    __syncthreads();
    __half* dst = vT + (size_t)bh * 64 * 1152 + s0;
#pragma unroll
    for (int it = 0; it < 16; it++) {
        int j = tid + it * 256;
        int d = j >> 6, tp = j & 63;
        __half2 v;
        v.x = tl[(2 * tp) * 72 + d];
        v.y = tl[(2 * tp + 1) * 72 + d];
        *(uint32_t*)(dst + (size_t)d * 1152 + 2 * tp) = *(uint32_t*)&v;
    }
}

// cond region s in [1024,1152): from ckvT, zero pad past 77
__global__ __launch_bounds__(256)
void prep_cond(const __half* __restrict__ ckvT, __half* __restrict__ kT,
               __half* __restrict__ vT)
{
    int bh = blockIdx.x, b = bh >> 3, h = bh & 7;
    int tid = threadIdx.x;
    __half z = __float2half(0.f);
#pragma unroll
    for (int it = 0; it < 32; it++) {
        int i = tid + it * 256;
        int sl = i >> 6, d = i & 63;
        __half v = z;
        if (sl < 77) v = ckvT[((size_t)b * 77 + sl) * 1024 + h * 64 + d];
        kT[((size_t)bh * 1152 + 1024 + sl) * 64 + d] = v;
    }
#pragma unroll
    for (int it = 0; it < 32; it++) {
        int i = tid + it * 256;
        int d = i >> 7, sl = i & 127;
        __half v = z;
        if (sl < 77) v = ckvT[((size_t)b * 77 + sl) * 1024 + 512 + h * 64 + d];
        vT[(size_t)bh * 64 * 1152 + (size_t)d * 1152 + 1024 + sl] = v;
    }
}

// ---------------------------------------------------------------------------
// Flash attention: QK^T = (Qh+Ql)·K fp16 2-pass; P·V fp16 1-pass.
// Block = 128 q for (b,h); 256 thr = 8 warps (4m x 2n).
// Writes aT [b][t][512] single fp16 (proj B operand).
// ---------------------------------------------------------------------------
__global__ __launch_bounds__(256)
void attn_kernel(const __half* __restrict__ qkvT, const __half* __restrict__ qTl,
                 const __half* __restrict__ kT, const __half* __restrict__ vT,
                 __half* __restrict__ aT)
{
    extern __shared__ uint32_t smw[];
    const int OQH = 0, OQL = 4608, OKS = 9216, OV = 13824, OP = 18176;
    float* red = (float*)(smw + 26880);   // [2][128]

    int t0 = blockIdx.x * 128;
    int h  = blockIdx.y;
    int b  = blockIdx.z;
    int bh = b * 8 + h;
    int tid = threadIdx.x;
    int w = tid >> 5, lane = tid & 31;
    int g = lane >> 2, tg = lane & 3;
    int warp_m = w >> 1, warp_n = w & 1;

    // stage Q hi/lo [t][64]
    {
        const __half* qh = qkvT + ((size_t)b * 1024 + t0) * 1536 + h * 64;
        const __half* ql = qTl + ((size_t)b * 1024 + t0) * 512 + h * 64;
#pragma unroll
        for (int it = 0; it < 4; it++) {
            int i = tid + it * 256;
            int row = i >> 3, seg = i & 7;
            *(uint4*)(smw + OQH + row * 36 + seg * 4) =
                *(const uint4*)(qh + (size_t)row * 1536 + seg * 8);
            *(uint4*)(smw + OQL + row * 36 + seg * 4) =
                *(const uint4*)(ql + (size_t)row * 512 + seg * 8);
        }
    }

    float oacc[2][4][4];
#pragma unroll
    for (int mt = 0; mt < 2; mt++)
#pragma unroll
        for (int nt = 0; nt < 4; nt++)
#pragma unroll
            for (int c = 0; c < 4; c++) oacc[mt][nt][c] = 0.f;
    float m_run[2][2] = {{-1e30f,-1e30f},{-1e30f,-1e30f}};
    float l_run[2][2] = {{0.f,0.f},{0.f,0.f}};

    __syncthreads();

    for (int kt = 0; kt < 9; kt++) {
        // stage K [s][64], V [d][128]
        {
            const __half* kp = kT + ((size_t)bh * 1152 + kt * 128) * 64;
#pragma unroll
            for (int it = 0; it < 4; it++) {
                int i = tid + it * 256;
                int s = i >> 3, seg = i & 7;
                *(uint4*)(smw + OKS + s * 36 + seg * 4) = *(const uint4*)(kp + s * 64 + seg * 8);
            }
            const __half* vp = vT + (size_t)bh * 64 * 1152 + kt * 128;
#pragma unroll
            for (int it = 0; it < 4; it++) {
                int i = tid + it * 256;
                int d = i >> 4, seg = i & 15;
                *(uint4*)(smw + OV + d * 68 + seg * 4) = *(const uint4*)(vp + (size_t)d * 1152 + seg * 8);
            }
        }
        __syncthreads();

        // S = Q K^T (2-pass fp16), warp tile 32q x 64s
        float sacc[2][8][4];
#pragma unroll
        for (int mt = 0; mt < 2; mt++)
#pragma unroll
            for (int nt = 0; nt < 8; nt++)
#pragma unroll
                for (int c = 0; c < 4; c++) sacc[mt][nt][c] = 0.f;

#pragma unroll
        for (int ks = 0; ks < 4; ks++) {
            int kb = ks * 8;
            uint32_t ah[2][4], al[2][4];
#pragma unroll
            for (int mt = 0; mt < 2; mt++) {
                int rb = warp_m * 32 + mt * 16;
                ah[mt][0] = smw[OQH + (rb+g  )*36 + kb + tg];
                ah[mt][1] = smw[OQH + (rb+g+8)*36 + kb + tg];
                ah[mt][2] = smw[OQH + (rb+g  )*36 + kb + tg + 4];
                ah[mt][3] = smw[OQH + (rb+g+8)*36 + kb + tg + 4];
                al[mt][0] = smw[OQL + (rb+g  )*36 + kb + tg];
                al[mt][1] = smw[OQL + (rb+g+8)*36 + kb + tg];
                al[mt][2] = smw[OQL + (rb+g  )*36 + kb + tg + 4];
                al[mt][3] = smw[OQL + (rb+g+8)*36 + kb + tg + 4];
            }
#pragma unroll
            for (int nt = 0; nt < 8; nt++) {
                int cb = warp_n * 64 + nt * 8 + g;
                uint32_t b0 = smw[OKS + cb*36 + kb + tg];
                uint32_t b1 = smw[OKS + cb*36 + kb + tg + 4];
#pragma unroll
                for (int mt = 0; mt < 2; mt++) {
                    mma_f16(sacc[mt][nt], al[mt], b0, b1);
                    mma_f16(sacc[mt][nt], ah[mt], b0, b1);
                }
            }
        }

        // scale + mask
#pragma unroll
        for (int mt = 0; mt < 2; mt++)
#pragma unroll
            for (int nt = 0; nt < 8; nt++)
#pragma unroll
                for (int c = 0; c < 4; c++) {
                    float v = sacc[mt][nt][c] * 0.125f;
                    if (kt == 8) {
                        int col = warp_n * 64 + nt * 8 + 2 * tg + (c & 1);
                        if (col >= 77) v = -1e30f;
                    }
                    sacc[mt][nt][c] = v;
                }

        // row max
        float mx[2][2];
#pragma unroll
        for (int mt = 0; mt < 2; mt++)
#pragma unroll
            for (int rr = 0; rr < 2; rr++) {
                float m = -1e30f;
#pragma unroll
                for (int nt = 0; nt < 8; nt++) {
                    m = fmaxf(m, sacc[mt][nt][rr*2]);
                    m = fmaxf(m, sacc[mt][nt][rr*2+1]);
                }
                m = fmaxf(m, __shfl_xor_sync(0xffffffffu, m, 1));
                m = fmaxf(m, __shfl_xor_sync(0xffffffffu, m, 2));
                mx[mt][rr] = m;
            }
        if (tg == 0) {
#pragma unroll
            for (int mt = 0; mt < 2; mt++)
#pragma unroll
                for (int rr = 0; rr < 2; rr++) {
                    int row = warp_m * 32 + mt * 16 + rr * 8 + g;
                    red[warp_n * 128 + row] = mx[mt][rr];
                }
        }
        __syncthreads();
        float corr[2][2], nm[2][2];
#pragma unroll
        for (int mt = 0; mt < 2; mt++)
#pragma unroll
            for (int rr = 0; rr < 2; rr++) {
                int row = warp_m * 32 + mt * 16 + rr * 8 + g;
                float tot = fmaxf(mx[mt][rr], red[(1 - warp_n) * 128 + row]);
                float newm = fmaxf(m_run[mt][rr], tot);
                corr[mt][rr] = __expf(m_run[mt][rr] - newm);
                nm[mt][rr] = newm;
                m_run[mt][rr] = newm;
            }
        __syncthreads();

        // exp, write P fp16, row sums
        float rs[2][2] = {{0.f,0.f},{0.f,0.f}};
#pragma unroll
        for (int mt = 0; mt < 2; mt++)
#pragma unroll
            for (int rr = 0; rr < 2; rr++) {
                int row = warp_m * 32 + mt * 16 + rr * 8 + g;
#pragma unroll
                for (int nt = 0; nt < 8; nt++) {
                    float p0 = __expf(sacc[mt][nt][rr*2]   - nm[mt][rr]);
                    float p1 = __expf(sacc[mt][nt][rr*2+1] - nm[mt][rr]);
                    rs[mt][rr] += p0 + p1;
                    smw[OP + row * 68 + warp_n * 32 + nt * 4 + tg] = pack_h2(p0, p1);
                }
            }
#pragma unroll
        for (int mt = 0; mt < 2; mt++)
#pragma unroll
            for (int rr = 0; rr < 2; rr++) {
                float s = rs[mt][rr];
                s += __shfl_xor_sync(0xffffffffu, s, 1);
                s += __shfl_xor_sync(0xffffffffu, s, 2);
                rs[mt][rr] = s;
            }
        if (tg == 0) {
#pragma unroll
            for (int mt = 0; mt < 2; mt++)
#pragma unroll
                for (int rr = 0; rr < 2; rr++) {
                    int row = warp_m * 32 + mt * 16 + rr * 8 + g;
                    red[warp_n * 128 + row] = rs[mt][rr];
                }
        }
#pragma unroll
        for (int mt = 0; mt < 2; mt++)
#pragma unroll
            for (int nt = 0; nt < 4; nt++) {
                oacc[mt][nt][0] *= corr[mt][0];
                oacc[mt][nt][1] *= corr[mt][0];
                oacc[mt][nt][2] *= corr[mt][1];
                oacc[mt][nt][3] *= corr[mt][1];
            }
        __syncthreads();
#pragma unroll
        for (int mt = 0; mt < 2; mt++)
#pragma unroll
            for (int rr = 0; rr < 2; rr++) {
                int row = warp_m * 32 + mt * 16 + rr * 8 + g;
                float tot = rs[mt][rr] + red[(1 - warp_n) * 128 + row];
                l_run[mt][rr] = l_run[mt][rr] * corr[mt][rr] + tot;
            }

        // O += P·V, warp tile 32q x 32d
#pragma unroll
        for (int ks = 0; ks < 8; ks++) {
            int kb = ks * 8;
            uint32_t pa[2][4];
#pragma unroll
            for (int mt = 0; mt < 2; mt++) {
                int rb = warp_m * 32 + mt * 16;
                pa[mt][0] = smw[OP + (rb+g  )*68 + kb + tg];
                pa[mt][1] = smw[OP + (rb+g+8)*68 + kb + tg];
                pa[mt][2] = smw[OP + (rb+g  )*68 + kb + tg + 4];
                pa[mt][3] = smw[OP + (rb+g+8)*68 + kb + tg + 4];
            }
#pragma unroll
            for (int nt = 0; nt < 4; nt++) {
                int db = warp_n * 32 + nt * 8 + g;
                uint32_t b0 = smw[OV + db*68 + kb + tg];
                uint32_t b1 = smw[OV + db*68 + kb + tg + 4];
#pragma unroll
                for (int mt = 0; mt < 2; mt++)
                    mma_f16(oacc[mt][nt], pa[mt], b0, b1);
            }
        }
        __syncthreads();
    }

    // normalize + write aT fp16 [t][512]
    float inv[2][2];
#pragma unroll
    for (int mt = 0; mt < 2; mt++)
#pragma unroll
        for (int rr = 0; rr < 2; rr++) inv[mt][rr] = 1.f / l_run[mt][rr];

#pragma unroll
    for (int mt = 0; mt < 2; mt++)
#pragma unroll
        for (int nt = 0; nt < 4; nt++)
#pragma unroll
            for (int rr = 0; rr < 2; rr++) {
                int t = t0 + warp_m * 32 + mt * 16 + rr * 8 + g;
                int d = warp_n * 32 + nt * 8 + 2 * tg;
                float v0 = oacc[mt][nt][rr*2]     * inv[mt][rr];
                float v1 = oacc[mt][nt][rr*2 + 1] * inv[mt][rr];
                *(uint32_t*)(aT + ((size_t)b * 1024 + t) * 512 + h * 64 + d) = pack_h2(v0, v1);
            }
}

// ---------------------------------------------------------------------------
// proj: out[b][m=ch][n=t] fp32 = (1/32)*sum_k (Wh+Wl)[ch][k]*aT[b][t][k]
//       + bias[ch] + x[b][ch][t]
// ---------------------------------------------------------------------------
__global__ __launch_bounds__(256)
void gemm_WA(const __half* __restrict__ Wh, const __half* __restrict__ Wl,
             const __half* __restrict__ Bm, const float* __restrict__ bias,
             const float* __restrict__ res, float* __restrict__ out)
{
    extern __shared__ uint32_t sm[];
    const int OAH = 0, OAL = 4608, OB = 9216;
    const int K = 512, N = 1024;

    int b = blockIdx.z;
    const __half* Bp = Bm + (size_t)b * 1024 * 512;
    float* op = out + (size_t)b * 512 * 1024;
    const float* rp = res + (size_t)b * 512 * 1024;

    int tid = threadIdx.x, w = tid >> 5, lane = tid & 31;
    int g = lane >> 2, tg = lane & 3;
    int warp_m = w >> 2, warp_n = w & 3;
    int m0 = blockIdx.y * 128, n0 = blockIdx.x * 128;

    float acc[4][4][4];
#pragma unroll
    for (int i = 0; i < 4; i++)
#pragma unroll
        for (int j = 0; j < 4; j++)
#pragma unroll
            for (int c = 0; c < 4; c++) acc[i][j][c] = 0.f;

    for (int k0 = 0; k0 < K; k0 += 64) {
#pragma unroll
        for (int it = 0; it < 4; it++) {
            int i = tid + it * 256;
            int row = i >> 3, seg = i & 7;
            *(uint4*)(sm + OAH + row * 36 + seg * 4) =
                *(const uint4*)(Wh + (size_t)(m0 + row) * K + k0 + seg * 8);
            *(uint4*)(sm + OAL + row * 36 + seg * 4) =
                *(const uint4*)(Wl + (size_t)(m0 + row) * K + k0 + seg * 8);
            *(uint4*)(sm + OB + row * 36 + seg * 4) =
                *(const uint4*)(Bp + (size_t)(n0 + row) * K + k0 + seg * 8);
        }
        __syncthreads();
#pragma unroll
        for (int ks = 0; ks < 4; ks++) {
            int kb = ks * 8;
            uint32_t ah[4][4], al[4][4];
#pragma unroll
            for (int mt = 0; mt < 4; mt++) {
                int rb = warp_m * 64 + mt * 16;
                ah[mt][0] = sm[OAH + (rb+g  )*36 + kb + tg];
                ah[mt][1] = sm[OAH + (rb+g+8)*36 + kb + tg];
                ah[mt][2] = sm[OAH + (rb+g  )*36 + kb + tg + 4];
                ah[mt][3] = sm[OAH + (rb+g+8)*36 + kb + tg + 4];
                al[mt][0] = sm[OAL + (rb+g  )*36 + kb + tg];
                al[mt][1] = sm[OAL + (rb+g+8)*36 + kb + tg];
                al[mt][2] = sm[OAL + (rb+g  )*36 + kb + tg + 4];
                al[mt][3] = sm[OAL + (rb+g+8)*36 + kb + tg + 4];
            }
#pragma unroll
            for (int nt = 0; nt < 4; nt++) {
                int cb = warp_n * 32 + nt * 8 + g;
                uint32_t b0 = sm[OB + cb*36 + kb + tg];
                uint32_t b1 = sm[OB + cb*36 + kb + tg + 4];
#pragma unroll
                for (int mt = 0; mt < 4; mt++) {
                    mma_f16(acc[mt][nt], al[mt], b0, b1);
                    mma_f16(acc[mt][nt], ah[mt], b0, b1);
                }
            }
        }
        __syncthreads();
    }

#pragma unroll
    for (int mt = 0; mt < 4; mt++) {
#pragma unroll
        for (int rr = 0; rr < 2; rr++) {
            int m = m0 + warp_m * 64 + mt * 16 + rr * 8 + g;
            float bi = bias[m];
#pragma unroll
            for (int nt = 0; nt < 4; nt++) {
#pragma unroll
                for (int ci = 0; ci < 2; ci++) {
                    int n = n0 + warp_n * 32 + nt * 8 + 2 * tg + ci;
                    float v = acc[mt][nt][rr * 2 + ci] * (1.f / 32.f) + bi
                            + rp[(size_t)m * N + n];
                    op[(size_t)m * N + n] = v;
                }
            }
        }
    }
}

// ---------------------------------------------------------------------------
extern "C" void kernel_launch(void* const* d_in, const int* in_sizes, int n_in,
                              void* d_out, int out_size)
{
    const float* x     = (const float*)d_in[0];
    const float* c     = (const float*)d_in[1];
    const float* gamma = (const float*)d_in[2];
    const float* beta  = (const float*)d_in[3];
    const float* w_qkv = (const float*)d_in[4];
    const float* b_qkv = (const float*)d_in[5];
    const float* w_c   = (const float*)d_in[6];
    const float* b_c   = (const float*)d_in[7];
    const float* w_p   = (const float*)d_in[8];
    const float* b_p   = (const float*)d_in[9];
    float* out = (float*)d_out;

    __half *xnT, *qkvT, *qTl, *cT, *ckvT, *kT, *vT, *aT;
    __half *wq_h, *wq_l, *wc_h, *wc_l, *wp_h, *wp_l;
    cudaGetSymbolAddress((void**)&xnT,  g_xnT);
    cudaGetSymbolAddress((void**)&qkvT, g_qkvT);
    cudaGetSymbolAddress((void**)&qTl,  g_qTl);
    cudaGetSymbolAddress((void**)&cT,   g_cT);
    cudaGetSymbolAddress((void**)&ckvT, g_ckvT);
    cudaGetSymbolAddress((void**)&kT,   g_kT);
    cudaGetSymbolAddress((void**)&vT,   g_vT);
    cudaGetSymbolAddress((void**)&aT,   g_aT);
    cudaGetSymbolAddress((void**)&wq_h, g_wq_h);
    cudaGetSymbolAddress((void**)&wq_l, g_wq_l);
    cudaGetSymbolAddress((void**)&wc_h, g_wc_h);
    cudaGetSymbolAddress((void**)&wc_l, g_wc_l);
    cudaGetSymbolAddress((void**)&wp_h, g_wp_h);
    cudaGetSymbolAddress((void**)&wp_l, g_wp_l);

    static bool attr_done = false;
    if (!attr_done) {
        cudaFuncSetAttribute(gemm_AT, cudaFuncAttributeMaxDynamicSharedMemorySize, 55296);
        cudaFuncSetAttribute(gemm_WA, cudaFuncAttributeMaxDynamicSharedMemorySize, 55296);
        cudaFuncSetAttribute(attn_kernel, cudaFuncAttributeMaxDynamicSharedMemorySize, 108544);
        attr_done = true;
    }

    groupnorm_kernel<<<512, 256>>>(x, gamma, beta, xnT);
    splitW_kernel<<<3072, 256>>>(w_qkv, wq_h, wq_l, 1536 * 512);
    splitW_kernel<<<3072, 256>>>(w_c, wc_h, wc_l, 1024 * 768);
    splitW_kernel<<<1024, 256>>>(w_p, wp_h, wp_l, 512 * 512);
    prep_c_kernel<<<dim3(3, 24, 16), 256>>>(c, cT);

    // qkv: [t][1536] fp16 (+ q lo for ch<512)
    gemm_AT<<<dim3(12, 8, 16), 256, 55296>>>(xnT, wq_h, wq_l, b_qkv, qkvT, qTl,
                                             1024, 512, 1024L * 512, 1536,
                                             1024L * 1536, 512, 1024L * 512);
    // ckv: [l][1024] fp16
    gemm_AT<<<dim3(8, 1, 16), 256, 55296>>>(cT, wc_h, wc_l, b_c, ckvT, nullptr,
                                            77, 768, 77L * 768, 1024,
                                            77L * 1024, 0, 0);

    prep_kT<<<dim3(8, 128), 256>>>(qkvT, kT);
    prep_vT<<<dim3(8, 128), 256>>>(qkvT, vT);
    prep_cond<<<128, 256>>>(ckvT, kT, vT);

    attn_kernel<<<dim3(8, 8, 16), 256, 108544>>>(qkvT, qTl, kT, vT, aT);

    gemm_WA<<<dim3(8, 4, 16), 256, 55296>>>(wp_h, wp_l, aT, b_p, x, out);
}

// round 7
// speedup vs baseline: 5.6618x; 1.4570x over previous
#include <cuda_runtime.h>
#include <cuda_fp16.h>
#include <cstdint>

// B=16, C=512, T=1024, L=77, S=1101(pad->1152), HEADS=8, D=64, GROUPS=32, CROSS=768

__device__ __half g_xnT [16 * 1024 * 512];     // [b][t][512]
__device__ __half g_qkvT[16 * 1024 * 1536];    // [b][t][1536]
__device__ __half g_cT  [16 * 77 * 768];       // [b][l][768]
__device__ __half g_ckvT[16 * 77 * 1024];      // [b][l][1024]
__device__ __half g_vT  [128 * 64 * 1152];     // [bh][d][s]
__device__ __half g_aT  [16 * 1024 * 512];     // [b][t][512]
__device__ __half g_wq[1536 * 512];
__device__ __half g_wc[1024 * 768];
__device__ __half g_wp[512 * 512];

#define DINL __device__ __forceinline__

DINL void mma_f16(float* c, const uint32_t* a, uint32_t b0, uint32_t b1) {
    asm volatile(
        "mma.sync.aligned.m16n8k16.row.col.f32.f16.f16.f32 "
        "{%0,%1,%2,%3},{%4,%5,%6,%7},{%8,%9},{%0,%1,%2,%3};"
        : "+f"(c[0]), "+f"(c[1]), "+f"(c[2]), "+f"(c[3])
        : "r"(a[0]), "r"(a[1]), "r"(a[2]), "r"(a[3]), "r"(b0), "r"(b1));
}
DINL uint32_t pack_h2(float a, float b) {
    __half2 h = __floats2half2_rn(a, b);
    return *(uint32_t*)&h;
}

// ---------------------------------------------------------------------------
// GroupNorm(32) fused transpose + fp16: x[b][C][T] -> xnT[b][t][C]
// ---------------------------------------------------------------------------
__global__ __launch_bounds__(256)
void groupnorm_kernel(const float* __restrict__ x,
                      const float* __restrict__ gamma,
                      const float* __restrict__ beta,
                      __half* __restrict__ xnT)
{
    int b = blockIdx.x >> 5;
    int g = blockIdx.x & 31;
    const float* xp = x + ((size_t)b * 512 + (size_t)g * 16) * 1024;

    float s = 0.f, s2 = 0.f;
    for (int i = threadIdx.x; i < 16384; i += 256) {
        float v = xp[i];
        s += v; s2 += v * v;
    }
#pragma unroll
    for (int o = 16; o > 0; o >>= 1) {
        s  += __shfl_xor_sync(0xffffffffu, s, o);
        s2 += __shfl_xor_sync(0xffffffffu, s2, o);
    }
    __shared__ float ss[8], ss2[8];
    __shared__ float smean, sinv;
    __shared__ float tile[256 * 17];
    int w = threadIdx.x >> 5;
    if ((threadIdx.x & 31) == 0) { ss[w] = s; ss2[w] = s2; }
    __syncthreads();
    if (threadIdx.x == 0) {
        float S = 0.f, S2 = 0.f;
#pragma unroll
        for (int i = 0; i < 8; i++) { S += ss[i]; S2 += ss2[i]; }
        float mean = S * (1.f / 16384.f);
        float var  = S2 * (1.f / 16384.f) - mean * mean;
        smean = mean;
        sinv  = rsqrtf(var + 1e-5f);
    }
    __syncthreads();
    float mean = smean, inv = sinv;

    for (int seg = 0; seg < 4; seg++) {
#pragma unroll
        for (int j = 0; j < 16; j++) {
            int idx = threadIdx.x + j * 256;
            int ch = idx >> 8, tt = idx & 255;
            float v = xp[ch * 1024 + seg * 256 + tt];
            tile[tt * 17 + ch] = (v - mean) * inv * gamma[g * 16 + ch] + beta[g * 16 + ch];
        }
        __syncthreads();
        {
            int t = seg * 256 + threadIdx.x;
            uint32_t wv[8];
#pragma unroll
            for (int c = 0; c < 8; c++)
                wv[c] = pack_h2(tile[threadIdx.x * 17 + 2 * c], tile[threadIdx.x * 17 + 2 * c + 1]);
            __half* dst = xnT + ((size_t)b * 1024 + t) * 512 + g * 16;
            *(uint4*)dst = *(uint4*)&wv[0];
            *(uint4*)(dst + 8) = *(uint4*)&wv[4];
        }
        __syncthreads();
    }
}

// ---------------------------------------------------------------------------
// weights fp32 -> fp16
// ---------------------------------------------------------------------------
__global__ __launch_bounds__(256)
void convW_kernel(const float* __restrict__ w, __half* __restrict__ h, int n)
{
    int i = blockIdx.x * 256 + threadIdx.x;
    if (i < n) h[i] = __float2half_rn(w[i]);
}

// ---------------------------------------------------------------------------
// c [b][768][77] fp32 -> cT [b][77][768] fp16
// ---------------------------------------------------------------------------
__global__ __launch_bounds__(256)
void prep_c_kernel(const float* __restrict__ c, __half* __restrict__ cT)
{
    __shared__ float tile[32][33];
    int t0 = blockIdx.x * 32, cb = blockIdx.y * 32, b = blockIdx.z;
    const float* ip = c + (size_t)b * 768 * 77;
    int tx = threadIdx.x & 31, ty = threadIdx.x >> 5;
#pragma unroll
    for (int i = 0; i < 4; i++) {
        int cr = ty + i * 8;
        tile[cr][tx] = (t0 + tx < 77) ? ip[(size_t)(cb + cr) * 77 + t0 + tx] : 0.f;
    }
    __syncthreads();
#pragma unroll
    for (int i = 0; i < 4; i++) {
        int tr = ty + i * 8;
        if (t0 + tr < 77)
            cT[(size_t)b * 77 * 768 + (size_t)(t0 + tr) * 768 + cb + tx] =
                __float2half_rn(tile[tx][tr]);
    }
}

// ---------------------------------------------------------------------------
// gemm_AT: oh[b][m=t][n=ch] = sum_k A[b][t][k]*W[ch][k] + bias, fp16 out.
// Block 128(t) x 128(ch), BK=64, 8 warps (2m x 4n), single-pass fp16.
// ---------------------------------------------------------------------------
__global__ __launch_bounds__(256)
void gemm_AT(const __half* __restrict__ A, const __half* __restrict__ W,
             const float* __restrict__ bias, __half* __restrict__ oh,
             int Mrows, int K, long aStride, int ldo, long oStride)
{
    extern __shared__ uint32_t sm[];
    const int OA = 0, OB = 4608;

    int b = blockIdx.z;
    A  += (size_t)b * aStride;
    oh += (size_t)b * oStride;

    int tid = threadIdx.x, w = tid >> 5, lane = tid & 31;
    int g = lane >> 2, tg = lane & 3;
    int warp_m = w >> 2, warp_n = w & 3;
    int m0 = blockIdx.y * 128, n0 = blockIdx.x * 128;

    float acc[4][4][4];
#pragma unroll
    for (int i = 0; i < 4; i++)
#pragma unroll
        for (int j = 0; j < 4; j++)
#pragma unroll
            for (int c = 0; c < 4; c++) acc[i][j][c] = 0.f;

    for (int k0 = 0; k0 < K; k0 += 64) {
#pragma unroll
        for (int it = 0; it < 4; it++) {
            int i = tid + it * 256;
            int row = i >> 3, seg = i & 7;
            uint4 av = make_uint4(0, 0, 0, 0);
            if (m0 + row < Mrows)
                av = *(const uint4*)(A + (size_t)(m0 + row) * K + k0 + seg * 8);
            *(uint4*)(sm + OA + row * 36 + seg * 4) = av;
            *(uint4*)(sm + OB + row * 36 + seg * 4) =
                *(const uint4*)(W + (size_t)(n0 + row) * K + k0 + seg * 8);
        }
        __syncthreads();
#pragma unroll
        for (int ks = 0; ks < 4; ks++) {
            int kb = ks * 8;
            uint32_t af[4][4];
#pragma unroll
            for (int mt = 0; mt < 4; mt++) {
                int rb = warp_m * 64 + mt * 16;
                af[mt][0] = sm[OA + (rb+g  )*36 + kb + tg];
                af[mt][1] = sm[OA + (rb+g+8)*36 + kb + tg];
                af[mt][2] = sm[OA + (rb+g  )*36 + kb + tg + 4];
                af[mt][3] = sm[OA + (rb+g+8)*36 + kb + tg + 4];
            }
#pragma unroll
            for (int nt = 0; nt < 4; nt++) {
                int cb = warp_n * 32 + nt * 8 + g;
                uint32_t b0 = sm[OB + cb*36 + kb + tg];
                uint32_t b1 = sm[OB + cb*36 + kb + tg + 4];
#pragma unroll
                for (int mt = 0; mt < 4; mt++)
                    mma_f16(acc[mt][nt], af[mt], b0, b1);
            }
        }
        __syncthreads();
    }

#pragma unroll
    for (int mt = 0; mt < 4; mt++) {
#pragma unroll
        for (int rr = 0; rr < 2; rr++) {
            int m = m0 + warp_m * 64 + mt * 16 + rr * 8 + g;
            if (m < Mrows) {
#pragma unroll
                for (int nt = 0; nt < 4; nt++) {
                    int n = n0 + warp_n * 32 + nt * 8 + 2 * tg;
                    float v0 = acc[mt][nt][rr * 2]     + bias[n];
                    float v1 = acc[mt][nt][rr * 2 + 1] + bias[n + 1];
                    *(uint32_t*)(oh + (size_t)m * ldo + n) = pack_h2(v0, v1);
                }
            }
        }
    }
}

// ---------------------------------------------------------------------------
// V transpose (self): vT[bh][d][s] <- qkvT[b][s][1024+h*64+d]
// ---------------------------------------------------------------------------
__global__ __launch_bounds__(256)
void prep_vT(const __half* __restrict__ qkvT, __half* __restrict__ vT)
{
    __shared__ __half tl[128 * 72];
    int s0 = blockIdx.x * 128, bh = blockIdx.y;
    int b = bh >> 3, h = bh & 7;
    const __half* src = qkvT + ((size_t)b * 1024 + s0) * 1536 + 1024 + h * 64;
    int tid = threadIdx.x;
#pragma unroll
    for (int it = 0; it < 4; it++) {
        int i = tid + it * 256;
        int row = i >> 3, seg = i & 7;
        *(uint4*)(tl + row * 72 + seg * 8) =
            *(const uint4*)(src + (size_t)row * 1536 + seg * 8);
    }
    __syncthreads();
    __half* dst = vT + (size_t)bh * 64 * 1152 + s0;
#pragma unroll
    for (int it = 0; it < 16; it++) {
        int j = tid + it * 256;
        int d = j >> 6, tp = j & 63;
        __half2 v;
        v.x = tl[(2 * tp) * 72 + d];
        v.y = tl[(2 * tp + 1) * 72 + d];
        *(uint32_t*)(dst + (size_t)d * 1152 + 2 * tp) = *(uint32_t*)&v;
    }
}

// cond V: vT[bh][d][1024+sl] <- ckvT[b][sl][512+h*64+d], zero pad sl>=77
__global__ __launch_bounds__(256)
void prep_condV(const __half* __restrict__ ckvT, __half* __restrict__ vT)
{
    int bh = blockIdx.x, b = bh >> 3, h = bh & 7;
    int tid = threadIdx.x;
    __half z = __float2half(0.f);
#pragma unroll
    for (int it = 0; it < 32; it++) {
        int i = tid + it * 256;
        int d = i >> 7, sl = i & 127;
        __half v = z;
        if (sl < 77) v = ckvT[((size_t)b * 77 + sl) * 1024 + 512 + h * 64 + d];
        vT[(size_t)bh * 64 * 1152 + (size_t)d * 1152 + 1024 + sl] = v;
    }
}

// ---------------------------------------------------------------------------
// Flash attention, all single-pass fp16 mma.
// Block = 128 q for (b,h); 256 thr = 8 warps (4m x 2n).
// K staged directly from qkvT (self) / ckvT (cond, predicated).
// Writes aT [b][t][512] fp16 (proj B operand).
// ---------------------------------------------------------------------------
__global__ __launch_bounds__(256)
void attn_kernel(const __half* __restrict__ qkvT, const __half* __restrict__ ckvT,
                 const __half* __restrict__ vT, __half* __restrict__ aT)
{
    extern __shared__ uint32_t smw[];
    const int OQ = 0, OK = 4608, OV = 9216, OP = 13568;
    float* red_max = (float*)(smw + 22272);   // [2][128]
    float* red_sum = (float*)(smw + 22528);   // [2][128]

    int t0 = blockIdx.x * 128;
    int h  = blockIdx.y;
    int b  = blockIdx.z;
    int bh = b * 8 + h;
    int tid = threadIdx.x;
    int w = tid >> 5, lane = tid & 31;
    int g = lane >> 2, tg = lane & 3;
    int warp_m = w >> 1, warp_n = w & 1;

    // stage Q [t][64] from qkvT
    {
        const __half* qp = qkvT + ((size_t)b * 1024 + t0) * 1536 + h * 64;
#pragma unroll
        for (int it = 0; it < 4; it++) {
            int i = tid + it * 256;
            int row = i >> 3, seg = i & 7;
            *(uint4*)(smw + OQ + row * 36 + seg * 4) =
                *(const uint4*)(qp + (size_t)row * 1536 + seg * 8);
        }
    }

    float oacc[2][4][4];
#pragma unroll
    for (int mt = 0; mt < 2; mt++)
#pragma unroll
        for (int nt = 0; nt < 4; nt++)
#pragma unroll
            for (int c = 0; c < 4; c++) oacc[mt][nt][c] = 0.f;
    float m_run[2][2] = {{-1e30f,-1e30f},{-1e30f,-1e30f}};
    float l_run[2][2] = {{0.f,0.f},{0.f,0.f}};

    __syncthreads();

    for (int kt = 0; kt < 9; kt++) {
        // stage K [s][64] and V [d][128]
        if (kt < 8) {
            const __half* kp = qkvT + ((size_t)b * 1024 + kt * 128) * 1536 + 512 + h * 64;
#pragma unroll
            for (int it = 0; it < 4; it++) {
                int i = tid + it * 256;
                int s = i >> 3, seg = i & 7;
                *(uint4*)(smw + OK + s * 36 + seg * 4) =
                    *(const uint4*)(kp + (size_t)s * 1536 + seg * 8);
            }
        } else {
            const __half* kp = ckvT + (size_t)b * 77 * 1024 + h * 64;
#pragma unroll
            for (int it = 0; it < 4; it++) {
                int i = tid + it * 256;
                int s = i >> 3, seg = i & 7;
                uint4 v = make_uint4(0, 0, 0, 0);
                if (s < 77) v = *(const uint4*)(kp + (size_t)s * 1024 + seg * 8);
                *(uint4*)(smw + OK + s * 36 + seg * 4) = v;
            }
        }
        {
            const __half* vp = vT + (size_t)bh * 64 * 1152 + kt * 128;
#pragma unroll
            for (int it = 0; it < 4; it++) {
                int i = tid + it * 256;
                int d = i >> 4, seg = i & 15;
                *(uint4*)(smw + OV + d * 68 + seg * 4) =
                    *(const uint4*)(vp + (size_t)d * 1152 + seg * 8);
            }
        }
        __syncthreads();

        // S = Q K^T, warp tile 32q x 64s
        float sacc[2][8][4];
#pragma unroll
        for (int mt = 0; mt < 2; mt++)
#pragma unroll
            for (int nt = 0; nt < 8; nt++)
#pragma unroll
                for (int c = 0; c < 4; c++) sacc[mt][nt][c] = 0.f;

#pragma unroll
        for (int ks = 0; ks < 4; ks++) {
            int kb = ks * 8;
            uint32_t af[2][4];
#pragma unroll
            for (int mt = 0; mt < 2; mt++) {
                int rb = warp_m * 32 + mt * 16;
                af[mt][0] = smw[OQ + (rb+g  )*36 + kb + tg];
                af[mt][1] = smw[OQ + (rb+g+8)*36 + kb + tg];
                af[mt][2] = smw[OQ + (rb+g  )*36 + kb + tg + 4];
                af[mt][3] = smw[OQ + (rb+g+8)*36 + kb + tg + 4];
            }
#pragma unroll
            for (int nt = 0; nt < 8; nt++) {
                int cb = warp_n * 64 + nt * 8 + g;
                uint32_t b0 = smw[OK + cb*36 + kb + tg];
                uint32_t b1 = smw[OK + cb*36 + kb + tg + 4];
#pragma unroll
                for (int mt = 0; mt < 2; mt++)
                    mma_f16(sacc[mt][nt], af[mt], b0, b1);
            }
        }

        // scale + mask
#pragma unroll
        for (int mt = 0; mt < 2; mt++)
#pragma unroll
            for (int nt = 0; nt < 8; nt++)
#pragma unroll
                for (int c = 0; c < 4; c++) {
                    float v = sacc[mt][nt][c] * 0.125f;
                    if (kt == 8) {
                        int col = warp_n * 64 + nt * 8 + 2 * tg + (c & 1);
                        if (col >= 77) v = -1e30f;
                    }
                    sacc[mt][nt][c] = v;
                }

        // row max
        float mx[2][2];
#pragma unroll
        for (int mt = 0; mt < 2; mt++)
#pragma unroll
            for (int rr = 0; rr < 2; rr++) {
                float m = -1e30f;
#pragma unroll
                for (int nt = 0; nt < 8; nt++) {
                    m = fmaxf(m, sacc[mt][nt][rr*2]);
                    m = fmaxf(m, sacc[mt][nt][rr*2+1]);
                }
                m = fmaxf(m, __shfl_xor_sync(0xffffffffu, m, 1));
                m = fmaxf(m, __shfl_xor_sync(0xffffffffu, m, 2));
                mx[mt][rr] = m;
            }
        if (tg == 0) {
#pragma unroll
            for (int mt = 0; mt < 2; mt++)
#pragma unroll
                for (int rr = 0; rr < 2; rr++) {
                    int row = warp_m * 32 + mt * 16 + rr * 8 + g;
                    red_max[warp_n * 128 + row] = mx[mt][rr];
                }
        }
        __syncthreads();
        float corr[2][2], nm[2][2];
#pragma unroll
        for (int mt = 0; mt < 2; mt++)
#pragma unroll
            for (int rr = 0; rr < 2; rr++) {
                int row = warp_m * 32 + mt * 16 + rr * 8 + g;
                float tot = fmaxf(mx[mt][rr], red_max[(1 - warp_n) * 128 + row]);
                float newm = fmaxf(m_run[mt][rr], tot);
                corr[mt][rr] = __expf(m_run[mt][rr] - newm);
                nm[mt][rr] = newm;
                m_run[mt][rr] = newm;
            }

        // exp, write P fp16, row sums
        float rs[2][2] = {{0.f,0.f},{0.f,0.f}};
#pragma unroll
        for (int mt = 0; mt < 2; mt++)
#pragma unroll
            for (int rr = 0; rr < 2; rr++) {
                int row = warp_m * 32 + mt * 16 + rr * 8 + g;
#pragma unroll
                for (int nt = 0; nt < 8; nt++) {
                    float p0 = __expf(sacc[mt][nt][rr*2]   - nm[mt][rr]);
                    float p1 = __expf(sacc[mt][nt][rr*2+1] - nm[mt][rr]);
                    rs[mt][rr] += p0 + p1;
                    smw[OP + row * 68 + warp_n * 32 + nt * 4 + tg] = pack_h2(p0, p1);
                }
            }
#pragma unroll
        for (int mt = 0; mt < 2; mt++)
#pragma unroll
            for (int rr = 0; rr < 2; rr++) {
                float s = rs[mt][rr];
                s += __shfl_xor_sync(0xffffffffu, s, 1);
                s += __shfl_xor_sync(0xffffffffu, s, 2);
                rs[mt][rr] = s;
            }
        if (tg == 0) {
#pragma unroll
            for (int mt = 0; mt < 2; mt++)
#pragma unroll
                for (int rr = 0; rr < 2; rr++) {
                    int row = warp_m * 32 + mt * 16 + rr * 8 + g;
                    red_sum[warp_n * 128 + row] = rs[mt][rr];
                }
        }
        // rescale O while waiting
#pragma unroll
        for (int mt = 0; mt < 2; mt++)
#pragma unroll
            for (int nt = 0; nt < 4; nt++) {
                oacc[mt][nt][0] *= corr[mt][0];
                oacc[mt][nt][1] *= corr[mt][0];
                oacc[mt][nt][2] *= corr[mt][1];
                oacc[mt][nt][3] *= corr[mt][1];
            }
        __syncthreads();   // P + red_sum ready
#pragma unroll
        for (int mt = 0; mt < 2; mt++)
#pragma unroll
            for (int rr = 0; rr < 2; rr++) {
                int row = warp_m * 32 + mt * 16 + rr * 8 + g;
                float tot = rs[mt][rr] + red_sum[(1 - warp_n) * 128 + row];
                l_run[mt][rr] = l_run[mt][rr] * corr[mt][rr] + tot;
            }

        // O += P·V, warp tile 32q x 32d
#pragma unroll
        for (int ks = 0; ks < 8; ks++) {
            int kb = ks * 8;
            uint32_t pa[2][4];
#pragma unroll
            for (int mt = 0; mt < 2; mt++) {
                int rb = warp_m * 32 + mt * 16;
                pa[mt][0] = smw[OP + (rb+g  )*68 + kb + tg];
                pa[mt][1] = smw[OP + (rb+g+8)*68 + kb + tg];
                pa[mt][2] = smw[OP + (rb+g  )*68 + kb + tg + 4];
                pa[mt][3] = smw[OP + (rb+g+8)*68 + kb + tg + 4];
            }
#pragma unroll
            for (int nt = 0; nt < 4; nt++) {
                int db = warp_n * 32 + nt * 8 + g;
                uint32_t b0 = smw[OV + db*68 + kb + tg];
                uint32_t b1 = smw[OV + db*68 + kb + tg + 4];
#pragma unroll
                for (int mt = 0; mt < 2; mt++)
                    mma_f16(oacc[mt][nt], pa[mt], b0, b1);
            }
        }
        __syncthreads();
    }

    // normalize + write aT fp16 [t][512]
    float inv[2][2];
#pragma unroll
    for (int mt = 0; mt < 2; mt++)
#pragma unroll
        for (int rr = 0; rr < 2; rr++) inv[mt][rr] = 1.f / l_run[mt][rr];

#pragma unroll
    for (int mt = 0; mt < 2; mt++)
#pragma unroll
        for (int nt = 0; nt < 4; nt++)
#pragma unroll
            for (int rr = 0; rr < 2; rr++) {
                int t = t0 + warp_m * 32 + mt * 16 + rr * 8 + g;
                int d = warp_n * 32 + nt * 8 + 2 * tg;
                float v0 = oacc[mt][nt][rr*2]     * inv[mt][rr];
                float v1 = oacc[mt][nt][rr*2 + 1] * inv[mt][rr];
                *(uint32_t*)(aT + ((size_t)b * 1024 + t) * 512 + h * 64 + d) = pack_h2(v0, v1);
            }
}

// ---------------------------------------------------------------------------
// proj: out[b][m=ch][n=t] fp32 = sum_k W[ch][k]*aT[b][t][k] + bias + x
// ---------------------------------------------------------------------------
__global__ __launch_bounds__(256)
void gemm_WA(const __half* __restrict__ W, const __half* __restrict__ Bm,
             const float* __restrict__ bias, const float* __restrict__ res,
             float* __restrict__ out)
{
    extern __shared__ uint32_t sm[];
    const int OA = 0, OB = 4608;
    const int K = 512, N = 1024;

    int b = blockIdx.z;
    const __half* Bp = Bm + (size_t)b * 1024 * 512;
    float* op = out + (size_t)b * 512 * 1024;
    const float* rp = res + (size_t)b * 512 * 1024;

    int tid = threadIdx.x, w = tid >> 5, lane = tid & 31;
    int g = lane >> 2, tg = lane & 3;
    int warp_m = w >> 2, warp_n = w & 3;
    int m0 = blockIdx.y * 128, n0 = blockIdx.x * 128;

    float acc[4][4][4];
#pragma unroll
    for (int i = 0; i < 4; i++)
#pragma unroll
        for (int j = 0; j < 4; j++)
#pragma unroll
            for (int c = 0; c < 4; c++) acc[i][j][c] = 0.f;

    for (int k0 = 0; k0 < K; k0 += 64) {
#pragma unroll
        for (int it = 0; it < 4; it++) {
            int i = tid + it * 256;
            int row = i >> 3, seg = i & 7;
            *(uint4*)(sm + OA + row * 36 + seg * 4) =
                *(const uint4*)(W + (size_t)(m0 + row) * K + k0 + seg * 8);
            *(uint4*)(sm + OB + row * 36 + seg * 4) =
                *(const uint4*)(Bp + (size_t)(n0 + row) * K + k0 + seg * 8);
        }
        __syncthreads();
#pragma unroll
        for (int ks = 0; ks < 4; ks++) {
            int kb = ks * 8;
            uint32_t af[4][4];
#pragma unroll
            for (int mt = 0; mt < 4; mt++) {
                int rb = warp_m * 64 + mt * 16;
                af[mt][0] = sm[OA + (rb+g  )*36 + kb + tg];
                af[mt][1] = sm[OA + (rb+g+8)*36 + kb + tg];
                af[mt][2] = sm[OA + (rb+g  )*36 + kb + tg + 4];
                af[mt][3] = sm[OA + (rb+g+8)*36 + kb + tg + 4];
            }
#pragma unroll
            for (int nt = 0; nt < 4; nt++) {
                int cb = warp_n * 32 + nt * 8 + g;
                uint32_t b0 = sm[OB + cb*36 + kb + tg];
                uint32_t b1 = sm[OB + cb*36 + kb + tg + 4];
#pragma unroll
                for (int mt = 0; mt < 4; mt++)
                    mma_f16(acc[mt][nt], af[mt], b0, b1);
            }
        }
        __syncthreads();
    }

#pragma unroll
    for (int mt = 0; mt < 4; mt++) {
#pragma unroll
        for (int rr = 0; rr < 2; rr++) {
            int m = m0 + warp_m * 64 + mt * 16 + rr * 8 + g;
            float bi = bias[m];
#pragma unroll
            for (int nt = 0; nt < 4; nt++) {
#pragma unroll
                for (int ci = 0; ci < 2; ci++) {
                    int n = n0 + warp_n * 32 + nt * 8 + 2 * tg + ci;
                    op[(size_t)m * N + n] = acc[mt][nt][rr * 2 + ci] + bi
                                          + rp[(size_t)m * N + n];
                }
            }
        }
    }
}

// ---------------------------------------------------------------------------
extern "C" void kernel_launch(void* const* d_in, const int* in_sizes, int n_in,
                              void* d_out, int out_size)
{
    const float* x     = (const float*)d_in[0];
    const float* c     = (const float*)d_in[1];
    const float* gamma = (const float*)d_in[2];
    const float* beta  = (const float*)d_in[3];
    const float* w_qkv = (const float*)d_in[4];
    const float* b_qkv = (const float*)d_in[5];
    const float* w_c   = (const float*)d_in[6];
    const float* b_c   = (const float*)d_in[7];
    const float* w_p   = (const float*)d_in[8];
    const float* b_p   = (const float*)d_in[9];
    float* out = (float*)d_out;

    __half *xnT, *qkvT, *cT, *ckvT, *vT, *aT, *wq, *wc, *wp;
    cudaGetSymbolAddress((void**)&xnT,  g_xnT);
    cudaGetSymbolAddress((void**)&qkvT, g_qkvT);
    cudaGetSymbolAddress((void**)&cT,   g_cT);
    cudaGetSymbolAddress((void**)&ckvT, g_ckvT);
    cudaGetSymbolAddress((void**)&vT,   g_vT);
    cudaGetSymbolAddress((void**)&aT,   g_aT);
    cudaGetSymbolAddress((void**)&wq,   g_wq);
    cudaGetSymbolAddress((void**)&wc,   g_wc);
    cudaGetSymbolAddress((void**)&wp,   g_wp);

    static bool attr_done = false;
    if (!attr_done) {
        cudaFuncSetAttribute(gemm_AT, cudaFuncAttributeMaxDynamicSharedMemorySize, 36864);
        cudaFuncSetAttribute(gemm_WA, cudaFuncAttributeMaxDynamicSharedMemorySize, 36864);
        cudaFuncSetAttribute(attn_kernel, cudaFuncAttributeMaxDynamicSharedMemorySize, 91136);
        attr_done = true;
    }

    groupnorm_kernel<<<512, 256>>>(x, gamma, beta, xnT);
    convW_kernel<<<3072, 256>>>(w_qkv, wq, 1536 * 512);
    convW_kernel<<<3072, 256>>>(w_c, wc, 1024 * 768);
    convW_kernel<<<1024, 256>>>(w_p, wp, 512 * 512);
    prep_c_kernel<<<dim3(3, 24, 16), 256>>>(c, cT);

    // qkv: [t][1536] fp16
    gemm_AT<<<dim3(12, 8, 16), 256, 36864>>>(xnT, wq, b_qkv, qkvT,
                                             1024, 512, 1024L * 512, 1536, 1024L * 1536);
    // ckv: [l][1024] fp16
    gemm_AT<<<dim3(8, 1, 16), 256, 36864>>>(cT, wc, b_c, ckvT,
                                            77, 768, 77L * 768, 1024, 77L * 1024);

    prep_vT<<<dim3(8, 128), 256>>>(qkvT, vT);
    prep_condV<<<128, 256>>>(ckvT, vT);

    attn_kernel<<<dim3(8, 8, 16), 256, 91136>>>(qkvT, ckvT, vT, aT);

    gemm_WA<<<dim3(8, 4, 16), 256, 36864>>>(wp, aT, b_p, x, out);
}

// round 8
// speedup vs baseline: 5.8579x; 1.0346x over previous
#include <cuda_runtime.h>
#include <cuda_fp16.h>
#include <cstdint>

// B=16, C=512, T=1024, L=77, S=1101(pad->1152), HEADS=8, D=64, GROUPS=32, CROSS=768

__device__ __half g_xnT [16 * 1024 * 512];     // [b][t][512]
__device__ __half g_qkvT[16 * 1024 * 1536];    // [b][t][1536]
__device__ __half g_cT  [16 * 77 * 768];       // [b][l][768]
__device__ __half g_ckvT[16 * 77 * 1024];      // [b][l][1024]
__device__ __half g_vT  [128 * 64 * 1152];     // [bh][d][s]
__device__ __half g_aT  [16 * 1024 * 512];     // [b][t][512]
__device__ __half g_wq[1536 * 512];
__device__ __half g_wc[1024 * 768];
__device__ __half g_wp[512 * 512];

#define DINL __device__ __forceinline__

DINL void mma_f16(float* c, const uint32_t* a, uint32_t b0, uint32_t b1) {
    asm volatile(
        "mma.sync.aligned.m16n8k16.row.col.f32.f16.f16.f32 "
        "{%0,%1,%2,%3},{%4,%5,%6,%7},{%8,%9},{%0,%1,%2,%3};"
        : "+f"(c[0]), "+f"(c[1]), "+f"(c[2]), "+f"(c[3])
        : "r"(a[0]), "r"(a[1]), "r"(a[2]), "r"(a[3]), "r"(b0), "r"(b1));
}
DINL uint32_t pack_h2(float a, float b) {
    __half2 h = __floats2half2_rn(a, b);
    return *(uint32_t*)&h;
}
DINL uint32_t sa32(const void* p) {
    uint32_t a;
    asm("{\n\t.reg .u64 t;\n\tcvta.to.shared.u64 t, %1;\n\tcvt.u32.u64 %0, t;\n\t}"
        : "=r"(a) : "l"(p));
    return a;
}
DINL void cpa16(uint32_t dst, const void* src) {
    asm volatile("cp.async.cg.shared.global [%0], [%1], 16;" :: "r"(dst), "l"(src));
}
DINL void cpa16z(uint32_t dst, const void* src, int sz) {
    asm volatile("cp.async.cg.shared.global [%0], [%1], 16, %2;"
                 :: "r"(dst), "l"(src), "r"(sz));
}
DINL void cpa_commit() { asm volatile("cp.async.commit_group;" ::: "memory"); }
DINL void cpa_wait0()  { asm volatile("cp.async.wait_group 0;" ::: "memory"); }

// ---------------------------------------------------------------------------
// GroupNorm(32) fused transpose + fp16: x[b][C][T] -> xnT[b][t][C]
// ---------------------------------------------------------------------------
__global__ __launch_bounds__(256)
void groupnorm_kernel(const float* __restrict__ x,
                      const float* __restrict__ gamma,
                      const float* __restrict__ beta,
                      __half* __restrict__ xnT)
{
    int b = blockIdx.x >> 5;
    int g = blockIdx.x & 31;
    const float* xp = x + ((size_t)b * 512 + (size_t)g * 16) * 1024;

    float s = 0.f, s2 = 0.f;
    for (int i = threadIdx.x; i < 16384; i += 256) {
        float v = xp[i];
        s += v; s2 += v * v;
    }
#pragma unroll
    for (int o = 16; o > 0; o >>= 1) {
        s  += __shfl_xor_sync(0xffffffffu, s, o);
        s2 += __shfl_xor_sync(0xffffffffu, s2, o);
    }
    __shared__ float ss[8], ss2[8];
    __shared__ float smean, sinv;
    __shared__ float tile[256 * 17];
    int w = threadIdx.x >> 5;
    if ((threadIdx.x & 31) == 0) { ss[w] = s; ss2[w] = s2; }
    __syncthreads();
    if (threadIdx.x == 0) {
        float S = 0.f, S2 = 0.f;
#pragma unroll
        for (int i = 0; i < 8; i++) { S += ss[i]; S2 += ss2[i]; }
        float mean = S * (1.f / 16384.f);
        float var  = S2 * (1.f / 16384.f) - mean * mean;
        smean = mean;
        sinv  = rsqrtf(var + 1e-5f);
    }
    __syncthreads();
    float mean = smean, inv = sinv;

    for (int seg = 0; seg < 4; seg++) {
#pragma unroll
        for (int j = 0; j < 16; j++) {
            int idx = threadIdx.x + j * 256;
            int ch = idx >> 8, tt = idx & 255;
            float v = xp[ch * 1024 + seg * 256 + tt];
            tile[tt * 17 + ch] = (v - mean) * inv * gamma[g * 16 + ch] + beta[g * 16 + ch];
        }
        __syncthreads();
        {
            int t = seg * 256 + threadIdx.x;
            uint32_t wv[8];
#pragma unroll
            for (int c = 0; c < 8; c++)
                wv[c] = pack_h2(tile[threadIdx.x * 17 + 2 * c], tile[threadIdx.x * 17 + 2 * c + 1]);
            __half* dst = xnT + ((size_t)b * 1024 + t) * 512 + g * 16;
            *(uint4*)dst = *(uint4*)&wv[0];
            *(uint4*)(dst + 8) = *(uint4*)&wv[4];
        }
        __syncthreads();
    }
}

// ---------------------------------------------------------------------------
__global__ __launch_bounds__(256)
void convW_kernel(const float* __restrict__ w, __half* __restrict__ h, int n)
{
    int i = blockIdx.x * 256 + threadIdx.x;
    if (i < n) h[i] = __float2half_rn(w[i]);
}

// c [b][768][77] fp32 -> cT [b][77][768] fp16
__global__ __launch_bounds__(256)
void prep_c_kernel(const float* __restrict__ c, __half* __restrict__ cT)
{
    __shared__ float tile[32][33];
    int t0 = blockIdx.x * 32, cb = blockIdx.y * 32, b = blockIdx.z;
    const float* ip = c + (size_t)b * 768 * 77;
    int tx = threadIdx.x & 31, ty = threadIdx.x >> 5;
#pragma unroll
    for (int i = 0; i < 4; i++) {
        int cr = ty + i * 8;
        tile[cr][tx] = (t0 + tx < 77) ? ip[(size_t)(cb + cr) * 77 + t0 + tx] : 0.f;
    }
    __syncthreads();
#pragma unroll
    for (int i = 0; i < 4; i++) {
        int tr = ty + i * 8;
        if (t0 + tr < 77)
            cT[(size_t)b * 77 * 768 + (size_t)(t0 + tr) * 768 + cb + tx] =
                __float2half_rn(tile[tx][tr]);
    }
}

// ---------------------------------------------------------------------------
// gemm_AT: oh[b][m=t][n=ch] = sum_k A[b][t][k]*W[ch][k] + bias, fp16 out.
// 128x128 tile, BK=64, cp.async double-buffered (1 sync / k-step).
// ---------------------------------------------------------------------------
__global__ __launch_bounds__(256)
void gemm_AT(const __half* __restrict__ A, const __half* __restrict__ W,
             const float* __restrict__ bias, __half* __restrict__ oh,
             int Mrows, int K, long aStride, int ldo, long oStride)
{
    extern __shared__ uint32_t sm[];
    int b = blockIdx.z;
    A  += (size_t)b * aStride;
    oh += (size_t)b * oStride;

    int tid = threadIdx.x, w = tid >> 5, lane = tid & 31;
    int g = lane >> 2, tg = lane & 3;
    int warp_m = w >> 2, warp_n = w & 3;
    int m0 = blockIdx.y * 128, n0 = blockIdx.x * 128;
    uint32_t sb = sa32(sm);

    float acc[4][4][4];
#pragma unroll
    for (int i = 0; i < 4; i++)
#pragma unroll
        for (int j = 0; j < 4; j++)
#pragma unroll
            for (int c = 0; c < 4; c++) acc[i][j][c] = 0.f;

    int nk = K >> 6;

    // stage k-step c into buffer
    auto stage = [&](int c, int buf) {
        int OA = buf * 9216, OB = OA + 4608;
        int k0 = c * 64;
#pragma unroll
        for (int it = 0; it < 4; it++) {
            int i = tid + it * 256;
            int row = i >> 3, seg = i & 7;
            int ar = (m0 + row < Mrows) ? (m0 + row) : 0;
            int sz = (m0 + row < Mrows) ? 16 : 0;
            cpa16z(sb + (OA + row * 36 + seg * 4) * 4,
                   A + (size_t)ar * K + k0 + seg * 8, sz);
            cpa16(sb + (OB + row * 36 + seg * 4) * 4,
                  W + (size_t)(n0 + row) * K + k0 + seg * 8);
        }
    };

    stage(0, 0);
    cpa_commit();

    for (int c = 0; c < nk; c++) {
        cpa_wait0();
        __syncthreads();
        if (c + 1 < nk) { stage(c + 1, (c + 1) & 1); cpa_commit(); }
        int OA = (c & 1) * 9216, OB = OA + 4608;
#pragma unroll
        for (int ks = 0; ks < 4; ks++) {
            int kb = ks * 8;
            uint32_t af[4][4];
#pragma unroll
            for (int mt = 0; mt < 4; mt++) {
                int rb = warp_m * 64 + mt * 16;
                af[mt][0] = sm[OA + (rb+g  )*36 + kb + tg];
                af[mt][1] = sm[OA + (rb+g+8)*36 + kb + tg];
                af[mt][2] = sm[OA + (rb+g  )*36 + kb + tg + 4];
                af[mt][3] = sm[OA + (rb+g+8)*36 + kb + tg + 4];
            }
#pragma unroll
            for (int nt = 0; nt < 4; nt++) {
                int cb = warp_n * 32 + nt * 8 + g;
                uint32_t b0 = sm[OB + cb*36 + kb + tg];
                uint32_t b1 = sm[OB + cb*36 + kb + tg + 4];
#pragma unroll
                for (int mt = 0; mt < 4; mt++)
                    mma_f16(acc[mt][nt], af[mt], b0, b1);
            }
        }
    }

#pragma unroll
    for (int mt = 0; mt < 4; mt++) {
#pragma unroll
        for (int rr = 0; rr < 2; rr++) {
            int m = m0 + warp_m * 64 + mt * 16 + rr * 8 + g;
            if (m < Mrows) {
#pragma unroll
                for (int nt = 0; nt < 4; nt++) {
                    int n = n0 + warp_n * 32 + nt * 8 + 2 * tg;
                    float v0 = acc[mt][nt][rr * 2]     + bias[n];
                    float v1 = acc[mt][nt][rr * 2 + 1] + bias[n + 1];
                    *(uint32_t*)(oh + (size_t)m * ldo + n) = pack_h2(v0, v1);
                }
            }
        }
    }
}

// ---------------------------------------------------------------------------
// V transpose (self): vT[bh][d][s] <- qkvT[b][s][1024+h*64+d]
// ---------------------------------------------------------------------------
__global__ __launch_bounds__(256)
void prep_vT(const __half* __restrict__ qkvT, __half* __restrict__ vT)
{
    __shared__ __half tl[128 * 72];
    int s0 = blockIdx.x * 128, bh = blockIdx.y;
    int b = bh >> 3, h = bh & 7;
    const __half* src = qkvT + ((size_t)b * 1024 + s0) * 1536 + 1024 + h * 64;
    int tid = threadIdx.x;
#pragma unroll
    for (int it = 0; it < 4; it++) {
        int i = tid + it * 256;
        int row = i >> 3, seg = i & 7;
        *(uint4*)(tl + row * 72 + seg * 8) =
            *(const uint4*)(src + (size_t)row * 1536 + seg * 8);
    }
    __syncthreads();
    __half* dst = vT + (size_t)bh * 64 * 1152 + s0;
#pragma unroll
    for (int it = 0; it < 16; it++) {
        int j = tid + it * 256;
        int d = j >> 6, tp = j & 63;
        __half2 v;
        v.x = tl[(2 * tp) * 72 + d];
        v.y = tl[(2 * tp + 1) * 72 + d];
        *(uint32_t*)(dst + (size_t)d * 1152 + 2 * tp) = *(uint32_t*)&v;
    }
}

// cond V: vT[bh][d][1024+sl] <- ckvT[b][sl][512+h*64+d], zero pad sl>=77
__global__ __launch_bounds__(256)
void prep_condV(const __half* __restrict__ ckvT, __half* __restrict__ vT)
{
    int bh = blockIdx.x, b = bh >> 3, h = bh & 7;
    int tid = threadIdx.x;
    __half z = __float2half(0.f);
#pragma unroll
    for (int it = 0; it < 32; it++) {
        int i = tid + it * 256;
        int d = i >> 7, sl = i & 127;
        __half v = z;
        if (sl < 77) v = ckvT[((size_t)b * 77 + sl) * 1024 + 512 + h * 64 + d];
        vT[(size_t)bh * 64 * 1152 + (size_t)d * 1152 + 1024 + sl] = v;
    }
}

// ---------------------------------------------------------------------------
// Flash attention v2: warp = 16q x 128k (full key width) -> P stays in
// registers; softmax is shuffle-only; cp.async double-buffered K/V; 1 sync/tile.
// smem: Q[128][36w] | {K[128][36w], V[64][68w]} x2  = 22528 words
// ---------------------------------------------------------------------------
__global__ __launch_bounds__(256)
void attn_kernel(const __half* __restrict__ qkvT, const __half* __restrict__ ckvT,
                 const __half* __restrict__ vT, __half* __restrict__ aT)
{
    extern __shared__ uint32_t smw[];
    const int OQ = 0;

    int t0 = blockIdx.x * 128;
    int h  = blockIdx.y;
    int b  = blockIdx.z;
    int bh = b * 8 + h;
    int tid = threadIdx.x;
    int w = tid >> 5, lane = tid & 31;
    int g = lane >> 2, tg = lane & 3;
    uint32_t sb = sa32(smw);

    auto stage_kv = [&](int kt, int buf) {
        int OKb = 4608 + buf * 8960;
        int OVb = OKb + 4608;
        if (kt < 8) {
            const __half* kp = qkvT + ((size_t)b * 1024 + kt * 128) * 1536 + 512 + h * 64;
#pragma unroll
            for (int it = 0; it < 4; it++) {
                int i = tid + it * 256, s = i >> 3, seg = i & 7;
                cpa16(sb + (OKb + s * 36 + seg * 4) * 4, kp + (size_t)s * 1536 + seg * 8);
            }
        } else {
            const __half* kp = ckvT + (size_t)b * 77 * 1024 + h * 64;
#pragma unroll
            for (int it = 0; it < 4; it++) {
                int i = tid + it * 256, s = i >> 3, seg = i & 7;
                int sr = (s < 77) ? s : 0;
                int sz = (s < 77) ? 16 : 0;
                cpa16z(sb + (OKb + s * 36 + seg * 4) * 4,
                       kp + (size_t)sr * 1024 + seg * 8, sz);
            }
        }
        const __half* vp = vT + (size_t)bh * 64 * 1152 + kt * 128;
#pragma unroll
        for (int it = 0; it < 4; it++) {
            int i = tid + it * 256, d = i >> 4, seg = i & 15;
            cpa16(sb + (OVb + d * 68 + seg * 4) * 4, vp + (size_t)d * 1152 + seg * 8);
        }
    };

    // prefetch Q + tile 0 (one group)
    {
        const __half* qp = qkvT + ((size_t)b * 1024 + t0) * 1536 + h * 64;
#pragma unroll
        for (int it = 0; it < 4; it++) {
            int i = tid + it * 256, row = i >> 3, seg = i & 7;
            cpa16(sb + (OQ + row * 36 + seg * 4) * 4, qp + (size_t)row * 1536 + seg * 8);
        }
    }
    stage_kv(0, 0);
    cpa_commit();

    float oacc[8][4];
#pragma unroll
    for (int nt = 0; nt < 8; nt++)
#pragma unroll
        for (int c = 0; c < 4; c++) oacc[nt][c] = 0.f;
    float m_run[2] = {-1e30f, -1e30f};
    float l_run[2] = {0.f, 0.f};
    int rb = w * 16;

    for (int kt = 0; kt < 9; kt++) {
        cpa_wait0();
        __syncthreads();
        if (kt < 8) { stage_kv(kt + 1, (kt + 1) & 1); cpa_commit(); }
        int OKb = 4608 + (kt & 1) * 8960;
        int OVb = OKb + 4608;

        // ---- S = Q K^T : warp tile 16q x 128k ----
        float sacc[16][4];
#pragma unroll
        for (int nt = 0; nt < 16; nt++)
#pragma unroll
            for (int c = 0; c < 4; c++) sacc[nt][c] = 0.f;

#pragma unroll
        for (int ks = 0; ks < 4; ks++) {
            int kb = ks * 8;
            uint32_t af[4];
            af[0] = smw[OQ + (rb+g  )*36 + kb + tg];
            af[1] = smw[OQ + (rb+g+8)*36 + kb + tg];
            af[2] = smw[OQ + (rb+g  )*36 + kb + tg + 4];
            af[3] = smw[OQ + (rb+g+8)*36 + kb + tg + 4];
#pragma unroll
            for (int nt = 0; nt < 16; nt++) {
                int cb = nt * 8 + g;
                uint32_t b0 = smw[OKb + cb*36 + kb + tg];
                uint32_t b1 = smw[OKb + cb*36 + kb + tg + 4];
                mma_f16(sacc[nt], af, b0, b1);
            }
        }

        // ---- scale + mask ----
#pragma unroll
        for (int nt = 0; nt < 16; nt++)
#pragma unroll
            for (int c = 0; c < 4; c++) {
                float v = sacc[nt][c] * 0.125f;
                if (kt == 8 && (nt * 8 + 2 * tg + (c & 1)) >= 77) v = -1e30f;
                sacc[nt][c] = v;
            }

        // ---- row max (shuffle-only; row lives in 4 tg lanes) ----
        float mx[2];
#pragma unroll
        for (int rr = 0; rr < 2; rr++) {
            float m = -1e30f;
#pragma unroll
            for (int nt = 0; nt < 16; nt++) {
                m = fmaxf(m, sacc[nt][rr*2]);
                m = fmaxf(m, sacc[nt][rr*2+1]);
            }
            m = fmaxf(m, __shfl_xor_sync(0xffffffffu, m, 1));
            m = fmaxf(m, __shfl_xor_sync(0xffffffffu, m, 2));
            mx[rr] = m;
        }
        float nm[2], corr[2];
#pragma unroll
        for (int rr = 0; rr < 2; rr++) {
            nm[rr] = fmaxf(m_run[rr], mx[rr]);
            corr[rr] = __expf(m_run[rr] - nm[rr]);
            m_run[rr] = nm[rr];
        }
#pragma unroll
        for (int nt = 0; nt < 8; nt++) {
            oacc[nt][0] *= corr[0];
            oacc[nt][1] *= corr[0];
            oacc[nt][2] *= corr[1];
            oacc[nt][3] *= corr[1];
        }

        // ---- per 16-key block: exp -> pack P frags (registers) -> PV ----
        float rs[2] = {0.f, 0.f};
#pragma unroll
        for (int j = 0; j < 8; j++) {
            float p0 = __expf(sacc[2*j  ][0] - nm[0]);
            float p1 = __expf(sacc[2*j  ][1] - nm[0]);
            float p2 = __expf(sacc[2*j  ][2] - nm[1]);
            float p3 = __expf(sacc[2*j  ][3] - nm[1]);
            float p4 = __expf(sacc[2*j+1][0] - nm[0]);
            float p5 = __expf(sacc[2*j+1][1] - nm[0]);
            float p6 = __expf(sacc[2*j+1][2] - nm[1]);
            float p7 = __expf(sacc[2*j+1][3] - nm[1]);
            rs[0] += (p0 + p1) + (p4 + p5);
            rs[1] += (p2 + p3) + (p6 + p7);
            uint32_t pa[4];
            pa[0] = pack_h2(p0, p1);
            pa[1] = pack_h2(p2, p3);
            pa[2] = pack_h2(p4, p5);
            pa[3] = pack_h2(p6, p7);
#pragma unroll
            for (int nt = 0; nt < 8; nt++) {
                int db = nt * 8 + g;
                uint32_t b0 = smw[OVb + db*68 + j*8 + tg];
                uint32_t b1 = smw[OVb + db*68 + j*8 + tg + 4];
                mma_f16(oacc[nt], pa, b0, b1);
            }
        }
#pragma unroll
        for (int rr = 0; rr < 2; rr++) {
            float s = rs[rr];
            s += __shfl_xor_sync(0xffffffffu, s, 1);
            s += __shfl_xor_sync(0xffffffffu, s, 2);
            l_run[rr] = l_run[rr] * corr[rr] + s;
        }
    }

    // ---- normalize + write aT fp16 [t][512] ----
    float inv[2] = {1.f / l_run[0], 1.f / l_run[1]};
#pragma unroll
    for (int nt = 0; nt < 8; nt++)
#pragma unroll
        for (int rr = 0; rr < 2; rr++) {
            int t = t0 + rb + rr * 8 + g;
            int d = nt * 8 + 2 * tg;
            float v0 = oacc[nt][rr*2]     * inv[rr];
            float v1 = oacc[nt][rr*2 + 1] * inv[rr];
            *(uint32_t*)(aT + ((size_t)b * 1024 + t) * 512 + h * 64 + d) = pack_h2(v0, v1);
        }
}

// ---------------------------------------------------------------------------
// proj: out[b][m=ch][n=t] fp32 = sum_k W[ch][k]*aT[b][t][k] + bias + x
// cp.async double-buffered.
// ---------------------------------------------------------------------------
__global__ __launch_bounds__(256)
void gemm_WA(const __half* __restrict__ W, const __half* __restrict__ Bm,
             const float* __restrict__ bias, const float* __restrict__ res,
             float* __restrict__ out)
{
    extern __shared__ uint32_t sm[];
    const int K = 512, N = 1024;

    int b = blockIdx.z;
    const __half* Bp = Bm + (size_t)b * 1024 * 512;
    float* op = out + (size_t)b * 512 * 1024;
    const float* rp = res + (size_t)b * 512 * 1024;

    int tid = threadIdx.x, w = tid >> 5, lane = tid & 31;
    int g = lane >> 2, tg = lane & 3;
    int warp_m = w >> 2, warp_n = w & 3;
    int m0 = blockIdx.y * 128, n0 = blockIdx.x * 128;
    uint32_t sb = sa32(sm);

    float acc[4][4][4];
#pragma unroll
    for (int i = 0; i < 4; i++)
#pragma unroll
        for (int j = 0; j < 4; j++)
#pragma unroll
            for (int c = 0; c < 4; c++) acc[i][j][c] = 0.f;

    auto stage = [&](int c, int buf) {
        int OA = buf * 9216, OB = OA + 4608;
        int k0 = c * 64;
#pragma unroll
        for (int it = 0; it < 4; it++) {
            int i = tid + it * 256;
            int row = i >> 3, seg = i & 7;
            cpa16(sb + (OA + row * 36 + seg * 4) * 4,
                  W + (size_t)(m0 + row) * K + k0 + seg * 8);
            cpa16(sb + (OB + row * 36 + seg * 4) * 4,
                  Bp + (size_t)(n0 + row) * K + k0 + seg * 8);
        }
    };

    stage(0, 0);
    cpa_commit();

    for (int c = 0; c < 8; c++) {
        cpa_wait0();
        __syncthreads();
        if (c + 1 < 8) { stage(c + 1, (c + 1) & 1); cpa_commit(); }
        int OA = (c & 1) * 9216, OB = OA + 4608;
#pragma unroll
        for (int ks = 0; ks < 4; ks++) {
            int kb = ks * 8;
            uint32_t af[4][4];
#pragma unroll
            for (int mt = 0; mt < 4; mt++) {
                int rb = warp_m * 64 + mt * 16;
                af[mt][0] = sm[OA + (rb+g  )*36 + kb + tg];
                af[mt][1] = sm[OA + (rb+g+8)*36 + kb + tg];
                af[mt][2] = sm[OA + (rb+g  )*36 + kb + tg + 4];
                af[mt][3] = sm[OA + (rb+g+8)*36 + kb + tg + 4];
            }
#pragma unroll
            for (int nt = 0; nt < 4; nt++) {
                int cb = warp_n * 32 + nt * 8 + g;
                uint32_t b0 = sm[OB + cb*36 + kb + tg];
                uint32_t b1 = sm[OB + cb*36 + kb + tg + 4];
#pragma unroll
                for (int mt = 0; mt < 4; mt++)
                    mma_f16(acc[mt][nt], af[mt], b0, b1);
            }
        }
    }

#pragma unroll
    for (int mt = 0; mt < 4; mt++) {
#pragma unroll
        for (int rr = 0; rr < 2; rr++) {
            int m = m0 + warp_m * 64 + mt * 16 + rr * 8 + g;
            float bi = bias[m];
#pragma unroll
            for (int nt = 0; nt < 4; nt++) {
#pragma unroll
                for (int ci = 0; ci < 2; ci++) {
                    int n = n0 + warp_n * 32 + nt * 8 + 2 * tg + ci;
                    op[(size_t)m * N + n] = acc[mt][nt][rr * 2 + ci] + bi
                                          + rp[(size_t)m * N + n];
                }
            }
        }
    }
}

// ---------------------------------------------------------------------------
extern "C" void kernel_launch(void* const* d_in, const int* in_sizes, int n_in,
                              void* d_out, int out_size)
{
    const float* x     = (const float*)d_in[0];
    const float* c     = (const float*)d_in[1];
    const float* gamma = (const float*)d_in[2];
    const float* beta  = (const float*)d_in[3];
    const float* w_qkv = (const float*)d_in[4];
    const float* b_qkv = (const float*)d_in[5];
    const float* w_c   = (const float*)d_in[6];
    const float* b_c   = (const float*)d_in[7];
    const float* w_p   = (const float*)d_in[8];
    const float* b_p   = (const float*)d_in[9];
    float* out = (float*)d_out;

    __half *xnT, *qkvT, *cT, *ckvT, *vT, *aT, *wq, *wc, *wp;
    cudaGetSymbolAddress((void**)&xnT,  g_xnT);
    cudaGetSymbolAddress((void**)&qkvT, g_qkvT);
    cudaGetSymbolAddress((void**)&cT,   g_cT);
    cudaGetSymbolAddress((void**)&ckvT, g_ckvT);
    cudaGetSymbolAddress((void**)&vT,   g_vT);
    cudaGetSymbolAddress((void**)&aT,   g_aT);
    cudaGetSymbolAddress((void**)&wq,   g_wq);
    cudaGetSymbolAddress((void**)&wc,   g_wc);
    cudaGetSymbolAddress((void**)&wp,   g_wp);

    static bool attr_done = false;
    if (!attr_done) {
        cudaFuncSetAttribute(gemm_AT, cudaFuncAttributeMaxDynamicSharedMemorySize, 73728);
        cudaFuncSetAttribute(gemm_WA, cudaFuncAttributeMaxDynamicSharedMemorySize, 73728);
        cudaFuncSetAttribute(attn_kernel, cudaFuncAttributeMaxDynamicSharedMemorySize, 90112);
        attr_done = true;
    }

    groupnorm_kernel<<<512, 256>>>(x, gamma, beta, xnT);
    convW_kernel<<<3072, 256>>>(w_qkv, wq, 1536 * 512);
    convW_kernel<<<3072, 256>>>(w_c, wc, 1024 * 768);
    convW_kernel<<<1024, 256>>>(w_p, wp, 512 * 512);
    prep_c_kernel<<<dim3(3, 24, 16), 256>>>(c, cT);

    // qkv: [t][1536] fp16
    gemm_AT<<<dim3(12, 8, 16), 256, 73728>>>(xnT, wq, b_qkv, qkvT,
                                             1024, 512, 1024L * 512, 1536, 1024L * 1536);
    // ckv: [l][1024] fp16
    gemm_AT<<<dim3(8, 1, 16), 256, 73728>>>(cT, wc, b_c, ckvT,
                                            77, 768, 77L * 768, 1024, 77L * 1024);

    prep_vT<<<dim3(8, 128), 256>>>(qkvT, vT);
    prep_condV<<<128, 256>>>(ckvT, vT);

    attn_kernel<<<dim3(8, 8, 16), 256, 90112>>>(qkvT, ckvT, vT, aT);

    gemm_WA<<<dim3(8, 4, 16), 256, 73728>>>(wp, aT, b_p, x, out);
}

// round 9
// speedup vs baseline: 7.1669x; 1.2234x over previous
#include <cuda_runtime.h>
#include <cuda_fp16.h>
#include <cstdint>

// B=16, C=512, T=1024, L=77, S=1101(pad->1152), HEADS=8, D=64, GROUPS=32, CROSS=768

__device__ __half g_xnT [16 * 1024 * 512];     // [b][t][512]
__device__ __half g_qkvT[16 * 1024 * 1536];    // [b][t][1536]
__device__ __half g_cT  [16 * 77 * 768];       // [b][l][768]
__device__ __half g_ckvT[16 * 77 * 1024];      // [b][l][1024]
__device__ __half g_vT  [128 * 64 * 1152];     // [bh][d][s]
__device__ __half g_aT  [16 * 1024 * 512];     // [b][t][512]
__device__ __half g_wq[1536 * 512];
__device__ __half g_wc[1024 * 768];
__device__ __half g_wp[512 * 512];

#define DINL __device__ __forceinline__

DINL void mma_f16(float* c, const uint32_t* a, uint32_t b0, uint32_t b1) {
    asm volatile(
        "mma.sync.aligned.m16n8k16.row.col.f32.f16.f16.f32 "
        "{%0,%1,%2,%3},{%4,%5,%6,%7},{%8,%9},{%0,%1,%2,%3};"
        : "+f"(c[0]), "+f"(c[1]), "+f"(c[2]), "+f"(c[3])
        : "r"(a[0]), "r"(a[1]), "r"(a[2]), "r"(a[3]), "r"(b0), "r"(b1));
}
DINL uint32_t pack_h2(float a, float b) {
    __half2 h = __floats2half2_rn(a, b);
    return *(uint32_t*)&h;
}
DINL uint32_t ex2_h2(float a, float b) {
    uint32_t in = pack_h2(a, b), out;
    asm("ex2.approx.f16x2 %0, %1;" : "=r"(out) : "r"(in));
    return out;
}
DINL uint32_t sa32(const void* p) {
    uint32_t a;
    asm("{\n\t.reg .u64 t;\n\tcvta.to.shared.u64 t, %1;\n\tcvt.u32.u64 %0, t;\n\t}"
        : "=r"(a) : "l"(p));
    return a;
}
DINL void cpa16(uint32_t dst, const void* src) {
    asm volatile("cp.async.cg.shared.global [%0], [%1], 16;" :: "r"(dst), "l"(src));
}
DINL void cpa16z(uint32_t dst, const void* src, int sz) {
    asm volatile("cp.async.cg.shared.global [%0], [%1], 16, %2;"
                 :: "r"(dst), "l"(src), "r"(sz));
}
DINL void cpa_commit() { asm volatile("cp.async.commit_group;" ::: "memory"); }
DINL void cpa_wait0()  { asm volatile("cp.async.wait_group 0;" ::: "memory"); }

// ---------------------------------------------------------------------------
// GroupNorm(32) fused transpose + fp16: x[b][C][T] -> xnT[b][t][C]
// ---------------------------------------------------------------------------
__global__ __launch_bounds__(256)
void groupnorm_kernel(const float* __restrict__ x,
                      const float* __restrict__ gamma,
                      const float* __restrict__ beta,
                      __half* __restrict__ xnT)
{
    int b = blockIdx.x >> 5;
    int g = blockIdx.x & 31;
    const float* xp = x + ((size_t)b * 512 + (size_t)g * 16) * 1024;

    float s = 0.f, s2 = 0.f;
    for (int i = threadIdx.x; i < 16384; i += 256) {
        float v = xp[i];
        s += v; s2 += v * v;
    }
#pragma unroll
    for (int o = 16; o > 0; o >>= 1) {
        s  += __shfl_xor_sync(0xffffffffu, s, o);
        s2 += __shfl_xor_sync(0xffffffffu, s2, o);
    }
    __shared__ float ss[8], ss2[8];
    __shared__ float smean, sinv;
    __shared__ float tile[256 * 17];
    int w = threadIdx.x >> 5;
    if ((threadIdx.x & 31) == 0) { ss[w] = s; ss2[w] = s2; }
    __syncthreads();
    if (threadIdx.x == 0) {
        float S = 0.f, S2 = 0.f;
#pragma unroll
        for (int i = 0; i < 8; i++) { S += ss[i]; S2 += ss2[i]; }
        float mean = S * (1.f / 16384.f);
        float var  = S2 * (1.f / 16384.f) - mean * mean;
        smean = mean;
        sinv  = rsqrtf(var + 1e-5f);
    }
    __syncthreads();
    float mean = smean, inv = sinv;

    for (int seg = 0; seg < 4; seg++) {
#pragma unroll
        for (int j = 0; j < 16; j++) {
            int idx = threadIdx.x + j * 256;
            int ch = idx >> 8, tt = idx & 255;
            float v = xp[ch * 1024 + seg * 256 + tt];
            tile[tt * 17 + ch] = (v - mean) * inv * gamma[g * 16 + ch] + beta[g * 16 + ch];
        }
        __syncthreads();
        {
            int t = seg * 256 + threadIdx.x;
            uint32_t wv[8];
#pragma unroll
            for (int c = 0; c < 8; c++)
                wv[c] = pack_h2(tile[threadIdx.x * 17 + 2 * c], tile[threadIdx.x * 17 + 2 * c + 1]);
            __half* dst = xnT + ((size_t)b * 1024 + t) * 512 + g * 16;
            *(uint4*)dst = *(uint4*)&wv[0];
            *(uint4*)(dst + 8) = *(uint4*)&wv[4];
        }
        __syncthreads();
    }
}

// ---------------------------------------------------------------------------
__global__ __launch_bounds__(256)
void convW_kernel(const float* __restrict__ w, __half* __restrict__ h, int n)
{
    int i = blockIdx.x * 256 + threadIdx.x;
    if (i < n) h[i] = __float2half_rn(w[i]);
}

// c [b][768][77] fp32 -> cT [b][77][768] fp16
__global__ __launch_bounds__(256)
void prep_c_kernel(const float* __restrict__ c, __half* __restrict__ cT)
{
    __shared__ float tile[32][33];
    int t0 = blockIdx.x * 32, cb = blockIdx.y * 32, b = blockIdx.z;
    const float* ip = c + (size_t)b * 768 * 77;
    int tx = threadIdx.x & 31, ty = threadIdx.x >> 5;
#pragma unroll
    for (int i = 0; i < 4; i++) {
        int cr = ty + i * 8;
        tile[cr][tx] = (t0 + tx < 77) ? ip[(size_t)(cb + cr) * 77 + t0 + tx] : 0.f;
    }
    __syncthreads();
#pragma unroll
    for (int i = 0; i < 4; i++) {
        int tr = ty + i * 8;
        if (t0 + tr < 77)
            cT[(size_t)b * 77 * 768 + (size_t)(t0 + tr) * 768 + cb + tx] =
                __float2half_rn(tile[tx][tr]);
    }
}

// ---------------------------------------------------------------------------
// gemm_AT: oh[b][m=t][n=ch] = sum_k A[b][t][k]*W[ch][k] + bias, fp16 out.
// 128x128, BK=64, cp.async double-buffered, 2 CTAs/SM.
// ---------------------------------------------------------------------------
__global__ __launch_bounds__(256, 2)
void gemm_AT(const __half* __restrict__ A, const __half* __restrict__ W,
             const float* __restrict__ bias, __half* __restrict__ oh,
             int Mrows, int K, long aStride, int ldo, long oStride)
{
    extern __shared__ uint32_t sm[];
    int b = blockIdx.z;
    A  += (size_t)b * aStride;
    oh += (size_t)b * oStride;

    int tid = threadIdx.x, w = tid >> 5, lane = tid & 31;
    int g = lane >> 2, tg = lane & 3;
    int warp_m = w >> 2, warp_n = w & 3;
    int m0 = blockIdx.y * 128, n0 = blockIdx.x * 128;
    uint32_t sb = sa32(sm);

    float acc[4][4][4];
#pragma unroll
    for (int i = 0; i < 4; i++)
#pragma unroll
        for (int j = 0; j < 4; j++)
#pragma unroll
            for (int c = 0; c < 4; c++) acc[i][j][c] = 0.f;

    int nk = K >> 6;

    auto stage = [&](int c, int buf) {
        int OA = buf * 9216, OB = OA + 4608;
        int k0 = c * 64;
#pragma unroll
        for (int it = 0; it < 4; it++) {
            int i = tid + it * 256;
            int row = i >> 3, seg = i & 7;
            int ar = (m0 + row < Mrows) ? (m0 + row) : 0;
            int sz = (m0 + row < Mrows) ? 16 : 0;
            cpa16z(sb + (OA + row * 36 + seg * 4) * 4,
                   A + (size_t)ar * K + k0 + seg * 8, sz);
            cpa16(sb + (OB + row * 36 + seg * 4) * 4,
                  W + (size_t)(n0 + row) * K + k0 + seg * 8);
        }
    };

    stage(0, 0);
    cpa_commit();

    for (int c = 0; c < nk; c++) {
        cpa_wait0();
        __syncthreads();
        if (c + 1 < nk) { stage(c + 1, (c + 1) & 1); cpa_commit(); }
        int OA = (c & 1) * 9216, OB = OA + 4608;
#pragma unroll
        for (int ks = 0; ks < 4; ks++) {
            int kb = ks * 8;
            uint32_t af[4][4];
#pragma unroll
            for (int mt = 0; mt < 4; mt++) {
                int rb = warp_m * 64 + mt * 16;
                af[mt][0] = sm[OA + (rb+g  )*36 + kb + tg];
                af[mt][1] = sm[OA + (rb+g+8)*36 + kb + tg];
                af[mt][2] = sm[OA + (rb+g  )*36 + kb + tg + 4];
                af[mt][3] = sm[OA + (rb+g+8)*36 + kb + tg + 4];
            }
#pragma unroll
            for (int nt = 0; nt < 4; nt++) {
                int cb = warp_n * 32 + nt * 8 + g;
                uint32_t b0 = sm[OB + cb*36 + kb + tg];
                uint32_t b1 = sm[OB + cb*36 + kb + tg + 4];
#pragma unroll
                for (int mt = 0; mt < 4; mt++)
                    mma_f16(acc[mt][nt], af[mt], b0, b1);
            }
        }
    }

#pragma unroll
    for (int mt = 0; mt < 4; mt++) {
#pragma unroll
        for (int rr = 0; rr < 2; rr++) {
            int m = m0 + warp_m * 64 + mt * 16 + rr * 8 + g;
            if (m < Mrows) {
#pragma unroll
                for (int nt = 0; nt < 4; nt++) {
                    int n = n0 + warp_n * 32 + nt * 8 + 2 * tg;
                    float v0 = acc[mt][nt][rr * 2]     + bias[n];
                    float v1 = acc[mt][nt][rr * 2 + 1] + bias[n + 1];
                    *(uint32_t*)(oh + (size_t)m * ldo + n) = pack_h2(v0, v1);
                }
            }
        }
    }
}

// ---------------------------------------------------------------------------
// V transpose (self): vT[bh][d][s] <- qkvT[b][s][1024+h*64+d]
// ---------------------------------------------------------------------------
__global__ __launch_bounds__(256)
void prep_vT(const __half* __restrict__ qkvT, __half* __restrict__ vT)
{
    __shared__ __half tl[128 * 72];
    int s0 = blockIdx.x * 128, bh = blockIdx.y;
    int b = bh >> 3, h = bh & 7;
    const __half* src = qkvT + ((size_t)b * 1024 + s0) * 1536 + 1024 + h * 64;
    int tid = threadIdx.x;
#pragma unroll
    for (int it = 0; it < 4; it++) {
        int i = tid + it * 256;
        int row = i >> 3, seg = i & 7;
        *(uint4*)(tl + row * 72 + seg * 8) =
            *(const uint4*)(src + (size_t)row * 1536 + seg * 8);
    }
    __syncthreads();
    __half* dst = vT + (size_t)bh * 64 * 1152 + s0;
#pragma unroll
    for (int it = 0; it < 16; it++) {
        int j = tid + it * 256;
        int d = j >> 6, tp = j & 63;
        __half2 v;
        v.x = tl[(2 * tp) * 72 + d];
        v.y = tl[(2 * tp + 1) * 72 + d];
        *(uint32_t*)(dst + (size_t)d * 1152 + 2 * tp) = *(uint32_t*)&v;
    }
}

// cond V: vT[bh][d][1024+sl] <- ckvT[b][sl][512+h*64+d], zero pad sl>=77
__global__ __launch_bounds__(256)
void prep_condV(const __half* __restrict__ ckvT, __half* __restrict__ vT)
{
    int bh = blockIdx.x, b = bh >> 3, h = bh & 7;
    int tid = threadIdx.x;
    __half z = __float2half(0.f);
#pragma unroll
    for (int it = 0; it < 32; it++) {
        int i = tid + it * 256;
        int d = i >> 7, sl = i & 127;
        __half v = z;
        if (sl < 77) v = ckvT[((size_t)b * 77 + sl) * 1024 + 512 + h * 64 + d];
        vT[(size_t)bh * 64 * 1152 + (size_t)d * 1152 + 1024 + sl] = v;
    }
}

// ---------------------------------------------------------------------------
// Flash attention v3: 64-key tiles (18 tiles), warp = 16q x 64k, P in regs,
// exp via ex2.f16x2, row sums via ones-column mma, 2 CTAs/SM.
// smem words: Q[128][36]=4608 | {K[64][36]=2304, V[64][36]=2304} x2 = 13824
// ---------------------------------------------------------------------------
__global__ __launch_bounds__(256, 2)
void attn_kernel(const __half* __restrict__ qkvT, const __half* __restrict__ ckvT,
                 const __half* __restrict__ vT, __half* __restrict__ aT)
{
    extern __shared__ uint32_t smw[];
    const int OQ = 0;
    const float L2E = 1.4426950408889634f;
    const uint32_t ONES2 = 0x3C003C00u;

    int t0 = blockIdx.x * 128;
    int h  = blockIdx.y;
    int b  = blockIdx.z;
    int bh = b * 8 + h;
    int tid = threadIdx.x;
    int w = tid >> 5, lane = tid & 31;
    int g = lane >> 2, tg = lane & 3;
    uint32_t sb = sa32(smw);

    auto stage_kv = [&](int kt, int buf) {
        int OKb = 4608 + buf * 4608;
        int OVb = OKb + 2304;
        if (kt < 16) {
            const __half* kp = qkvT + ((size_t)b * 1024 + kt * 64) * 1536 + 512 + h * 64;
#pragma unroll
            for (int it = 0; it < 2; it++) {
                int i = tid + it * 256, s = i >> 3, seg = i & 7;
                cpa16(sb + (OKb + s * 36 + seg * 4) * 4, kp + (size_t)s * 1536 + seg * 8);
            }
        } else {
            const __half* kp = ckvT + (size_t)b * 77 * 1024 + h * 64;
            int base = (kt - 16) * 64;
#pragma unroll
            for (int it = 0; it < 2; it++) {
                int i = tid + it * 256, s = i >> 3, seg = i & 7;
                int sl = base + s;
                int sr = (sl < 77) ? sl : 0;
                int sz = (sl < 77) ? 16 : 0;
                cpa16z(sb + (OKb + s * 36 + seg * 4) * 4,
                       kp + (size_t)sr * 1024 + seg * 8, sz);
            }
        }
        const __half* vp = vT + (size_t)bh * 64 * 1152 + kt * 64;
#pragma unroll
        for (int it = 0; it < 2; it++) {
            int i = tid + it * 256, d = i >> 3, seg = i & 7;
            cpa16(sb + (OVb + d * 36 + seg * 4) * 4, vp + (size_t)d * 1152 + seg * 8);
        }
    };

    // prefetch Q + tile 0
    {
        const __half* qp = qkvT + ((size_t)b * 1024 + t0) * 1536 + h * 64;
#pragma unroll
        for (int it = 0; it < 4; it++) {
            int i = tid + it * 256, row = i >> 3, seg = i & 7;
            cpa16(sb + (OQ + row * 36 + seg * 4) * 4, qp + (size_t)row * 1536 + seg * 8);
        }
    }
    stage_kv(0, 0);
    cpa_commit();

    float oacc[8][4];
#pragma unroll
    for (int nt = 0; nt < 8; nt++)
#pragma unroll
        for (int c = 0; c < 4; c++) oacc[nt][c] = 0.f;
    float lacc[4] = {0.f, 0.f, 0.f, 0.f};
    float m_run[2] = {-1e30f, -1e30f};
    int rb = w * 16;

    for (int kt = 0; kt < 18; kt++) {
        cpa_wait0();
        __syncthreads();
        if (kt < 17) { stage_kv(kt + 1, (kt + 1) & 1); cpa_commit(); }
        int OKb = 4608 + (kt & 1) * 4608;
        int OVb = OKb + 2304;

        // ---- S = Q K^T : warp tile 16q x 64k ----
        float sacc[8][4];
#pragma unroll
        for (int nt = 0; nt < 8; nt++)
#pragma unroll
            for (int c = 0; c < 4; c++) sacc[nt][c] = 0.f;

#pragma unroll
        for (int ks = 0; ks < 4; ks++) {
            int kb = ks * 8;
            uint32_t af[4];
            af[0] = smw[OQ + (rb+g  )*36 + kb + tg];
            af[1] = smw[OQ + (rb+g+8)*36 + kb + tg];
            af[2] = smw[OQ + (rb+g  )*36 + kb + tg + 4];
            af[3] = smw[OQ + (rb+g+8)*36 + kb + tg + 4];
#pragma unroll
            for (int nt = 0; nt < 8; nt++) {
                int cb = nt * 8 + g;
                uint32_t b0 = smw[OKb + cb*36 + kb + tg];
                uint32_t b1 = smw[OKb + cb*36 + kb + tg + 4];
                mma_f16(sacc[nt], af, b0, b1);
            }
        }

        // ---- scale + mask (tile 17: keys >= 1101 i.e. local col >= 13) ----
#pragma unroll
        for (int nt = 0; nt < 8; nt++)
#pragma unroll
            for (int c = 0; c < 4; c++) {
                float v = sacc[nt][c] * 0.125f;
                if (kt == 17 && (nt * 8 + 2 * tg + (c & 1)) >= 13) v = -1e30f;
                sacc[nt][c] = v;
            }

        // ---- row max (shuffle-only) ----
        float mx[2];
#pragma unroll
        for (int rr = 0; rr < 2; rr++) {
            float m = fmaxf(sacc[0][rr*2], sacc[0][rr*2+1]);
#pragma unroll
            for (int nt = 1; nt < 8; nt++) {
                m = fmaxf(m, sacc[nt][rr*2]);
                m = fmaxf(m, sacc[nt][rr*2+1]);
            }
            m = fmaxf(m, __shfl_xor_sync(0xffffffffu, m, 1));
            m = fmaxf(m, __shfl_xor_sync(0xffffffffu, m, 2));
            mx[rr] = m;
        }
        float nm[2], corr[2], nml[2];
#pragma unroll
        for (int rr = 0; rr < 2; rr++) {
            nm[rr] = fmaxf(m_run[rr], mx[rr]);
            corr[rr] = __expf(m_run[rr] - nm[rr]);
            m_run[rr] = nm[rr];
            nml[rr] = nm[rr] * L2E;
        }
#pragma unroll
        for (int nt = 0; nt < 8; nt++) {
            oacc[nt][0] *= corr[0];
            oacc[nt][1] *= corr[0];
            oacc[nt][2] *= corr[1];
            oacc[nt][3] *= corr[1];
        }
        lacc[0] *= corr[0]; lacc[1] *= corr[0];
        lacc[2] *= corr[1]; lacc[3] *= corr[1];

        // ---- per 16-key block: ex2.f16x2 exp -> P frags -> PV + ones ----
#pragma unroll
        for (int j = 0; j < 4; j++) {
            uint32_t pa[4];
            pa[0] = ex2_h2(fmaf(sacc[2*j  ][0], L2E, -nml[0]),
                           fmaf(sacc[2*j  ][1], L2E, -nml[0]));
            pa[1] = ex2_h2(fmaf(sacc[2*j  ][2], L2E, -nml[1]),
                           fmaf(sacc[2*j  ][3], L2E, -nml[1]));
            pa[2] = ex2_h2(fmaf(sacc[2*j+1][0], L2E, -nml[0]),
                           fmaf(sacc[2*j+1][1], L2E, -nml[0]));
            pa[3] = ex2_h2(fmaf(sacc[2*j+1][2], L2E, -nml[1]),
                           fmaf(sacc[2*j+1][3], L2E, -nml[1]));
#pragma unroll
            for (int nt = 0; nt < 8; nt++) {
                int db = nt * 8 + g;
                uint32_t b0 = smw[OVb + db*36 + j*8 + tg];
                uint32_t b1 = smw[OVb + db*36 + j*8 + tg + 4];
                mma_f16(oacc[nt], pa, b0, b1);
            }
            mma_f16(lacc, pa, ONES2, ONES2);   // row sums
        }
    }

    // ---- normalize + write aT fp16 [t][512] ----
    float inv[2] = {1.f / lacc[0], 1.f / lacc[2]};
#pragma unroll
    for (int nt = 0; nt < 8; nt++)
#pragma unroll
        for (int rr = 0; rr < 2; rr++) {
            int t = t0 + rb + rr * 8 + g;
            int d = nt * 8 + 2 * tg;
            float v0 = oacc[nt][rr*2]     * inv[rr];
            float v1 = oacc[nt][rr*2 + 1] * inv[rr];
            *(uint32_t*)(aT + ((size_t)b * 1024 + t) * 512 + h * 64 + d) = pack_h2(v0, v1);
        }
}

// ---------------------------------------------------------------------------
// proj: out[b][m=ch][n=t] fp32 = sum_k W[ch][k]*aT[b][t][k] + bias + x
// ---------------------------------------------------------------------------
__global__ __launch_bounds__(256, 2)
void gemm_WA(const __half* __restrict__ W, const __half* __restrict__ Bm,
             const float* __restrict__ bias, const float* __restrict__ res,
             float* __restrict__ out)
{
    extern __shared__ uint32_t sm[];
    const int K = 512, N = 1024;

    int b = blockIdx.z;
    const __half* Bp = Bm + (size_t)b * 1024 * 512;
    float* op = out + (size_t)b * 512 * 1024;
    const float* rp = res + (size_t)b * 512 * 1024;

    int tid = threadIdx.x, w = tid >> 5, lane = tid & 31;
    int g = lane >> 2, tg = lane & 3;
    int warp_m = w >> 2, warp_n = w & 3;
    int m0 = blockIdx.y * 128, n0 = blockIdx.x * 128;
    uint32_t sb = sa32(sm);

    float acc[4][4][4];
#pragma unroll
    for (int i = 0; i < 4; i++)
#pragma unroll
        for (int j = 0; j < 4; j++)
#pragma unroll
            for (int c = 0; c < 4; c++) acc[i][j][c] = 0.f;

    auto stage = [&](int c, int buf) {
        int OA = buf * 9216, OB = OA + 4608;
        int k0 = c * 64;
#pragma unroll
        for (int it = 0; it < 4; it++) {
            int i = tid + it * 256;
            int row = i >> 3, seg = i & 7;
            cpa16(sb + (OA + row * 36 + seg * 4) * 4,
                  W + (size_t)(m0 + row) * K + k0 + seg * 8);
            cpa16(sb + (OB + row * 36 + seg * 4) * 4,
                  Bp + (size_t)(n0 + row) * K + k0 + seg * 8);
        }
    };

    stage(0, 0);
    cpa_commit();

    for (int c = 0; c < 8; c++) {
        cpa_wait0();
        __syncthreads();
        if (c + 1 < 8) { stage(c + 1, (c + 1) & 1); cpa_commit(); }
        int OA = (c & 1) * 9216, OB = OA + 4608;
#pragma unroll
        for (int ks = 0; ks < 4; ks++) {
            int kb = ks * 8;
            uint32_t af[4][4];
#pragma unroll
            for (int mt = 0; mt < 4; mt++) {
                int rb = warp_m * 64 + mt * 16;
                af[mt][0] = sm[OA + (rb+g  )*36 + kb + tg];
                af[mt][1] = sm[OA + (rb+g+8)*36 + kb + tg];
                af[mt][2] = sm[OA + (rb+g  )*36 + kb + tg + 4];
                af[mt][3] = sm[OA + (rb+g+8)*36 + kb + tg + 4];
            }
#pragma unroll
            for (int nt = 0; nt < 4; nt++) {
                int cb = warp_n * 32 + nt * 8 + g;
                uint32_t b0 = sm[OB + cb*36 + kb + tg];
                uint32_t b1 = sm[OB + cb*36 + kb + tg + 4];
#pragma unroll
                for (int mt = 0; mt < 4; mt++)
                    mma_f16(acc[mt][nt], af[mt], b0, b1);
            }
        }
    }

#pragma unroll
    for (int mt = 0; mt < 4; mt++) {
#pragma unroll
        for (int rr = 0; rr < 2; rr++) {
            int m = m0 + warp_m * 64 + mt * 16 + rr * 8 + g;
            float bi = bias[m];
#pragma unroll
            for (int nt = 0; nt < 4; nt++) {
#pragma unroll
                for (int ci = 0; ci < 2; ci++) {
                    int n = n0 + warp_n * 32 + nt * 8 + 2 * tg + ci;
                    op[(size_t)m * N + n] = acc[mt][nt][rr * 2 + ci] + bi
                                          + rp[(size_t)m * N + n];
                }
            }
        }
    }
}

// ---------------------------------------------------------------------------
extern "C" void kernel_launch(void* const* d_in, const int* in_sizes, int n_in,
                              void* d_out, int out_size)
{
    const float* x     = (const float*)d_in[0];
    const float* c     = (const float*)d_in[1];
    const float* gamma = (const float*)d_in[2];
    const float* beta  = (const float*)d_in[3];
    const float* w_qkv = (const float*)d_in[4];
    const float* b_qkv = (const float*)d_in[5];
    const float* w_c   = (const float*)d_in[6];
    const float* b_c   = (const float*)d_in[7];
    const float* w_p   = (const float*)d_in[8];
    const float* b_p   = (const float*)d_in[9];
    float* out = (float*)d_out;

    __half *xnT, *qkvT, *cT, *ckvT, *vT, *aT, *wq, *wc, *wp;
    cudaGetSymbolAddress((void**)&xnT,  g_xnT);
    cudaGetSymbolAddress((void**)&qkvT, g_qkvT);
    cudaGetSymbolAddress((void**)&cT,   g_cT);
    cudaGetSymbolAddress((void**)&ckvT, g_ckvT);
    cudaGetSymbolAddress((void**)&vT,   g_vT);
    cudaGetSymbolAddress((void**)&aT,   g_aT);
    cudaGetSymbolAddress((void**)&wq,   g_wq);
    cudaGetSymbolAddress((void**)&wc,   g_wc);
    cudaGetSymbolAddress((void**)&wp,   g_wp);

    static bool attr_done = false;
    if (!attr_done) {
        cudaFuncSetAttribute(gemm_AT, cudaFuncAttributeMaxDynamicSharedMemorySize, 73728);
        cudaFuncSetAttribute(gemm_WA, cudaFuncAttributeMaxDynamicSharedMemorySize, 73728);
        cudaFuncSetAttribute(attn_kernel, cudaFuncAttributeMaxDynamicSharedMemorySize, 55296);
        attr_done = true;
    }

    groupnorm_kernel<<<512, 256>>>(x, gamma, beta, xnT);
    convW_kernel<<<3072, 256>>>(w_qkv, wq, 1536 * 512);
    convW_kernel<<<3072, 256>>>(w_c, wc, 1024 * 768);
    convW_kernel<<<1024, 256>>>(w_p, wp, 512 * 512);
    prep_c_kernel<<<dim3(3, 24, 16), 256>>>(c, cT);

    // qkv: [t][1536] fp16
    gemm_AT<<<dim3(12, 8, 16), 256, 73728>>>(xnT, wq, b_qkv, qkvT,
                                             1024, 512, 1024L * 512, 1536, 1024L * 1536);
    // ckv: [l][1024] fp16
    gemm_AT<<<dim3(8, 1, 16), 256, 73728>>>(cT, wc, b_c, ckvT,
                                            77, 768, 77L * 768, 1024, 77L * 1024);

    prep_vT<<<dim3(8, 128), 256>>>(qkvT, vT);
    prep_condV<<<128, 256>>>(ckvT, vT);

    attn_kernel<<<dim3(8, 8, 16), 256, 55296>>>(qkvT, ckvT, vT, aT);

    gemm_WA<<<dim3(8, 4, 16), 256, 73728>>>(wp, aT, b_p, x, out);
}

// round 10
// speedup vs baseline: 7.3199x; 1.0214x over previous
#include <cuda_runtime.h>
#include <cuda_fp16.h>
#include <cstdint>

// B=16, C=512, T=1024, L=77, S=1101(pad->1152), HEADS=8, D=64, GROUPS=32, CROSS=768

__device__ __half g_xnT [16 * 1024 * 512];     // [b][t][512]
__device__ __half g_qkvT[16 * 1024 * 1536];    // [b][t][1536]
__device__ __half g_cT  [16 * 77 * 768];       // [b][l][768]
__device__ __half g_ckvT[16 * 77 * 1024];      // [b][l][1024]
__device__ __half g_vT  [128 * 64 * 1152];     // [bh][d][s]  (BSS zero => pad rows 0)
__device__ __half g_aT  [16 * 1024 * 512];     // [b][t][512]
__device__ __half g_wq[1536 * 512];
__device__ __half g_wc[1024 * 768];
__device__ __half g_wp[512 * 512];

#define DINL __device__ __forceinline__

DINL void mma_f16(float* c, const uint32_t* a, uint32_t b0, uint32_t b1) {
    asm volatile(
        "mma.sync.aligned.m16n8k16.row.col.f32.f16.f16.f32 "
        "{%0,%1,%2,%3},{%4,%5,%6,%7},{%8,%9},{%0,%1,%2,%3};"
        : "+f"(c[0]), "+f"(c[1]), "+f"(c[2]), "+f"(c[3])
        : "r"(a[0]), "r"(a[1]), "r"(a[2]), "r"(a[3]), "r"(b0), "r"(b1));
}
DINL uint32_t pack_h2(float a, float b) {
    __half2 h = __floats2half2_rn(a, b);
    return *(uint32_t*)&h;
}
DINL uint32_t ex2_h2(float a, float b) {
    uint32_t in = pack_h2(a, b), out;
    asm("ex2.approx.f16x2 %0, %1;" : "=r"(out) : "r"(in));
    return out;
}
DINL uint32_t sa32(const void* p) {
    uint32_t a;
    asm("{\n\t.reg .u64 t;\n\tcvta.to.shared.u64 t, %1;\n\tcvt.u32.u64 %0, t;\n\t}"
        : "=r"(a) : "l"(p));
    return a;
}
DINL void cpa16(uint32_t dst, const void* src) {
    asm volatile("cp.async.cg.shared.global [%0], [%1], 16;" :: "r"(dst), "l"(src));
}
DINL void cpa16z(uint32_t dst, const void* src, int sz) {
    asm volatile("cp.async.cg.shared.global [%0], [%1], 16, %2;"
                 :: "r"(dst), "l"(src), "r"(sz));
}
DINL void cpa_commit() { asm volatile("cp.async.commit_group;" ::: "memory"); }
DINL void cpa_wait0()  { asm volatile("cp.async.wait_group 0;" ::: "memory"); }

// ---------------------------------------------------------------------------
// GroupNorm(32), ONE global read: slab cached in smem, then normalize +
// transpose + fp16 from smem.  x[b][C][T] -> xnT[b][t][C]
// ---------------------------------------------------------------------------
__global__ __launch_bounds__(256)
void groupnorm_kernel(const float* __restrict__ x,
                      const float* __restrict__ gamma,
                      const float* __restrict__ beta,
                      __half* __restrict__ xnT)
{
    extern __shared__ float xs[];   // [16][1024] = 64KB
    int b = blockIdx.x >> 5;
    int g = blockIdx.x & 31;
    const float* xp = x + ((size_t)b * 512 + (size_t)g * 16) * 1024;

    float s = 0.f, s2 = 0.f;
    for (int i = threadIdx.x; i < 16384; i += 256) {
        float v = xp[i];
        xs[i] = v;
        s += v; s2 += v * v;
    }
#pragma unroll
    for (int o = 16; o > 0; o >>= 1) {
        s  += __shfl_xor_sync(0xffffffffu, s, o);
        s2 += __shfl_xor_sync(0xffffffffu, s2, o);
    }
    __shared__ float ss[8], ss2[8];
    __shared__ float smean, sinv;
    int w = threadIdx.x >> 5;
    if ((threadIdx.x & 31) == 0) { ss[w] = s; ss2[w] = s2; }
    __syncthreads();
    if (threadIdx.x == 0) {
        float S = 0.f, S2 = 0.f;
#pragma unroll
        for (int i = 0; i < 8; i++) { S += ss[i]; S2 += ss2[i]; }
        float mean = S * (1.f / 16384.f);
        float var  = S2 * (1.f / 16384.f) - mean * mean;
        smean = mean;
        sinv  = rsqrtf(var + 1e-5f);
    }
    __syncthreads();
    float mean = smean, inv = sinv;

    float gm[16], bt[16];
#pragma unroll
    for (int ch = 0; ch < 16; ch++) {
        gm[ch] = gamma[g * 16 + ch] * inv;
        bt[ch] = beta[g * 16 + ch] - mean * gm[ch];
    }
#pragma unroll
    for (int seg = 0; seg < 4; seg++) {
        int t = seg * 256 + threadIdx.x;
        uint32_t wv[8];
#pragma unroll
        for (int c = 0; c < 8; c++) {
            float v0 = xs[(2 * c)     * 1024 + t] * gm[2 * c]     + bt[2 * c];
            float v1 = xs[(2 * c + 1) * 1024 + t] * gm[2 * c + 1] + bt[2 * c + 1];
            wv[c] = pack_h2(v0, v1);
        }
        __half* dst = xnT + ((size_t)b * 1024 + t) * 512 + g * 16;
        *(uint4*)dst = *(uint4*)&wv[0];
        *(uint4*)(dst + 8) = *(uint4*)&wv[4];
    }
}

// ---------------------------------------------------------------------------
// all three weight conversions in one launch
// ---------------------------------------------------------------------------
__global__ __launch_bounds__(256)
void convW_all(const float* __restrict__ w0, __half* __restrict__ h0, int n0,
               const float* __restrict__ w1, __half* __restrict__ h1, int n1,
               const float* __restrict__ w2, __half* __restrict__ h2, int n2)
{
    int i = blockIdx.x * 256 + threadIdx.x;
    if (i < n0) { h0[i] = __float2half_rn(w0[i]); return; }
    i -= n0;
    if (i < n1) { h1[i] = __float2half_rn(w1[i]); return; }
    i -= n1;
    if (i < n2) { h2[i] = __float2half_rn(w2[i]); }
}

// c [b][768][77] fp32 -> cT [b][77][768] fp16
__global__ __launch_bounds__(256)
void prep_c_kernel(const float* __restrict__ c, __half* __restrict__ cT)
{
    __shared__ float tile[32][33];
    int t0 = blockIdx.x * 32, cb = blockIdx.y * 32, b = blockIdx.z;
    const float* ip = c + (size_t)b * 768 * 77;
    int tx = threadIdx.x & 31, ty = threadIdx.x >> 5;
#pragma unroll
    for (int i = 0; i < 4; i++) {
        int cr = ty + i * 8;
        tile[cr][tx] = (t0 + tx < 77) ? ip[(size_t)(cb + cr) * 77 + t0 + tx] : 0.f;
    }
    __syncthreads();
#pragma unroll
    for (int i = 0; i < 4; i++) {
        int tr = ty + i * 8;
        if (t0 + tr < 77)
            cT[(size_t)b * 77 * 768 + (size_t)(t0 + tr) * 768 + cb + tx] =
                __float2half_rn(tile[tx][tr]);
    }
}

// ---------------------------------------------------------------------------
// fused qkv + ckv GEMM.  y<8 -> qkv tile (x<12), y==8 -> ckv tile (x<8).
// epilogue also writes V^T slices: n>=vlo -> vT[bh][d][sOff+m].
// ---------------------------------------------------------------------------
DINL void gemm_at_body(const __half* __restrict__ A, const __half* __restrict__ W,
                       const float* __restrict__ bias, __half* __restrict__ oh,
                       __half* __restrict__ voutB,   // vT + b*8*64*1152
                       int Mrows, int K, int ldo, int m0, int n0,
                       int vlo, int sOff, uint32_t* sm, uint32_t sb, int tid)
{
    int w = tid >> 5, lane = tid & 31;
    int g = lane >> 2, tg = lane & 3;
    int warp_m = w >> 2, warp_n = w & 3;

    float acc[4][4][4];
#pragma unroll
    for (int i = 0; i < 4; i++)
#pragma unroll
        for (int j = 0; j < 4; j++)
#pragma unroll
            for (int c = 0; c < 4; c++) acc[i][j][c] = 0.f;

    int nk = K >> 6;

    for (int c = 0; c <= nk; c++) {
        if (c < nk) {   // stage k-step c into buffer c&1
            int OA = (c & 1) * 9216, OB = OA + 4608;
            int k0 = c * 64;
#pragma unroll
            for (int it = 0; it < 4; it++) {
                int i = tid + it * 256;
                int row = i >> 3, seg = i & 7;
                int ar = (m0 + row < Mrows) ? (m0 + row) : 0;
                int sz = (m0 + row < Mrows) ? 16 : 0;
                cpa16z(sb + (OA + row * 36 + seg * 4) * 4,
                       A + (size_t)ar * K + k0 + seg * 8, sz);
                cpa16(sb + (OB + row * 36 + seg * 4) * 4,
                      W + (size_t)(n0 + row) * K + k0 + seg * 8);
            }
            cpa_commit();
        }
        if (c == 0) continue;
        int cc = c - 1;
        if (c < nk)
            asm volatile("cp.async.wait_group 1;" ::: "memory");
        else
            cpa_wait0();
        __syncthreads();
        int OA = (cc & 1) * 9216, OB = OA + 4608;
#pragma unroll
        for (int ks = 0; ks < 4; ks++) {
            int kb = ks * 8;
            uint32_t af[4][4];
#pragma unroll
            for (int mt = 0; mt < 4; mt++) {
                int rb = warp_m * 64 + mt * 16;
                af[mt][0] = sm[OA + (rb+g  )*36 + kb + tg];
                af[mt][1] = sm[OA + (rb+g+8)*36 + kb + tg];
                af[mt][2] = sm[OA + (rb+g  )*36 + kb + tg + 4];
                af[mt][3] = sm[OA + (rb+g+8)*36 + kb + tg + 4];
            }
#pragma unroll
            for (int nt = 0; nt < 4; nt++) {
                int cb = warp_n * 32 + nt * 8 + g;
                uint32_t b0 = sm[OB + cb*36 + kb + tg];
                uint32_t b1 = sm[OB + cb*36 + kb + tg + 4];
#pragma unroll
                for (int mt = 0; mt < 4; mt++)
                    mma_f16(acc[mt][nt], af[mt], b0, b1);
            }
        }
        __syncthreads();
    }

#pragma unroll
    for (int mt = 0; mt < 4; mt++) {
#pragma unroll
        for (int rr = 0; rr < 2; rr++) {
            int m = m0 + warp_m * 64 + mt * 16 + rr * 8 + g;
            if (m < Mrows) {
#pragma unroll
                for (int nt = 0; nt < 4; nt++) {
                    int n = n0 + warp_n * 32 + nt * 8 + 2 * tg;
                    float v0 = acc[mt][nt][rr * 2]     + bias[n];
                    float v1 = acc[mt][nt][rr * 2 + 1] + bias[n + 1];
                    __half2 hh = __floats2half2_rn(v0, v1);
                    *(uint32_t*)(oh + (size_t)m * ldo + n) = *(uint32_t*)&hh;
                    int d0 = n - vlo;
                    if (d0 >= 0) {
                        voutB[((size_t)((d0 >> 6) * 64) + (d0 & 63)) * 1152 + sOff + m] = hh.x;
                        int d1 = d0 + 1;
                        voutB[((size_t)((d1 >> 6) * 64) + (d1 & 63)) * 1152 + sOff + m] = hh.y;
                    }
                }
            }
        }
    }
}

__global__ __launch_bounds__(256, 2)
void gemm_qkv_ckv(const __half* __restrict__ xnT, const __half* __restrict__ wq,
                  const float* __restrict__ b_qkv,
                  const __half* __restrict__ cT, const __half* __restrict__ wc,
                  const float* __restrict__ b_c,
                  __half* __restrict__ qkvT, __half* __restrict__ ckvT,
                  __half* __restrict__ vT)
{
    extern __shared__ uint32_t sm[];
    int b = blockIdx.z;
    uint32_t sb = sa32(sm);
    int tid = threadIdx.x;
    __half* voutB = vT + (size_t)b * 8 * 64 * 1152;

    if (blockIdx.y < 8) {
        gemm_at_body(xnT + (size_t)b * 1024 * 512, wq, b_qkv,
                     qkvT + (size_t)b * 1024 * 1536, voutB,
                     1024, 512, 1536, blockIdx.y * 128, blockIdx.x * 128,
                     1024, 0, sm, sb, tid);
    } else {
        if (blockIdx.x >= 8) return;
        gemm_at_body(cT + (size_t)b * 77 * 768, wc, b_c,
                     ckvT + (size_t)b * 77 * 1024, voutB,
                     77, 768, 1024, 0, blockIdx.x * 128,
                     512, 1024, sm, sb, tid);
    }
}

// ---------------------------------------------------------------------------
// Flash attention: 64-key tiles, warp = 16q x 64k, P in regs, ex2.f16x2 exp,
// row sums via ones-column mma, 2 CTAs/SM, cp.async double-buffered.
// ---------------------------------------------------------------------------
__global__ __launch_bounds__(256, 2)
void attn_kernel(const __half* __restrict__ qkvT, const __half* __restrict__ ckvT,
                 const __half* __restrict__ vT, __half* __restrict__ aT)
{
    extern __shared__ uint32_t smw[];
    const int OQ = 0;
    const float L2E = 1.4426950408889634f;
    const uint32_t ONES2 = 0x3C003C00u;

    int t0 = blockIdx.x * 128;
    int h  = blockIdx.y;
    int b  = blockIdx.z;
    int bh = b * 8 + h;
    int tid = threadIdx.x;
    int w = tid >> 5, lane = tid & 31;
    int g = lane >> 2, tg = lane & 3;
    uint32_t sb = sa32(smw);

    auto stage_kv = [&](int kt, int buf) {
        int OKb = 4608 + buf * 4608;
        int OVb = OKb + 2304;
        if (kt < 16) {
            const __half* kp = qkvT + ((size_t)b * 1024 + kt * 64) * 1536 + 512 + h * 64;
#pragma unroll
            for (int it = 0; it < 2; it++) {
                int i = tid + it * 256, s = i >> 3, seg = i & 7;
                cpa16(sb + (OKb + s * 36 + seg * 4) * 4, kp + (size_t)s * 1536 + seg * 8);
            }
        } else {
            const __half* kp = ckvT + (size_t)b * 77 * 1024 + h * 64;
            int base = (kt - 16) * 64;
#pragma unroll
            for (int it = 0; it < 2; it++) {
                int i = tid + it * 256, s = i >> 3, seg = i & 7;
                int sl = base + s;
                int sr = (sl < 77) ? sl : 0;
                int sz = (sl < 77) ? 16 : 0;
                cpa16z(sb + (OKb + s * 36 + seg * 4) * 4,
                       kp + (size_t)sr * 1024 + seg * 8, sz);
            }
        }
        const __half* vp = vT + (size_t)bh * 64 * 1152 + kt * 64;
#pragma unroll
        for (int it = 0; it < 2; it++) {
            int i = tid + it * 256, d = i >> 3, seg = i & 7;
            cpa16(sb + (OVb + d * 36 + seg * 4) * 4, vp + (size_t)d * 1152 + seg * 8);
        }
    };

    {
        const __half* qp = qkvT + ((size_t)b * 1024 + t0) * 1536 + h * 64;
#pragma unroll
        for (int it = 0; it < 4; it++) {
            int i = tid + it * 256, row = i >> 3, seg = i & 7;
            cpa16(sb + (OQ + row * 36 + seg * 4) * 4, qp + (size_t)row * 1536 + seg * 8);
        }
    }
    stage_kv(0, 0);
    cpa_commit();

    float oacc[8][4];
#pragma unroll
    for (int nt = 0; nt < 8; nt++)
#pragma unroll
        for (int c = 0; c < 4; c++) oacc[nt][c] = 0.f;
    float lacc[4] = {0.f, 0.f, 0.f, 0.f};
    float m_run[2] = {-1e30f, -1e30f};
    int rb = w * 16;

    for (int kt = 0; kt < 18; kt++) {
        cpa_wait0();
        __syncthreads();
        if (kt < 17) { stage_kv(kt + 1, (kt + 1) & 1); cpa_commit(); }
        int OKb = 4608 + (kt & 1) * 4608;
        int OVb = OKb + 2304;

        float sacc[8][4];
#pragma unroll
        for (int nt = 0; nt < 8; nt++)
#pragma unroll
            for (int c = 0; c < 4; c++) sacc[nt][c] = 0.f;

#pragma unroll
        for (int ks = 0; ks < 4; ks++) {
            int kb = ks * 8;
            uint32_t af[4];
            af[0] = smw[OQ + (rb+g  )*36 + kb + tg];
            af[1] = smw[OQ + (rb+g+8)*36 + kb + tg];
            af[2] = smw[OQ + (rb+g  )*36 + kb + tg + 4];
            af[3] = smw[OQ + (rb+g+8)*36 + kb + tg + 4];
#pragma unroll
            for (int nt = 0; nt < 8; nt++) {
                int cb = nt * 8 + g;
                uint32_t b0 = smw[OKb + cb*36 + kb + tg];
                uint32_t b1 = smw[OKb + cb*36 + kb + tg + 4];
                mma_f16(sacc[nt], af, b0, b1);
            }
        }

#pragma unroll
        for (int nt = 0; nt < 8; nt++)
#pragma unroll
            for (int c = 0; c < 4; c++) {
                float v = sacc[nt][c] * 0.125f;
                if (kt == 17 && (nt * 8 + 2 * tg + (c & 1)) >= 13) v = -1e30f;
                sacc[nt][c] = v;
            }

        float mx[2];
#pragma unroll
        for (int rr = 0; rr < 2; rr++) {
            float m = fmaxf(sacc[0][rr*2], sacc[0][rr*2+1]);
#pragma unroll
            for (int nt = 1; nt < 8; nt++) {
                m = fmaxf(m, sacc[nt][rr*2]);
                m = fmaxf(m, sacc[nt][rr*2+1]);
            }
            m = fmaxf(m, __shfl_xor_sync(0xffffffffu, m, 1));
            m = fmaxf(m, __shfl_xor_sync(0xffffffffu, m, 2));
            mx[rr] = m;
        }
        float nm[2], corr[2], nml[2];
#pragma unroll
        for (int rr = 0; rr < 2; rr++) {
            nm[rr] = fmaxf(m_run[rr], mx[rr]);
            corr[rr] = __expf(m_run[rr] - nm[rr]);
            m_run[rr] = nm[rr];
            nml[rr] = nm[rr] * L2E;
        }
#pragma unroll
        for (int nt = 0; nt < 8; nt++) {
            oacc[nt][0] *= corr[0];
            oacc[nt][1] *= corr[0];
            oacc[nt][2] *= corr[1];
            oacc[nt][3] *= corr[1];
        }
        lacc[0] *= corr[0]; lacc[1] *= corr[0];
        lacc[2] *= corr[1]; lacc[3] *= corr[1];

#pragma unroll
        for (int j = 0; j < 4; j++) {
            uint32_t pa[4];
            pa[0] = ex2_h2(fmaf(sacc[2*j  ][0], L2E, -nml[0]),
                           fmaf(sacc[2*j  ][1], L2E, -nml[0]));
            pa[1] = ex2_h2(fmaf(sacc[2*j  ][2], L2E, -nml[1]),
                           fmaf(sacc[2*j  ][3], L2E, -nml[1]));
            pa[2] = ex2_h2(fmaf(sacc[2*j+1][0], L2E, -nml[0]),
                           fmaf(sacc[2*j+1][1], L2E, -nml[0]));
            pa[3] = ex2_h2(fmaf(sacc[2*j+1][2], L2E, -nml[1]),
                           fmaf(sacc[2*j+1][3], L2E, -nml[1]));
#pragma unroll
            for (int nt = 0; nt < 8; nt++) {
                int db = nt * 8 + g;
                uint32_t b0 = smw[OVb + db*36 + j*8 + tg];
                uint32_t b1 = smw[OVb + db*36 + j*8 + tg + 4];
                mma_f16(oacc[nt], pa, b0, b1);
            }
            mma_f16(lacc, pa, ONES2, ONES2);
        }
    }

    float inv[2] = {1.f / lacc[0], 1.f / lacc[2]};
#pragma unroll
    for (int nt = 0; nt < 8; nt++)
#pragma unroll
        for (int rr = 0; rr < 2; rr++) {
            int t = t0 + rb + rr * 8 + g;
            int d = nt * 8 + 2 * tg;
            float v0 = oacc[nt][rr*2]     * inv[rr];
            float v1 = oacc[nt][rr*2 + 1] * inv[rr];
            *(uint32_t*)(aT + ((size_t)b * 1024 + t) * 512 + h * 64 + d) = pack_h2(v0, v1);
        }
}

// ---------------------------------------------------------------------------
// proj: out[b][m=ch][n=t] fp32 = sum_k W[ch][k]*aT[b][t][k] + bias + x
// ---------------------------------------------------------------------------
__global__ __launch_bounds__(256, 2)
void gemm_WA(const __half* __restrict__ W, const __half* __restrict__ Bm,
             const float* __restrict__ bias, const float* __restrict__ res,
             float* __restrict__ out)
{
    extern __shared__ uint32_t sm[];
    const int K = 512, N = 1024;

    int b = blockIdx.z;
    const __half* Bp = Bm + (size_t)b * 1024 * 512;
    float* op = out + (size_t)b * 512 * 1024;
    const float* rp = res + (size_t)b * 512 * 1024;

    int tid = threadIdx.x, w = tid >> 5, lane = tid & 31;
    int g = lane >> 2, tg = lane & 3;
    int warp_m = w >> 2, warp_n = w & 3;
    int m0 = blockIdx.y * 128, n0 = blockIdx.x * 128;
    uint32_t sb = sa32(sm);

    float acc[4][4][4];
#pragma unroll
    for (int i = 0; i < 4; i++)
#pragma unroll
        for (int j = 0; j < 4; j++)
#pragma unroll
            for (int c = 0; c < 4; c++) acc[i][j][c] = 0.f;

    auto stage = [&](int c, int buf) {
        int OA = buf * 9216, OB = OA + 4608;
        int k0 = c * 64;
#pragma unroll
        for (int it = 0; it < 4; it++) {
            int i = tid + it * 256;
            int row = i >> 3, seg = i & 7;
            cpa16(sb + (OA + row * 36 + seg * 4) * 4,
                  W + (size_t)(m0 + row) * K + k0 + seg * 8);
            cpa16(sb + (OB + row * 36 + seg * 4) * 4,
                  Bp + (size_t)(n0 + row) * K + k0 + seg * 8);
        }
    };

    stage(0, 0);
    cpa_commit();

    for (int c = 0; c < 8; c++) {
        cpa_wait0();
        __syncthreads();
        if (c + 1 < 8) { stage(c + 1, (c + 1) & 1); cpa_commit(); }
        int OA = (c & 1) * 9216, OB = OA + 4608;
#pragma unroll
        for (int ks = 0; ks < 4; ks++) {
            int kb = ks * 8;
            uint32_t af[4][4];
#pragma unroll
            for (int mt = 0; mt < 4; mt++) {
                int rb = warp_m * 64 + mt * 16;
                af[mt][0] = sm[OA + (rb+g  )*36 + kb + tg];
                af[mt][1] = sm[OA + (rb+g+8)*36 + kb + tg];
                af[mt][2] = sm[OA + (rb+g  )*36 + kb + tg + 4];
                af[mt][3] = sm[OA + (rb+g+8)*36 + kb + tg + 4];
            }
#pragma unroll
            for (int nt = 0; nt < 4; nt++) {
                int cb = warp_n * 32 + nt * 8 + g;
                uint32_t b0 = sm[OB + cb*36 + kb + tg];
                uint32_t b1 = sm[OB + cb*36 + kb + tg + 4];
#pragma unroll
                for (int mt = 0; mt < 4; mt++)
                    mma_f16(acc[mt][nt], af[mt], b0, b1);
            }
        }
        __syncthreads();
    }

#pragma unroll
    for (int mt = 0; mt < 4; mt++) {
#pragma unroll
        for (int rr = 0; rr < 2; rr++) {
            int m = m0 + warp_m * 64 + mt * 16 + rr * 8 + g;
            float bi = bias[m];
#pragma unroll
            for (int nt = 0; nt < 4; nt++) {
#pragma unroll
                for (int ci = 0; ci < 2; ci++) {
                    int n = n0 + warp_n * 32 + nt * 8 + 2 * tg + ci;
                    op[(size_t)m * N + n] = acc[mt][nt][rr * 2 + ci] + bi
                                          + rp[(size_t)m * N + n];
                }
            }
        }
    }
}

// ---------------------------------------------------------------------------
extern "C" void kernel_launch(void* const* d_in, const int* in_sizes, int n_in,
                              void* d_out, int out_size)
{
    const float* x     = (const float*)d_in[0];
    const float* c     = (const float*)d_in[1];
    const float* gamma = (const float*)d_in[2];
    const float* beta  = (const float*)d_in[3];
    const float* w_qkv = (const float*)d_in[4];
    const float* b_qkv = (const float*)d_in[5];
    const float* w_c   = (const float*)d_in[6];
    const float* b_c   = (const float*)d_in[7];
    const float* w_p   = (const float*)d_in[8];
    const float* b_p   = (const float*)d_in[9];
    float* out = (float*)d_out;

    __half *xnT, *qkvT, *cT, *ckvT, *vT, *aT, *wq, *wc, *wp;
    cudaGetSymbolAddress((void**)&xnT,  g_xnT);
    cudaGetSymbolAddress((void**)&qkvT, g_qkvT);
    cudaGetSymbolAddress((void**)&cT,   g_cT);
    cudaGetSymbolAddress((void**)&ckvT, g_ckvT);
    cudaGetSymbolAddress((void**)&vT,   g_vT);
    cudaGetSymbolAddress((void**)&aT,   g_aT);
    cudaGetSymbolAddress((void**)&wq,   g_wq);
    cudaGetSymbolAddress((void**)&wc,   g_wc);
    cudaGetSymbolAddress((void**)&wp,   g_wp);

    static bool attr_done = false;
    if (!attr_done) {
        cudaFuncSetAttribute(groupnorm_kernel, cudaFuncAttributeMaxDynamicSharedMemorySize, 65536);
        cudaFuncSetAttribute(gemm_qkv_ckv, cudaFuncAttributeMaxDynamicSharedMemorySize, 73728);
        cudaFuncSetAttribute(gemm_WA, cudaFuncAttributeMaxDynamicSharedMemorySize, 73728);
        cudaFuncSetAttribute(attn_kernel, cudaFuncAttributeMaxDynamicSharedMemorySize, 55296);
        attr_done = true;
    }

    groupnorm_kernel<<<512, 256, 65536>>>(x, gamma, beta, xnT);
    convW_all<<<7168, 256>>>(w_qkv, wq, 1536 * 512,
                             w_c, wc, 1024 * 768,
                             w_p, wp, 512 * 512);
    prep_c_kernel<<<dim3(3, 24, 16), 256>>>(c, cT);

    // fused qkv (y<8) + ckv (y==8); epilogues also produce vT
    gemm_qkv_ckv<<<dim3(12, 9, 16), 256, 73728>>>(xnT, wq, b_qkv, cT, wc, b_c,
                                                  qkvT, ckvT, vT);

    attn_kernel<<<dim3(8, 8, 16), 256, 55296>>>(qkvT, ckvT, vT, aT);

    gemm_WA<<<dim3(8, 4, 16), 256, 73728>>>(wp, aT, b_p, x, out);
}

// round 11
// speedup vs baseline: 7.7216x; 1.0549x over previous
#include <cuda_runtime.h>
#include <cuda_fp16.h>
#include <cstdint>

// B=16, C=512, T=1024, L=77, S=1101(pad->1152), HEADS=8, D=64, GROUPS=32, CROSS=768

__device__ __half g_xnT [16 * 1024 * 512];     // [b][t][512]
__device__ __half g_qkvT[16 * 1024 * 1536];    // [b][t][1536]
__device__ __half g_cT  [16 * 77 * 768];       // [b][l][768]
__device__ __half g_ckvT[16 * 77 * 1024];      // [b][l][1024]
__device__ __half g_vT  [128 * 64 * 1152];     // [bh][d][s]  (BSS zero => pad rows 0)
__device__ __half g_aT  [16 * 1024 * 512];     // [b][t][512]
__device__ __half g_wq[1536 * 512];
__device__ __half g_wc[1024 * 768];
__device__ __half g_wp[512 * 512];

#define DINL __device__ __forceinline__

DINL void mma_f16(float* c, const uint32_t* a, uint32_t b0, uint32_t b1) {
    asm volatile(
        "mma.sync.aligned.m16n8k16.row.col.f32.f16.f16.f32 "
        "{%0,%1,%2,%3},{%4,%5,%6,%7},{%8,%9},{%0,%1,%2,%3};"
        : "+f"(c[0]), "+f"(c[1]), "+f"(c[2]), "+f"(c[3])
        : "r"(a[0]), "r"(a[1]), "r"(a[2]), "r"(a[3]), "r"(b0), "r"(b1));
}
DINL void ldsm4(uint32_t* r, uint32_t addr) {
    asm volatile(
        "ldmatrix.sync.aligned.m8n8.x4.shared.b16 {%0,%1,%2,%3}, [%4];"
        : "=r"(r[0]), "=r"(r[1]), "=r"(r[2]), "=r"(r[3]) : "r"(addr));
}
DINL uint32_t pack_h2(float a, float b) {
    __half2 h = __floats2half2_rn(a, b);
    return *(uint32_t*)&h;
}
DINL uint32_t ex2_h2(float a, float b) {
    uint32_t in = pack_h2(a, b), out;
    asm("ex2.approx.f16x2 %0, %1;" : "=r"(out) : "r"(in));
    return out;
}
DINL uint32_t sa32(const void* p) {
    uint32_t a;
    asm("{\n\t.reg .u64 t;\n\tcvta.to.shared.u64 t, %1;\n\tcvt.u32.u64 %0, t;\n\t}"
        : "=r"(a) : "l"(p));
    return a;
}
DINL void cpa16(uint32_t dst, const void* src) {
    asm volatile("cp.async.cg.shared.global [%0], [%1], 16;" :: "r"(dst), "l"(src));
}
DINL void cpa16z(uint32_t dst, const void* src, int sz) {
    asm volatile("cp.async.cg.shared.global [%0], [%1], 16, %2;"
                 :: "r"(dst), "l"(src), "r"(sz));
}
DINL void cpa_commit() { asm volatile("cp.async.commit_group;" ::: "memory"); }
DINL void cpa_wait0()  { asm volatile("cp.async.wait_group 0;" ::: "memory"); }

// ---------------------------------------------------------------------------
// GroupNorm(32), one global read; normalize + transpose + fp16 from smem.
// ---------------------------------------------------------------------------
__global__ __launch_bounds__(256)
void groupnorm_kernel(const float* __restrict__ x,
                      const float* __restrict__ gamma,
                      const float* __restrict__ beta,
                      __half* __restrict__ xnT)
{
    extern __shared__ float xs[];   // [16][1024]
    int b = blockIdx.x >> 5;
    int g = blockIdx.x & 31;
    const float* xp = x + ((size_t)b * 512 + (size_t)g * 16) * 1024;

    float s = 0.f, s2 = 0.f;
    for (int i = threadIdx.x; i < 16384; i += 256) {
        float v = xp[i];
        xs[i] = v;
        s += v; s2 += v * v;
    }
#pragma unroll
    for (int o = 16; o > 0; o >>= 1) {
        s  += __shfl_xor_sync(0xffffffffu, s, o);
        s2 += __shfl_xor_sync(0xffffffffu, s2, o);
    }
    __shared__ float ss[8], ss2[8];
    __shared__ float smean, sinv;
    int w = threadIdx.x >> 5;
    if ((threadIdx.x & 31) == 0) { ss[w] = s; ss2[w] = s2; }
    __syncthreads();
    if (threadIdx.x == 0) {
        float S = 0.f, S2 = 0.f;
#pragma unroll
        for (int i = 0; i < 8; i++) { S += ss[i]; S2 += ss2[i]; }
        float mean = S * (1.f / 16384.f);
        float var  = S2 * (1.f / 16384.f) - mean * mean;
        smean = mean;
        sinv  = rsqrtf(var + 1e-5f);
    }
    __syncthreads();
    float mean = smean, inv = sinv;

    float gm[16], bt[16];
#pragma unroll
    for (int ch = 0; ch < 16; ch++) {
        gm[ch] = gamma[g * 16 + ch] * inv;
        bt[ch] = beta[g * 16 + ch] - mean * gm[ch];
    }
#pragma unroll
    for (int seg = 0; seg < 4; seg++) {
        int t = seg * 256 + threadIdx.x;
        uint32_t wv[8];
#pragma unroll
        for (int c = 0; c < 8; c++) {
            float v0 = xs[(2 * c)     * 1024 + t] * gm[2 * c]     + bt[2 * c];
            float v1 = xs[(2 * c + 1) * 1024 + t] * gm[2 * c + 1] + bt[2 * c + 1];
            wv[c] = pack_h2(v0, v1);
        }
        __half* dst = xnT + ((size_t)b * 1024 + t) * 512 + g * 16;
        *(uint4*)dst = *(uint4*)&wv[0];
        *(uint4*)(dst + 8) = *(uint4*)&wv[4];
    }
}

// ---------------------------------------------------------------------------
__global__ __launch_bounds__(256)
void convW_all(const float* __restrict__ w0, __half* __restrict__ h0, int n0,
               const float* __restrict__ w1, __half* __restrict__ h1, int n1,
               const float* __restrict__ w2, __half* __restrict__ h2, int n2)
{
    int i = blockIdx.x * 256 + threadIdx.x;
    if (i < n0) { h0[i] = __float2half_rn(w0[i]); return; }
    i -= n0;
    if (i < n1) { h1[i] = __float2half_rn(w1[i]); return; }
    i -= n1;
    if (i < n2) { h2[i] = __float2half_rn(w2[i]); }
}

// c [b][768][77] fp32 -> cT [b][77][768] fp16
__global__ __launch_bounds__(256)
void prep_c_kernel(const float* __restrict__ c, __half* __restrict__ cT)
{
    __shared__ float tile[32][33];
    int t0 = blockIdx.x * 32, cb = blockIdx.y * 32, b = blockIdx.z;
    const float* ip = c + (size_t)b * 768 * 77;
    int tx = threadIdx.x & 31, ty = threadIdx.x >> 5;
#pragma unroll
    for (int i = 0; i < 4; i++) {
        int cr = ty + i * 8;
        tile[cr][tx] = (t0 + tx < 77) ? ip[(size_t)(cb + cr) * 77 + t0 + tx] : 0.f;
    }
    __syncthreads();
#pragma unroll
    for (int i = 0; i < 4; i++) {
        int tr = ty + i * 8;
        if (t0 + tr < 77)
            cT[(size_t)b * 77 * 768 + (size_t)(t0 + tr) * 768 + cb + tx] =
                __float2half_rn(tile[tx][tr]);
    }
}

// ---------------------------------------------------------------------------
// fused qkv + ckv GEMM, ldmatrix fragment loads.
// ---------------------------------------------------------------------------
DINL void gemm_at_body(const __half* __restrict__ A, const __half* __restrict__ W,
                       const float* __restrict__ bias, __half* __restrict__ oh,
                       __half* __restrict__ voutB,
                       int Mrows, int K, int ldo, int m0, int n0,
                       int vlo, int sOff, uint32_t sb, int tid)
{
    int w = tid >> 5, lane = tid & 31;
    int g = lane >> 2, tg = lane & 3;
    int warp_m = w >> 2, warp_n = w & 3;
    // ldmatrix lane constants
    int lr  = (lane & 7) + ((lane >> 3) & 1) * 8;   // A row in 16
    int lk  = (lane >> 4) * 4;                      // A k-word offset
    int bnt = lane >> 4;                            // B nt within pair
    int bko = ((lane >> 3) & 1) * 4;                // B k-word offset
    int br  = lane & 7;                             // B row in 8

    float acc[4][4][4];
#pragma unroll
    for (int i = 0; i < 4; i++)
#pragma unroll
        for (int j = 0; j < 4; j++)
#pragma unroll
            for (int c = 0; c < 4; c++) acc[i][j][c] = 0.f;

    int nk = K >> 6;

    for (int c = 0; c <= nk; c++) {
        if (c < nk) {
            int OA = (c & 1) * 9216, OB = OA + 4608;
            int k0 = c * 64;
#pragma unroll
            for (int it = 0; it < 4; it++) {
                int i = tid + it * 256;
                int row = i >> 3, seg = i & 7;
                int ar = (m0 + row < Mrows) ? (m0 + row) : 0;
                int sz = (m0 + row < Mrows) ? 16 : 0;
                cpa16z(sb + (OA + row * 36 + seg * 4) * 4,
                       A + (size_t)ar * K + k0 + seg * 8, sz);
                cpa16(sb + (OB + row * 36 + seg * 4) * 4,
                      W + (size_t)(n0 + row) * K + k0 + seg * 8);
            }
            cpa_commit();
        }
        if (c == 0) continue;
        int cc = c - 1;
        if (c < nk)
            asm volatile("cp.async.wait_group 1;" ::: "memory");
        else
            cpa_wait0();
        __syncthreads();
        int OA = (cc & 1) * 9216, OB = OA + 4608;
        uint32_t abase = sb + (OA + (warp_m * 64 + lr) * 36 + lk) * 4;
        uint32_t bbase = sb + (OB + (warp_n * 32 + bnt * 8 + br) * 36 + bko) * 4;
#pragma unroll
        for (int ks = 0; ks < 4; ks++) {
            int kb = ks * 8;
            uint32_t af[4][4];
#pragma unroll
            for (int mt = 0; mt < 4; mt++)
                ldsm4(af[mt], abase + (mt * 16 * 36 + kb) * 4);
            uint32_t bf[2][4];
#pragma unroll
            for (int p = 0; p < 2; p++)
                ldsm4(bf[p], bbase + (p * 16 * 36 + kb) * 4);
#pragma unroll
            for (int nt = 0; nt < 4; nt++) {
                uint32_t b0 = bf[nt >> 1][(nt & 1) * 2];
                uint32_t b1 = bf[nt >> 1][(nt & 1) * 2 + 1];
#pragma unroll
                for (int mt = 0; mt < 4; mt++)
                    mma_f16(acc[mt][nt], af[mt], b0, b1);
            }
        }
        __syncthreads();
    }

#pragma unroll
    for (int mt = 0; mt < 4; mt++) {
#pragma unroll
        for (int rr = 0; rr < 2; rr++) {
            int m = m0 + warp_m * 64 + mt * 16 + rr * 8 + g;
            if (m < Mrows) {
#pragma unroll
                for (int nt = 0; nt < 4; nt++) {
                    int n = n0 + warp_n * 32 + nt * 8 + 2 * tg;
                    float v0 = acc[mt][nt][rr * 2]     + bias[n];
                    float v1 = acc[mt][nt][rr * 2 + 1] + bias[n + 1];
                    __half2 hh = __floats2half2_rn(v0, v1);
                    *(uint32_t*)(oh + (size_t)m * ldo + n) = *(uint32_t*)&hh;
                    int d0 = n - vlo;
                    if (d0 >= 0) {
                        voutB[((size_t)((d0 >> 6) * 64) + (d0 & 63)) * 1152 + sOff + m] = hh.x;
                        int d1 = d0 + 1;
                        voutB[((size_t)((d1 >> 6) * 64) + (d1 & 63)) * 1152 + sOff + m] = hh.y;
                    }
                }
            }
        }
    }
}

__global__ __launch_bounds__(256, 2)
void gemm_qkv_ckv(const __half* __restrict__ xnT, const __half* __restrict__ wq,
                  const float* __restrict__ b_qkv,
                  const __half* __restrict__ cT, const __half* __restrict__ wc,
                  const float* __restrict__ b_c,
                  __half* __restrict__ qkvT, __half* __restrict__ ckvT,
                  __half* __restrict__ vT)
{
    extern __shared__ uint32_t sm[];
    int b = blockIdx.z;
    uint32_t sb = sa32(sm);
    int tid = threadIdx.x;
    __half* voutB = vT + (size_t)b * 8 * 64 * 1152;

    if (blockIdx.y < 8) {
        gemm_at_body(xnT + (size_t)b * 1024 * 512, wq, b_qkv,
                     qkvT + (size_t)b * 1024 * 1536, voutB,
                     1024, 512, 1536, blockIdx.y * 128, blockIdx.x * 128,
                     1024, 0, sb, tid);
    } else {
        if (blockIdx.x >= 8) return;
        gemm_at_body(cT + (size_t)b * 77 * 768, wc, b_c,
                     ckvT + (size_t)b * 77 * 1024, voutB,
                     77, 768, 1024, 0, blockIdx.x * 128,
                     512, 1024, sb, tid);
    }
}

// ---------------------------------------------------------------------------
// Flash attention: 64-key tiles, warp = 16q x 64k, P in regs, ex2.f16x2,
// ones-column row sums, ldmatrix fragment loads, 2 CTAs/SM.
// ---------------------------------------------------------------------------
__global__ __launch_bounds__(256, 2)
void attn_kernel(const __half* __restrict__ qkvT, const __half* __restrict__ ckvT,
                 const __half* __restrict__ vT, __half* __restrict__ aT)
{
    extern __shared__ uint32_t smw[];
    const int OQ = 0;
    const float L2E = 1.4426950408889634f;
    const uint32_t ONES2 = 0x3C003C00u;

    int t0 = blockIdx.x * 128;
    int h  = blockIdx.y;
    int b  = blockIdx.z;
    int bh = b * 8 + h;
    int tid = threadIdx.x;
    int w = tid >> 5, lane = tid & 31;
    int g = lane >> 2, tg = lane & 3;
    uint32_t sb = sa32(smw);
    // ldmatrix lane constants
    int lr  = (lane & 7) + ((lane >> 3) & 1) * 8;
    int lk  = (lane >> 4) * 4;
    int bnt = lane >> 4;
    int bko = ((lane >> 3) & 1) * 4;
    int br  = lane & 7;

    auto stage_kv = [&](int kt, int buf) {
        int OKb = 4608 + buf * 4608;
        int OVb = OKb + 2304;
        if (kt < 16) {
            const __half* kp = qkvT + ((size_t)b * 1024 + kt * 64) * 1536 + 512 + h * 64;
#pragma unroll
            for (int it = 0; it < 2; it++) {
                int i = tid + it * 256, s = i >> 3, seg = i & 7;
                cpa16(sb + (OKb + s * 36 + seg * 4) * 4, kp + (size_t)s * 1536 + seg * 8);
            }
        } else {
            const __half* kp = ckvT + (size_t)b * 77 * 1024 + h * 64;
            int base = (kt - 16) * 64;
#pragma unroll
            for (int it = 0; it < 2; it++) {
                int i = tid + it * 256, s = i >> 3, seg = i & 7;
                int sl = base + s;
                int sr = (sl < 77) ? sl : 0;
                int sz = (sl < 77) ? 16 : 0;
                cpa16z(sb + (OKb + s * 36 + seg * 4) * 4,
                       kp + (size_t)sr * 1024 + seg * 8, sz);
            }
        }
        const __half* vp = vT + (size_t)bh * 64 * 1152 + kt * 64;
#pragma unroll
        for (int it = 0; it < 2; it++) {
            int i = tid + it * 256, d = i >> 3, seg = i & 7;
            cpa16(sb + (OVb + d * 36 + seg * 4) * 4, vp + (size_t)d * 1152 + seg * 8);
        }
    };

    {
        const __half* qp = qkvT + ((size_t)b * 1024 + t0) * 1536 + h * 64;
#pragma unroll
        for (int it = 0; it < 4; it++) {
            int i = tid + it * 256, row = i >> 3, seg = i & 7;
            cpa16(sb + (OQ + row * 36 + seg * 4) * 4, qp + (size_t)row * 1536 + seg * 8);
        }
    }
    stage_kv(0, 0);
    cpa_commit();

    float oacc[8][4];
#pragma unroll
    for (int nt = 0; nt < 8; nt++)
#pragma unroll
        for (int c = 0; c < 4; c++) oacc[nt][c] = 0.f;
    float lacc[4] = {0.f, 0.f, 0.f, 0.f};
    float m_run[2] = {-1e30f, -1e30f};
    int rb = w * 16;
    uint32_t qbase = sb + (OQ + (rb + lr) * 36 + lk) * 4;

    for (int kt = 0; kt < 18; kt++) {
        cpa_wait0();
        __syncthreads();
        if (kt < 17) { stage_kv(kt + 1, (kt + 1) & 1); cpa_commit(); }
        int OKb = 4608 + (kt & 1) * 4608;
        int OVb = OKb + 2304;
        uint32_t kbase = sb + (OKb + (bnt * 8 + br) * 36 + bko) * 4;
        uint32_t vbase = sb + (OVb + (bnt * 8 + br) * 36 + bko) * 4;

        float sacc[8][4];
#pragma unroll
        for (int nt = 0; nt < 8; nt++)
#pragma unroll
            for (int c = 0; c < 4; c++) sacc[nt][c] = 0.f;

#pragma unroll
        for (int ks = 0; ks < 4; ks++) {
            int kb = ks * 8;
            uint32_t af[4];
            ldsm4(af, qbase + kb * 4);
            uint32_t bf[4][4];
#pragma unroll
            for (int p = 0; p < 4; p++)
                ldsm4(bf[p], kbase + (p * 16 * 36 + kb) * 4);
#pragma unroll
            for (int nt = 0; nt < 8; nt++) {
                uint32_t b0 = bf[nt >> 1][(nt & 1) * 2];
                uint32_t b1 = bf[nt >> 1][(nt & 1) * 2 + 1];
                mma_f16(sacc[nt], af, b0, b1);
            }
        }

#pragma unroll
        for (int nt = 0; nt < 8; nt++)
#pragma unroll
            for (int c = 0; c < 4; c++) {
                float v = sacc[nt][c] * 0.125f;
                if (kt == 17 && (nt * 8 + 2 * tg + (c & 1)) >= 13) v = -1e30f;
                sacc[nt][c] = v;
            }

        float mx[2];
#pragma unroll
        for (int rr = 0; rr < 2; rr++) {
            float m = fmaxf(sacc[0][rr*2], sacc[0][rr*2+1]);
#pragma unroll
            for (int nt = 1; nt < 8; nt++) {
                m = fmaxf(m, sacc[nt][rr*2]);
                m = fmaxf(m, sacc[nt][rr*2+1]);
            }
            m = fmaxf(m, __shfl_xor_sync(0xffffffffu, m, 1));
            m = fmaxf(m, __shfl_xor_sync(0xffffffffu, m, 2));
            mx[rr] = m;
        }
        float nm[2], corr[2], nml[2];
#pragma unroll
        for (int rr = 0; rr < 2; rr++) {
            nm[rr] = fmaxf(m_run[rr], mx[rr]);
            corr[rr] = __expf(m_run[rr] - nm[rr]);
            m_run[rr] = nm[rr];
            nml[rr] = nm[rr] * L2E;
        }
#pragma unroll
        for (int nt = 0; nt < 8; nt++) {
            oacc[nt][0] *= corr[0];
            oacc[nt][1] *= corr[0];
            oacc[nt][2] *= corr[1];
            oacc[nt][3] *= corr[1];
        }
        lacc[0] *= corr[0]; lacc[1] *= corr[0];
        lacc[2] *= corr[1]; lacc[3] *= corr[1];

#pragma unroll
        for (int j = 0; j < 4; j++) {
            uint32_t pa[4];
            pa[0] = ex2_h2(fmaf(sacc[2*j  ][0], L2E, -nml[0]),
                           fmaf(sacc[2*j  ][1], L2E, -nml[0]));
            pa[1] = ex2_h2(fmaf(sacc[2*j  ][2], L2E, -nml[1]),
                           fmaf(sacc[2*j  ][3], L2E, -nml[1]));
            pa[2] = ex2_h2(fmaf(sacc[2*j+1][0], L2E, -nml[0]),
                           fmaf(sacc[2*j+1][1], L2E, -nml[0]));
            pa[3] = ex2_h2(fmaf(sacc[2*j+1][2], L2E, -nml[1]),
                           fmaf(sacc[2*j+1][3], L2E, -nml[1]));
            uint32_t vf[4][4];
#pragma unroll
            for (int p = 0; p < 4; p++)
                ldsm4(vf[p], vbase + (p * 16 * 36 + j * 8) * 4);
#pragma unroll
            for (int nt = 0; nt < 8; nt++) {
                uint32_t b0 = vf[nt >> 1][(nt & 1) * 2];
                uint32_t b1 = vf[nt >> 1][(nt & 1) * 2 + 1];
                mma_f16(oacc[nt], pa, b0, b1);
            }
            mma_f16(lacc, pa, ONES2, ONES2);
        }
    }

    float inv[2] = {1.f / lacc[0], 1.f / lacc[2]};
#pragma unroll
    for (int nt = 0; nt < 8; nt++)
#pragma unroll
        for (int rr = 0; rr < 2; rr++) {
            int t = t0 + rb + rr * 8 + g;
            int d = nt * 8 + 2 * tg;
            float v0 = oacc[nt][rr*2]     * inv[rr];
            float v1 = oacc[nt][rr*2 + 1] * inv[rr];
            *(uint32_t*)(aT + ((size_t)b * 1024 + t) * 512 + h * 64 + d) = pack_h2(v0, v1);
        }
}

// ---------------------------------------------------------------------------
// proj: out[b][m=ch][n=t] = sum_k W[ch][k]*aT[b][t][k] + bias + x, ldmatrix.
// ---------------------------------------------------------------------------
__global__ __launch_bounds__(256, 2)
void gemm_WA(const __half* __restrict__ W, const __half* __restrict__ Bm,
             const float* __restrict__ bias, const float* __restrict__ res,
             float* __restrict__ out)
{
    extern __shared__ uint32_t sm[];
    const int K = 512, N = 1024;

    int b = blockIdx.z;
    const __half* Bp = Bm + (size_t)b * 1024 * 512;
    float* op = out + (size_t)b * 512 * 1024;
    const float* rp = res + (size_t)b * 512 * 1024;

    int tid = threadIdx.x, w = tid >> 5, lane = tid & 31;
    int g = lane >> 2, tg = lane & 3;
    int warp_m = w >> 2, warp_n = w & 3;
    int m0 = blockIdx.y * 128, n0 = blockIdx.x * 128;
    uint32_t sb = sa32(sm);
    int lr  = (lane & 7) + ((lane >> 3) & 1) * 8;
    int lk  = (lane >> 4) * 4;
    int bnt = lane >> 4;
    int bko = ((lane >> 3) & 1) * 4;
    int br  = lane & 7;

    float acc[4][4][4];
#pragma unroll
    for (int i = 0; i < 4; i++)
#pragma unroll
        for (int j = 0; j < 4; j++)
#pragma unroll
            for (int c = 0; c < 4; c++) acc[i][j][c] = 0.f;

    auto stage = [&](int c, int buf) {
        int OA = buf * 9216, OB = OA + 4608;
        int k0 = c * 64;
#pragma unroll
        for (int it = 0; it < 4; it++) {
            int i = tid + it * 256;
            int row = i >> 3, seg = i & 7;
            cpa16(sb + (OA + row * 36 + seg * 4) * 4,
                  W + (size_t)(m0 + row) * K + k0 + seg * 8);
            cpa16(sb + (OB + row * 36 + seg * 4) * 4,
                  Bp + (size_t)(n0 + row) * K + k0 + seg * 8);
        }
    };

    stage(0, 0);
    cpa_commit();

    for (int c = 0; c < 8; c++) {
        cpa_wait0();
        __syncthreads();
        if (c + 1 < 8) { stage(c + 1, (c + 1) & 1); cpa_commit(); }
        int OA = (c & 1) * 9216, OB = OA + 4608;
        uint32_t abase = sb + (OA + (warp_m * 64 + lr) * 36 + lk) * 4;
        uint32_t bbase = sb + (OB + (warp_n * 32 + bnt * 8 + br) * 36 + bko) * 4;
#pragma unroll
        for (int ks = 0; ks < 4; ks++) {
            int kb = ks * 8;
            uint32_t af[4][4];
#pragma unroll
            for (int mt = 0; mt < 4; mt++)
                ldsm4(af[mt], abase + (mt * 16 * 36 + kb) * 4);
            uint32_t bf[2][4];
#pragma unroll
            for (int p = 0; p < 2; p++)
                ldsm4(bf[p], bbase + (p * 16 * 36 + kb) * 4);
#pragma unroll
            for (int nt = 0; nt < 4; nt++) {
                uint32_t b0 = bf[nt >> 1][(nt & 1) * 2];
                uint32_t b1 = bf[nt >> 1][(nt & 1) * 2 + 1];
#pragma unroll
                for (int mt = 0; mt < 4; mt++)
                    mma_f16(acc[mt][nt], af[mt], b0, b1);
            }
        }
        __syncthreads();
    }

#pragma unroll
    for (int mt = 0; mt < 4; mt++) {
#pragma unroll
        for (int rr = 0; rr < 2; rr++) {
            int m = m0 + warp_m * 64 + mt * 16 + rr * 8 + g;
            float bi = bias[m];
#pragma unroll
            for (int nt = 0; nt < 4; nt++) {
#pragma unroll
                for (int ci = 0; ci < 2; ci++) {
                    int n = n0 + warp_n * 32 + nt * 8 + 2 * tg + ci;
                    op[(size_t)m * N + n] = acc[mt][nt][rr * 2 + ci] + bi
                                          + rp[(size_t)m * N + n];
                }
            }
        }
    }
}

// ---------------------------------------------------------------------------
extern "C" void kernel_launch(void* const* d_in, const int* in_sizes, int n_in,
                              void* d_out, int out_size)
{
    const float* x     = (const float*)d_in[0];
    const float* c     = (const float*)d_in[1];
    const float* gamma = (const float*)d_in[2];
    const float* beta  = (const float*)d_in[3];
    const float* w_qkv = (const float*)d_in[4];
    const float* b_qkv = (const float*)d_in[5];
    const float* w_c   = (const float*)d_in[6];
    const float* b_c   = (const float*)d_in[7];
    const float* w_p   = (const float*)d_in[8];
    const float* b_p   = (const float*)d_in[9];
    float* out = (float*)d_out;

    __half *xnT, *qkvT, *cT, *ckvT, *vT, *aT, *wq, *wc, *wp;
    cudaGetSymbolAddress((void**)&xnT,  g_xnT);
    cudaGetSymbolAddress((void**)&qkvT, g_qkvT);
    cudaGetSymbolAddress((void**)&cT,   g_cT);
    cudaGetSymbolAddress((void**)&ckvT, g_ckvT);
    cudaGetSymbolAddress((void**)&vT,   g_vT);
    cudaGetSymbolAddress((void**)&aT,   g_aT);
    cudaGetSymbolAddress((void**)&wq,   g_wq);
    cudaGetSymbolAddress((void**)&wc,   g_wc);
    cudaGetSymbolAddress((void**)&wp,   g_wp);

    static bool attr_done = false;
    if (!attr_done) {
        cudaFuncSetAttribute(groupnorm_kernel, cudaFuncAttributeMaxDynamicSharedMemorySize, 65536);
        cudaFuncSetAttribute(gemm_qkv_ckv, cudaFuncAttributeMaxDynamicSharedMemorySize, 73728);
        cudaFuncSetAttribute(gemm_WA, cudaFuncAttributeMaxDynamicSharedMemorySize, 73728);
        cudaFuncSetAttribute(attn_kernel, cudaFuncAttributeMaxDynamicSharedMemorySize, 55296);
        attr_done = true;
    }

    groupnorm_kernel<<<512, 256, 65536>>>(x, gamma, beta, xnT);
    convW_all<<<7168, 256>>>(w_qkv, wq, 1536 * 512,
                             w_c, wc, 1024 * 768,
                             w_p, wp, 512 * 512);
    prep_c_kernel<<<dim3(3, 24, 16), 256>>>(c, cT);

    gemm_qkv_ckv<<<dim3(12, 9, 16), 256, 73728>>>(xnT, wq, b_qkv, cT, wc, b_c,
                                                  qkvT, ckvT, vT);

    attn_kernel<<<dim3(8, 8, 16), 256, 55296>>>(qkvT, ckvT, vT, aT);

    gemm_WA<<<dim3(8, 4, 16), 256, 73728>>>(wp, aT, b_p, x, out);
}

// round 12
// speedup vs baseline: 7.9682x; 1.0319x over previous
#include <cuda_runtime.h>
#include <cuda_fp16.h>
#include <cstdint>

// B=16, C=512, T=1024, L=77, S=1101(pad->1152), HEADS=8, D=64, GROUPS=32, CROSS=768

__device__ __half g_xnT [16 * 1024 * 512];     // [b][t][512]
__device__ __half g_qkvT[16 * 1024 * 1536];    // [b][t][1536]
__device__ __half g_cT  [16 * 77 * 768];       // [b][l][768]
__device__ __half g_ckvT[16 * 77 * 1024];      // [b][l][1024]
__device__ __half g_vT  [128 * 1152 * 64];     // [bh][s][d]  (BSS zero => pad rows 0)
__device__ __half g_aT  [16 * 1024 * 512];     // [b][t][512]
__device__ __half g_wq[1536 * 512];
__device__ __half g_wc[1024 * 768];
__device__ __half g_wp[512 * 512];

#define DINL __device__ __forceinline__

DINL void mma_f16(float* c, const uint32_t* a, uint32_t b0, uint32_t b1) {
    asm volatile(
        "mma.sync.aligned.m16n8k16.row.col.f32.f16.f16.f32 "
        "{%0,%1,%2,%3},{%4,%5,%6,%7},{%8,%9},{%0,%1,%2,%3};"
        : "+f"(c[0]), "+f"(c[1]), "+f"(c[2]), "+f"(c[3])
        : "r"(a[0]), "r"(a[1]), "r"(a[2]), "r"(a[3]), "r"(b0), "r"(b1));
}
DINL void ldsm4(uint32_t* r, uint32_t addr) {
    asm volatile(
        "ldmatrix.sync.aligned.m8n8.x4.shared.b16 {%0,%1,%2,%3}, [%4];"
        : "=r"(r[0]), "=r"(r[1]), "=r"(r[2]), "=r"(r[3]) : "r"(addr));
}
DINL void ldsm4t(uint32_t* r, uint32_t addr) {
    asm volatile(
        "ldmatrix.sync.aligned.m8n8.x4.trans.shared.b16 {%0,%1,%2,%3}, [%4];"
        : "=r"(r[0]), "=r"(r[1]), "=r"(r[2]), "=r"(r[3]) : "r"(addr));
}
DINL uint32_t pack_h2(float a, float b) {
    __half2 h = __floats2half2_rn(a, b);
    return *(uint32_t*)&h;
}
DINL uint32_t ex2_h2(float a, float b) {
    uint32_t in = pack_h2(a, b), out;
    asm("ex2.approx.f16x2 %0, %1;" : "=r"(out) : "r"(in));
    return out;
}
DINL uint32_t sa32(const void* p) {
    uint32_t a;
    asm("{\n\t.reg .u64 t;\n\tcvta.to.shared.u64 t, %1;\n\tcvt.u32.u64 %0, t;\n\t}"
        : "=r"(a) : "l"(p));
    return a;
}
DINL void cpa16(uint32_t dst, const void* src) {
    asm volatile("cp.async.cg.shared.global [%0], [%1], 16;" :: "r"(dst), "l"(src));
}
DINL void cpa16z(uint32_t dst, const void* src, int sz) {
    asm volatile("cp.async.cg.shared.global [%0], [%1], 16, %2;"
                 :: "r"(dst), "l"(src), "r"(sz));
}
DINL void cpa_commit() { asm volatile("cp.async.commit_group;" ::: "memory"); }
DINL void cpa_wait0()  { asm volatile("cp.async.wait_group 0;" ::: "memory"); }

// ---------------------------------------------------------------------------
// GroupNorm(32), one global read; normalize + transpose + fp16 from smem.
// ---------------------------------------------------------------------------
__global__ __launch_bounds__(256)
void groupnorm_kernel(const float* __restrict__ x,
                      const float* __restrict__ gamma,
                      const float* __restrict__ beta,
                      __half* __restrict__ xnT)
{
    extern __shared__ float xs[];   // [16][1024]
    int b = blockIdx.x >> 5;
    int g = blockIdx.x & 31;
    const float* xp = x + ((size_t)b * 512 + (size_t)g * 16) * 1024;

    float s = 0.f, s2 = 0.f;
    for (int i = threadIdx.x; i < 16384; i += 256) {
        float v = xp[i];
        xs[i] = v;
        s += v; s2 += v * v;
    }
#pragma unroll
    for (int o = 16; o > 0; o >>= 1) {
        s  += __shfl_xor_sync(0xffffffffu, s, o);
        s2 += __shfl_xor_sync(0xffffffffu, s2, o);
    }
    __shared__ float ss[8], ss2[8];
    __shared__ float smean, sinv;
    int w = threadIdx.x >> 5;
    if ((threadIdx.x & 31) == 0) { ss[w] = s; ss2[w] = s2; }
    __syncthreads();
    if (threadIdx.x == 0) {
        float S = 0.f, S2 = 0.f;
#pragma unroll
        for (int i = 0; i < 8; i++) { S += ss[i]; S2 += ss2[i]; }
        float mean = S * (1.f / 16384.f);
        float var  = S2 * (1.f / 16384.f) - mean * mean;
        smean = mean;
        sinv  = rsqrtf(var + 1e-5f);
    }
    __syncthreads();
    float mean = smean, inv = sinv;

    float gm[16], bt[16];
#pragma unroll
    for (int ch = 0; ch < 16; ch++) {
        gm[ch] = gamma[g * 16 + ch] * inv;
        bt[ch] = beta[g * 16 + ch] - mean * gm[ch];
    }
#pragma unroll
    for (int seg = 0; seg < 4; seg++) {
        int t = seg * 256 + threadIdx.x;
        uint32_t wv[8];
#pragma unroll
        for (int c = 0; c < 8; c++) {
            float v0 = xs[(2 * c)     * 1024 + t] * gm[2 * c]     + bt[2 * c];
            float v1 = xs[(2 * c + 1) * 1024 + t] * gm[2 * c + 1] + bt[2 * c + 1];
            wv[c] = pack_h2(v0, v1);
        }
        __half* dst = xnT + ((size_t)b * 1024 + t) * 512 + g * 16;
        *(uint4*)dst = *(uint4*)&wv[0];
        *(uint4*)(dst + 8) = *(uint4*)&wv[4];
    }
}

// ---------------------------------------------------------------------------
__global__ __launch_bounds__(256)
void convW_all(const float* __restrict__ w0, __half* __restrict__ h0, int n0,
               const float* __restrict__ w1, __half* __restrict__ h1, int n1,
               const float* __restrict__ w2, __half* __restrict__ h2, int n2)
{
    int i = blockIdx.x * 256 + threadIdx.x;
    if (i < n0) { h0[i] = __float2half_rn(w0[i]); return; }
    i -= n0;
    if (i < n1) { h1[i] = __float2half_rn(w1[i]); return; }
    i -= n1;
    if (i < n2) { h2[i] = __float2half_rn(w2[i]); }
}

// c [b][768][77] fp32 -> cT [b][77][768] fp16
__global__ __launch_bounds__(256)
void prep_c_kernel(const float* __restrict__ c, __half* __restrict__ cT)
{
    __shared__ float tile[32][33];
    int t0 = blockIdx.x * 32, cb = blockIdx.y * 32, b = blockIdx.z;
    const float* ip = c + (size_t)b * 768 * 77;
    int tx = threadIdx.x & 31, ty = threadIdx.x >> 5;
#pragma unroll
    for (int i = 0; i < 4; i++) {
        int cr = ty + i * 8;
        tile[cr][tx] = (t0 + tx < 77) ? ip[(size_t)(cb + cr) * 77 + t0 + tx] : 0.f;
    }
    __syncthreads();
#pragma unroll
    for (int i = 0; i < 4; i++) {
        int tr = ty + i * 8;
        if (t0 + tr < 77)
            cT[(size_t)b * 77 * 768 + (size_t)(t0 + tr) * 768 + cb + tx] =
                __float2half_rn(tile[tx][tr]);
    }
}

// ---------------------------------------------------------------------------
// fused qkv + ckv GEMM, ldmatrix fragment loads; V epilogue writes the
// s-major vT[bh][s][64] with coalesced half2 stores (no scatter).
// ---------------------------------------------------------------------------
DINL void gemm_at_body(const __half* __restrict__ A, const __half* __restrict__ W,
                       const float* __restrict__ bias, __half* __restrict__ oh,
                       __half* __restrict__ voutB,   // vT + b*8*1152*64
                       int Mrows, int K, int ldo, int m0, int n0,
                       int vlo, int sOff, uint32_t sb, int tid)
{
    int w = tid >> 5, lane = tid & 31;
    int g = lane >> 2, tg = lane & 3;
    int warp_m = w >> 2, warp_n = w & 3;
    int lr  = (lane & 7) + ((lane >> 3) & 1) * 8;
    int lk  = (lane >> 4) * 4;
    int bnt = lane >> 4;
    int bko = ((lane >> 3) & 1) * 4;
    int br  = lane & 7;

    float acc[4][4][4];
#pragma unroll
    for (int i = 0; i < 4; i++)
#pragma unroll
        for (int j = 0; j < 4; j++)
#pragma unroll
            for (int c = 0; c < 4; c++) acc[i][j][c] = 0.f;

    int nk = K >> 6;

    for (int c = 0; c <= nk; c++) {
        if (c < nk) {
            int OA = (c & 1) * 9216, OB = OA + 4608;
            int k0 = c * 64;
#pragma unroll
            for (int it = 0; it < 4; it++) {
                int i = tid + it * 256;
                int row = i >> 3, seg = i & 7;
                int ar = (m0 + row < Mrows) ? (m0 + row) : 0;
                int sz = (m0 + row < Mrows) ? 16 : 0;
                cpa16z(sb + (OA + row * 36 + seg * 4) * 4,
                       A + (size_t)ar * K + k0 + seg * 8, sz);
                cpa16(sb + (OB + row * 36 + seg * 4) * 4,
                      W + (size_t)(n0 + row) * K + k0 + seg * 8);
            }
            cpa_commit();
        }
        if (c == 0) continue;
        int cc = c - 1;
        if (c < nk)
            asm volatile("cp.async.wait_group 1;" ::: "memory");
        else
            cpa_wait0();
        __syncthreads();
        int OA = (cc & 1) * 9216, OB = OA + 4608;
        uint32_t abase = sb + (OA + (warp_m * 64 + lr) * 36 + lk) * 4;
        uint32_t bbase = sb + (OB + (warp_n * 32 + bnt * 8 + br) * 36 + bko) * 4;
#pragma unroll
        for (int ks = 0; ks < 4; ks++) {
            int kb = ks * 8;
            uint32_t af[4][4];
#pragma unroll
            for (int mt = 0; mt < 4; mt++)
                ldsm4(af[mt], abase + (mt * 16 * 36 + kb) * 4);
            uint32_t bf[2][4];
#pragma unroll
            for (int p = 0; p < 2; p++)
                ldsm4(bf[p], bbase + (p * 16 * 36 + kb) * 4);
#pragma unroll
            for (int nt = 0; nt < 4; nt++) {
                uint32_t b0 = bf[nt >> 1][(nt & 1) * 2];
                uint32_t b1 = bf[nt >> 1][(nt & 1) * 2 + 1];
#pragma unroll
                for (int mt = 0; mt < 4; mt++)
                    mma_f16(acc[mt][nt], af[mt], b0, b1);
            }
        }
        __syncthreads();
    }

#pragma unroll
    for (int mt = 0; mt < 4; mt++) {
#pragma unroll
        for (int rr = 0; rr < 2; rr++) {
            int m = m0 + warp_m * 64 + mt * 16 + rr * 8 + g;
            if (m < Mrows) {
#pragma unroll
                for (int nt = 0; nt < 4; nt++) {
                    int n = n0 + warp_n * 32 + nt * 8 + 2 * tg;
                    float v0 = acc[mt][nt][rr * 2]     + bias[n];
                    float v1 = acc[mt][nt][rr * 2 + 1] + bias[n + 1];
                    __half2 hh = __floats2half2_rn(v0, v1);
                    *(uint32_t*)(oh + (size_t)m * ldo + n) = *(uint32_t*)&hh;
                    int d0 = n - vlo;
                    if (d0 >= 0) {
                        // vT[bh][s][d]: coalesced half2 store
                        size_t o = ((size_t)(d0 >> 6) * 1152 + sOff + m) * 64 + (d0 & 63);
                        *(uint32_t*)(voutB + o) = *(uint32_t*)&hh;
                    }
                }
            }
        }
    }
}

__global__ __launch_bounds__(256, 2)
void gemm_qkv_ckv(const __half* __restrict__ xnT, const __half* __restrict__ wq,
                  const float* __restrict__ b_qkv,
                  const __half* __restrict__ cT, const __half* __restrict__ wc,
                  const float* __restrict__ b_c,
                  __half* __restrict__ qkvT, __half* __restrict__ ckvT,
                  __half* __restrict__ vT)
{
    extern __shared__ uint32_t sm[];
    int b = blockIdx.z;
    uint32_t sb = sa32(sm);
    int tid = threadIdx.x;
    __half* voutB = vT + (size_t)b * 8 * 1152 * 64;

    if (blockIdx.y < 8) {
        gemm_at_body(xnT + (size_t)b * 1024 * 512, wq, b_qkv,
                     qkvT + (size_t)b * 1024 * 1536, voutB,
                     1024, 512, 1536, blockIdx.y * 128, blockIdx.x * 128,
                     1024, 0, sb, tid);
    } else {
        if (blockIdx.x >= 8) return;
        gemm_at_body(cT + (size_t)b * 77 * 768, wc, b_c,
                     ckvT + (size_t)b * 77 * 1024, voutB,
                     77, 768, 1024, 0, blockIdx.x * 128,
                     512, 1024, sb, tid);
    }
}

// ---------------------------------------------------------------------------
// Flash attention: 64-key tiles, warp = 16q x 64k, P in regs, ex2.f16x2,
// ones-column row sums, ldmatrix (+ trans for V), 2 CTAs/SM.
// smem: Q[128][36] | {K[64][36], V[64][36]} x2
// ---------------------------------------------------------------------------
__global__ __launch_bounds__(256, 2)
void attn_kernel(const __half* __restrict__ qkvT, const __half* __restrict__ ckvT,
                 const __half* __restrict__ vT, __half* __restrict__ aT)
{
    extern __shared__ uint32_t smw[];
    const int OQ = 0;
    const float L2E = 1.4426950408889634f;
    const uint32_t ONES2 = 0x3C003C00u;

    int t0 = blockIdx.x * 128;
    int h  = blockIdx.y;
    int b  = blockIdx.z;
    int bh = b * 8 + h;
    int tid = threadIdx.x;
    int w = tid >> 5, lane = tid & 31;
    int g = lane >> 2, tg = lane & 3;
    uint32_t sb = sa32(smw);
    int lr  = (lane & 7) + ((lane >> 3) & 1) * 8;
    int lk  = (lane >> 4) * 4;
    int bnt = lane >> 4;
    int bko = ((lane >> 3) & 1) * 4;
    int br  = lane & 7;
    // trans-ldmatrix lane constants for V [s][d]: row = lane&15, d-off = (lane>>4)*8 halves
    int vr  = lane & 15;
    int vkw = (lane >> 4) * 4;

    auto stage_kv = [&](int kt, int buf) {
        int OKb = 4608 + buf * 4608;
        int OVb = OKb + 2304;
        if (kt < 16) {
            const __half* kp = qkvT + ((size_t)b * 1024 + kt * 64) * 1536 + 512 + h * 64;
#pragma unroll
            for (int it = 0; it < 2; it++) {
                int i = tid + it * 256, s = i >> 3, seg = i & 7;
                cpa16(sb + (OKb + s * 36 + seg * 4) * 4, kp + (size_t)s * 1536 + seg * 8);
            }
        } else {
            const __half* kp = ckvT + (size_t)b * 77 * 1024 + h * 64;
            int base = (kt - 16) * 64;
#pragma unroll
            for (int it = 0; it < 2; it++) {
                int i = tid + it * 256, s = i >> 3, seg = i & 7;
                int sl = base + s;
                int sr = (sl < 77) ? sl : 0;
                int sz = (sl < 77) ? 16 : 0;
                cpa16z(sb + (OKb + s * 36 + seg * 4) * 4,
                       kp + (size_t)sr * 1024 + seg * 8, sz);
            }
        }
        const __half* vp = vT + ((size_t)bh * 1152 + kt * 64) * 64;
#pragma unroll
        for (int it = 0; it < 2; it++) {
            int i = tid + it * 256, s = i >> 3, seg = i & 7;
            cpa16(sb + (OVb + s * 36 + seg * 4) * 4, vp + (size_t)s * 64 + seg * 8);
        }
    };

    {
        const __half* qp = qkvT + ((size_t)b * 1024 + t0) * 1536 + h * 64;
#pragma unroll
        for (int it = 0; it < 4; it++) {
            int i = tid + it * 256, row = i >> 3, seg = i & 7;
            cpa16(sb + (OQ + row * 36 + seg * 4) * 4, qp + (size_t)row * 1536 + seg * 8);
        }
    }
    stage_kv(0, 0);
    cpa_commit();

    float oacc[8][4];
#pragma unroll
    for (int nt = 0; nt < 8; nt++)
#pragma unroll
        for (int c = 0; c < 4; c++) oacc[nt][c] = 0.f;
    float lacc[4] = {0.f, 0.f, 0.f, 0.f};
    float m_run[2] = {-1e30f, -1e30f};
    int rb = w * 16;
    uint32_t qbase = sb + (OQ + (rb + lr) * 36 + lk) * 4;

    for (int kt = 0; kt < 18; kt++) {
        cpa_wait0();
        __syncthreads();
        if (kt < 17) { stage_kv(kt + 1, (kt + 1) & 1); cpa_commit(); }
        int OKb = 4608 + (kt & 1) * 4608;
        int OVb = OKb + 2304;
        uint32_t kbase = sb + (OKb + (bnt * 8 + br) * 36 + bko) * 4;
        uint32_t vbase = sb + (OVb + vr * 36 + vkw) * 4;

        float sacc[8][4];
#pragma unroll
        for (int nt = 0; nt < 8; nt++)
#pragma unroll
            for (int c = 0; c < 4; c++) sacc[nt][c] = 0.f;

#pragma unroll
        for (int ks = 0; ks < 4; ks++) {
            int kb = ks * 8;
            uint32_t af[4];
            ldsm4(af, qbase + kb * 4);
            uint32_t bf[4][4];
#pragma unroll
            for (int p = 0; p < 4; p++)
                ldsm4(bf[p], kbase + (p * 16 * 36 + kb) * 4);
#pragma unroll
            for (int nt = 0; nt < 8; nt++) {
                uint32_t b0 = bf[nt >> 1][(nt & 1) * 2];
                uint32_t b1 = bf[nt >> 1][(nt & 1) * 2 + 1];
                mma_f16(sacc[nt], af, b0, b1);
            }
        }

#pragma unroll
        for (int nt = 0; nt < 8; nt++)
#pragma unroll
            for (int c = 0; c < 4; c++) {
                float v = sacc[nt][c] * 0.125f;
                if (kt == 17 && (nt * 8 + 2 * tg + (c & 1)) >= 13) v = -1e30f;
                sacc[nt][c] = v;
            }

        float mx[2];
#pragma unroll
        for (int rr = 0; rr < 2; rr++) {
            float m = fmaxf(sacc[0][rr*2], sacc[0][rr*2+1]);
#pragma unroll
            for (int nt = 1; nt < 8; nt++) {
                m = fmaxf(m, sacc[nt][rr*2]);
                m = fmaxf(m, sacc[nt][rr*2+1]);
            }
            m = fmaxf(m, __shfl_xor_sync(0xffffffffu, m, 1));
            m = fmaxf(m, __shfl_xor_sync(0xffffffffu, m, 2));
            mx[rr] = m;
        }
        float nm[2], corr[2], nml[2];
#pragma unroll
        for (int rr = 0; rr < 2; rr++) {
            nm[rr] = fmaxf(m_run[rr], mx[rr]);
            corr[rr] = __expf(m_run[rr] - nm[rr]);
            m_run[rr] = nm[rr];
            nml[rr] = nm[rr] * L2E;
        }
#pragma unroll
        for (int nt = 0; nt < 8; nt++) {
            oacc[nt][0] *= corr[0];
            oacc[nt][1] *= corr[0];
            oacc[nt][2] *= corr[1];
            oacc[nt][3] *= corr[1];
        }
        lacc[0] *= corr[0]; lacc[1] *= corr[0];
        lacc[2] *= corr[1]; lacc[3] *= corr[1];

#pragma unroll
        for (int j = 0; j < 4; j++) {
            uint32_t pa[4];
            pa[0] = ex2_h2(fmaf(sacc[2*j  ][0], L2E, -nml[0]),
                           fmaf(sacc[2*j  ][1], L2E, -nml[0]));
            pa[1] = ex2_h2(fmaf(sacc[2*j  ][2], L2E, -nml[1]),
                           fmaf(sacc[2*j  ][3], L2E, -nml[1]));
            pa[2] = ex2_h2(fmaf(sacc[2*j+1][0], L2E, -nml[0]),
                           fmaf(sacc[2*j+1][1], L2E, -nml[0]));
            pa[3] = ex2_h2(fmaf(sacc[2*j+1][2], L2E, -nml[1]),
                           fmaf(sacc[2*j+1][3], L2E, -nml[1]));
            // V frags via trans-ldmatrix from [s][d] tile; j selects 16-s block
            uint32_t vf[4][4];
#pragma unroll
            for (int p = 0; p < 4; p++)
                ldsm4t(vf[p], vbase + (j * 16 * 36 + p * 8) * 4);
#pragma unroll
            for (int nt = 0; nt < 8; nt++) {
                uint32_t b0 = vf[nt >> 1][(nt & 1) * 2];
                uint32_t b1 = vf[nt >> 1][(nt & 1) * 2 + 1];
                mma_f16(oacc[nt], pa, b0, b1);
            }
            mma_f16(lacc, pa, ONES2, ONES2);
        }
    }

    float inv[2] = {1.f / lacc[0], 1.f / lacc[2]};
#pragma unroll
    for (int nt = 0; nt < 8; nt++)
#pragma unroll
        for (int rr = 0; rr < 2; rr++) {
            int t = t0 + rb + rr * 8 + g;
            int d = nt * 8 + 2 * tg;
            float v0 = oacc[nt][rr*2]     * inv[rr];
            float v1 = oacc[nt][rr*2 + 1] * inv[rr];
            *(uint32_t*)(aT + ((size_t)b * 1024 + t) * 512 + h * 64 + d) = pack_h2(v0, v1);
        }
}

// ---------------------------------------------------------------------------
// proj: out[b][m=ch][n=t] = sum_k W[ch][k]*aT[b][t][k] + bias + x, ldmatrix.
// ---------------------------------------------------------------------------
__global__ __launch_bounds__(256, 2)
void gemm_WA(const __half* __restrict__ W, const __half* __restrict__ Bm,
             const float* __restrict__ bias, const float* __restrict__ res,
             float* __restrict__ out)
{
    extern __shared__ uint32_t sm[];
    const int K = 512, N = 1024;

    int b = blockIdx.z;
    const __half* Bp = Bm + (size_t)b * 1024 * 512;
    float* op = out + (size_t)b * 512 * 1024;
    const float* rp = res + (size_t)b * 512 * 1024;

    int tid = threadIdx.x, w = tid >> 5, lane = tid & 31;
    int g = lane >> 2, tg = lane & 3;
    int warp_m = w >> 2, warp_n = w & 3;
    int m0 = blockIdx.y * 128, n0 = blockIdx.x * 128;
    uint32_t sb = sa32(sm);
    int lr  = (lane & 7) + ((lane >> 3) & 1) * 8;
    int lk  = (lane >> 4) * 4;
    int bnt = lane >> 4;
    int bko = ((lane >> 3) & 1) * 4;
    int br  = lane & 7;

    float acc[4][4][4];
#pragma unroll
    for (int i = 0; i < 4; i++)
#pragma unroll
        for (int j = 0; j < 4; j++)
#pragma unroll
            for (int c = 0; c < 4; c++) acc[i][j][c] = 0.f;

    auto stage = [&](int c, int buf) {
        int OA = buf * 9216, OB = OA + 4608;
        int k0 = c * 64;
#pragma unroll
        for (int it = 0; it < 4; it++) {
            int i = tid + it * 256;
            int row = i >> 3, seg = i & 7;
            cpa16(sb + (OA + row * 36 + seg * 4) * 4,
                  W + (size_t)(m0 + row) * K + k0 + seg * 8);
            cpa16(sb + (OB + row * 36 + seg * 4) * 4,
                  Bp + (size_t)(n0 + row) * K + k0 + seg * 8);
        }
    };

    stage(0, 0);
    cpa_commit();

    for (int c = 0; c < 8; c++) {
        cpa_wait0();
        __syncthreads();
        if (c + 1 < 8) { stage(c + 1, (c + 1) & 1); cpa_commit(); }
        int OA = (c & 1) * 9216, OB = OA + 4608;
        uint32_t abase = sb + (OA + (warp_m * 64 + lr) * 36 + lk) * 4;
        uint32_t bbase = sb + (OB + (warp_n * 32 + bnt * 8 + br) * 36 + bko) * 4;
#pragma unroll
        for (int ks = 0; ks < 4; ks++) {
            int kb = ks * 8;
            uint32_t af[4][4];
#pragma unroll
            for (int mt = 0; mt < 4; mt++)
                ldsm4(af[mt], abase + (mt * 16 * 36 + kb) * 4);
            uint32_t bf[2][4];
#pragma unroll
            for (int p = 0; p < 2; p++)
                ldsm4(bf[p], bbase + (p * 16 * 36 + kb) * 4);
#pragma unroll
            for (int nt = 0; nt < 4; nt++) {
                uint32_t b0 = bf[nt >> 1][(nt & 1) * 2];
                uint32_t b1 = bf[nt >> 1][(nt & 1) * 2 + 1];
#pragma unroll
                for (int mt = 0; mt < 4; mt++)
                    mma_f16(acc[mt][nt], af[mt], b0, b1);
            }
        }
        __syncthreads();
    }

#pragma unroll
    for (int mt = 0; mt < 4; mt++) {
#pragma unroll
        for (int rr = 0; rr < 2; rr++) {
            int m = m0 + warp_m * 64 + mt * 16 + rr * 8 + g;
            float bi = bias[m];
#pragma unroll
            for (int nt = 0; nt < 4; nt++) {
#pragma unroll
                for (int ci = 0; ci < 2; ci++) {
                    int n = n0 + warp_n * 32 + nt * 8 + 2 * tg + ci;
                    op[(size_t)m * N + n] = acc[mt][nt][rr * 2 + ci] + bi
                                          + rp[(size_t)m * N + n];
                }
            }
        }
    }
}

// ---------------------------------------------------------------------------
extern "C" void kernel_launch(void* const* d_in, const int* in_sizes, int n_in,
                              void* d_out, int out_size)
{
    const float* x     = (const float*)d_in[0];
    const float* c     = (const float*)d_in[1];
    const float* gamma = (const float*)d_in[2];
    const float* beta  = (const float*)d_in[3];
    const float* w_qkv = (const float*)d_in[4];
    const float* b_qkv = (const float*)d_in[5];
    const float* w_c   = (const float*)d_in[6];
    const float* b_c   = (const float*)d_in[7];
    const float* w_p   = (const float*)d_in[8];
    const float* b_p   = (const float*)d_in[9];
    float* out = (float*)d_out;

    __half *xnT, *qkvT, *cT, *ckvT, *vT, *aT, *wq, *wc, *wp;
    cudaGetSymbolAddress((void**)&xnT,  g_xnT);
    cudaGetSymbolAddress((void**)&qkvT, g_qkvT);
    cudaGetSymbolAddress((void**)&cT,   g_cT);
    cudaGetSymbolAddress((void**)&ckvT, g_ckvT);
    cudaGetSymbolAddress((void**)&vT,   g_vT);
    cudaGetSymbolAddress((void**)&aT,   g_aT);
    cudaGetSymbolAddress((void**)&wq,   g_wq);
    cudaGetSymbolAddress((void**)&wc,   g_wc);
    cudaGetSymbolAddress((void**)&wp,   g_wp);

    static bool attr_done = false;
    if (!attr_done) {
        cudaFuncSetAttribute(groupnorm_kernel, cudaFuncAttributeMaxDynamicSharedMemorySize, 65536);
        cudaFuncSetAttribute(gemm_qkv_ckv, cudaFuncAttributeMaxDynamicSharedMemorySize, 73728);
        cudaFuncSetAttribute(gemm_WA, cudaFuncAttributeMaxDynamicSharedMemorySize, 73728);
        cudaFuncSetAttribute(attn_kernel, cudaFuncAttributeMaxDynamicSharedMemorySize, 55296);
        attr_done = true;
    }

    groupnorm_kernel<<<512, 256, 65536>>>(x, gamma, beta, xnT);
    convW_all<<<7168, 256>>>(w_qkv, wq, 1536 * 512,
                             w_c, wc, 1024 * 768,
                             w_p, wp, 512 * 512);
    prep_c_kernel<<<dim3(3, 24, 16), 256>>>(c, cT);

    gemm_qkv_ckv<<<dim3(12, 9, 16), 256, 73728>>>(xnT, wq, b_qkv, cT, wc, b_c,
                                                  qkvT, ckvT, vT);

    attn_kernel<<<dim3(8, 8, 16), 256, 55296>>>(qkvT, ckvT, vT, aT);

    gemm_WA<<<dim3(8, 4, 16), 256, 73728>>>(wp, aT, b_p, x, out);
}